// round 1
// baseline (speedup 1.0000x reference)
#include <cuda_runtime.h>

// ---------------------------------------------------------------------------
// Problem constants (fixed by the reference generator)
//   B=256 pairs, MAX=64, D=128, E_DIM=64, NODE_F=32, EDGE_F=16, 3 prop steps
//   N = sum(sizes) <= 2*B*MAX = 32768 ; E = 8*N <= 262144
// ---------------------------------------------------------------------------
#define NMAX 32768
#define EMAX 262144

// Scratch (device globals; allocation-free kernel_launch)
__device__ float g_h   [NMAX * 128];          // node states
__device__ float g_e   [EMAX * 64];           // edge embeddings
__device__ float g_agg [NMAX * 256];          // aggregated messages
__device__ float g_flat[2 * 256 * 64 * 128];  // padded stacks (sq|sc)
__device__ float g_t   [2 * 256 * 64 * 128];  // attention features

// ---- packed f32x2 helpers --------------------------------------------------
__device__ __forceinline__ unsigned long long pk2(float x, float y) {
    unsigned long long r;
    asm("mov.b64 %0, {%1, %2};" : "=l"(r) : "f"(x), "f"(y));
    return r;
}
__device__ __forceinline__ float2 upk2(unsigned long long v) {
    float2 r;
    asm("mov.b64 {%0, %1}, %2;" : "=f"(r.x), "=f"(r.y) : "l"(v));
    return r;
}
__device__ __forceinline__ void fma2(unsigned long long& d,
                                     unsigned long long a,
                                     unsigned long long b) {
    asm("fma.rn.f32x2 %0, %1, %2, %0;" : "+l"(d) : "l"(a), "l"(b));
}

// ---------------------------------------------------------------------------
// K1: h = node_features @ W_node + b_node    [N,32]x[32,128]
// ---------------------------------------------------------------------------
__global__ void k_enc_node(const float* __restrict__ nf,
                           const float* __restrict__ Wn,
                           const float* __restrict__ bn, int N) {
    __shared__ float Ws[32 * 128];
    for (int i = threadIdx.x; i < 32 * 128; i += 256) Ws[i] = Wn[i];
    __syncthreads();
    int idx = blockIdx.x * 256 + threadIdx.x;
    if (idx >= N * 128) return;
    int n = idx >> 7, c = idx & 127;
    const float* row = nf + n * 32;
    float s = bn[c];
#pragma unroll
    for (int k = 0; k < 32; k++) s += row[k] * Ws[k * 128 + c];
    g_h[idx] = s;
}

// ---------------------------------------------------------------------------
// K2: e = edge_features @ W_edge + b_edge    [E,16]x[16,64]
// ---------------------------------------------------------------------------
__global__ void k_enc_edge(const float* __restrict__ ef,
                           const float* __restrict__ We,
                           const float* __restrict__ be, int E) {
    __shared__ float Ws[16 * 64];
    for (int i = threadIdx.x; i < 16 * 64; i += 256) Ws[i] = We[i];
    __syncthreads();
    int idx = blockIdx.x * 256 + threadIdx.x;
    if (idx >= E * 64) return;
    int ed = idx >> 6, c = idx & 63;
    const float* row = ef + ed * 16;
    float s = be[c];
#pragma unroll
    for (int k = 0; k < 16; k++) s += row[k] * Ws[k * 64 + c];
    g_e[idx] = s;
}

// ---------------------------------------------------------------------------
// K3: fused message MLP + segment-sum (per prop step)
//   per 64-edge tile: gather edge_in [64,320] -> relu(@W1) -> @W2 -> atomicAdd
//   SMEM layout transposed [k][row], stride 66 floats (8B-aligned, low conflict)
//   inner loops packed f32x2 over row pairs
// ---------------------------------------------------------------------------
#define MSG_SMEM ((320 + 256) * 66 * 4)
__global__ void __launch_bounds__(256, 1)
k_msg(const float* __restrict__ W1, const float* __restrict__ b1,
      const float* __restrict__ W2, const float* __restrict__ b2,
      const int* __restrict__ from_idx, const int* __restrict__ to_idx, int E) {
    extern __shared__ float sm[];
    float* a_sm = sm;               // [320][66]
    float* h_sm = sm + 320 * 66;    // [256][66]
    const int tid = threadIdx.x;
    const int e0 = blockIdx.x * 64;

    // gather edge_in (coalesced on global, 2-way conflict on SMEM write)
    for (int idx = tid; idx < 64 * 320; idx += 256) {
        int r = idx / 320, c = idx - r * 320;
        int ed = e0 + r;
        float v = 0.f;
        if (ed < E) {
            if (c < 128)       v = g_h[from_idx[ed] * 128 + c];
            else if (c < 256)  v = g_h[to_idx[ed] * 128 + (c - 128)];
            else               v = g_e[ed * 64 + (c - 256)];
        }
        a_sm[c * 66 + r] = v;
    }
    __syncthreads();

    const int c0 = tid & 63;   // base column (of 256 outputs)
    const int g  = tid >> 6;   // row group: rows g*16 .. g*16+15

    unsigned long long acc[8][4];
#pragma unroll
    for (int rp = 0; rp < 8; rp++)
#pragma unroll
        for (int j = 0; j < 4; j++) acc[rp][j] = 0ull;

    // GEMM1: hidden = edge_in @ W1   (K=320)
#pragma unroll 2
    for (int k = 0; k < 320; k++) {
        const float* wr = W1 + k * 256 + c0;
        unsigned long long w0 = pk2(wr[0],   wr[0]);
        unsigned long long w1 = pk2(wr[64],  wr[64]);
        unsigned long long w2 = pk2(wr[128], wr[128]);
        unsigned long long w3 = pk2(wr[192], wr[192]);
        const unsigned long long* ar =
            (const unsigned long long*)(a_sm + k * 66) + g * 8;
#pragma unroll
        for (int rp = 0; rp < 8; rp++) {
            unsigned long long a2 = ar[rp];
            fma2(acc[rp][0], a2, w0);
            fma2(acc[rp][1], a2, w1);
            fma2(acc[rp][2], a2, w2);
            fma2(acc[rp][3], a2, w3);
        }
    }
    // bias + relu -> h_sm (transposed)
#pragma unroll
    for (int j = 0; j < 4; j++) {
        float bb = b1[c0 + 64 * j];
        float* col = h_sm + (c0 + 64 * j) * 66 + g * 16;
#pragma unroll
        for (int rp = 0; rp < 8; rp++) {
            float2 v = upk2(acc[rp][j]);
            col[2 * rp]     = fmaxf(v.x + bb, 0.f);
            col[2 * rp + 1] = fmaxf(v.y + bb, 0.f);
        }
    }
    __syncthreads();

#pragma unroll
    for (int rp = 0; rp < 8; rp++)
#pragma unroll
        for (int j = 0; j < 4; j++) acc[rp][j] = 0ull;

    // GEMM2: msg = hidden @ W2   (K=256)
#pragma unroll 2
    for (int k = 0; k < 256; k++) {
        const float* wr = W2 + k * 256 + c0;
        unsigned long long w0 = pk2(wr[0],   wr[0]);
        unsigned long long w1 = pk2(wr[64],  wr[64]);
        unsigned long long w2 = pk2(wr[128], wr[128]);
        unsigned long long w3 = pk2(wr[192], wr[192]);
        const unsigned long long* ar =
            (const unsigned long long*)(h_sm + k * 66) + g * 8;
#pragma unroll
        for (int rp = 0; rp < 8; rp++) {
            unsigned long long a2 = ar[rp];
            fma2(acc[rp][0], a2, w0);
            fma2(acc[rp][1], a2, w1);
            fma2(acc[rp][2], a2, w2);
            fma2(acc[rp][3], a2, w3);
        }
    }

    // epilogue: bias + atomic segment-sum into g_agg[to]
    int tov[16];
#pragma unroll
    for (int r = 0; r < 16; r++) {
        int ed = e0 + g * 16 + r;
        tov[r] = (ed < E) ? to_idx[ed] : -1;
    }
#pragma unroll
    for (int j = 0; j < 4; j++) {
        float bb = b2[c0 + 64 * j];
        int cc = c0 + 64 * j;
#pragma unroll
        for (int rp = 0; rp < 8; rp++) {
            float2 v = upk2(acc[rp][j]);
            int t0 = tov[2 * rp], t1 = tov[2 * rp + 1];
            if (t0 >= 0) atomicAdd(&g_agg[t0 * 256 + cc], v.x + bb);
            if (t1 >= 0) atomicAdd(&g_agg[t1 * 256 + cc], v.y + bb);
        }
    }
}

// ---------------------------------------------------------------------------
// K4: node update  h = h + concat(h, agg) @ W_upd + b_upd   (K=384, cols=128)
// ---------------------------------------------------------------------------
#define UPD_SMEM (384 * 33 * 4)
__global__ void __launch_bounds__(256, 1)
k_upd(const float* __restrict__ Wu, const float* __restrict__ bu, int N) {
    extern __shared__ float sm[];  // [384][33]
    const int tid = threadIdx.x;
    const int n0 = blockIdx.x * 32;
    for (int idx = tid; idx < 32 * 384; idx += 256) {
        int r = idx / 384, c = idx - r * 384;
        int n = n0 + r;
        float v = 0.f;
        if (n < N) v = (c < 128) ? g_h[n * 128 + c] : g_agg[n * 256 + (c - 128)];
        sm[c * 33 + r] = v;
    }
    __syncthreads();
    const int c0 = tid & 127, rg = tid >> 7;
    float acc[16];
#pragma unroll
    for (int r = 0; r < 16; r++) acc[r] = 0.f;
#pragma unroll 4
    for (int k = 0; k < 384; k++) {
        float w = Wu[k * 128 + c0];
        const float* a = sm + k * 33 + rg * 16;
#pragma unroll
        for (int r = 0; r < 16; r++) acc[r] += a[r] * w;
    }
    float bb = bu[c0];
#pragma unroll
    for (int r = 0; r < 16; r++) {
        int n = n0 + rg * 16 + r;
        if (n < N)
            g_h[n * 128 + c0] = sm[c0 * 33 + (rg * 16 + r)] + acc[r] + bb;
    }
}

// ---------------------------------------------------------------------------
// K5: scatter h into padded stacks (g_flat pre-zeroed by memset)
// ---------------------------------------------------------------------------
__global__ void k_scatter(const int* __restrict__ pos, int N) {
    int idx = blockIdx.x * 256 + threadIdx.x;
    if (idx >= N * 128) return;
    int n = idx >> 7, c = idx & 127;
    g_flat[pos[n] * 128 + c] = g_h[idx];
}

// ---------------------------------------------------------------------------
// K6: attention features  t = relu(x @ Wa1 + ba1) @ Wa2 + ba2, masked
// ---------------------------------------------------------------------------
__global__ void __launch_bounds__(256, 1)
k_att(const float* __restrict__ Wa1, const float* __restrict__ ba1,
      const float* __restrict__ Wa2, const float* __restrict__ ba2,
      const int* __restrict__ qsz, const int* __restrict__ csz) {
    __shared__ float x_sm[128 * 33];
    __shared__ float h_sm[128 * 33];
    const int tid = threadIdx.x;
    const int r0 = blockIdx.x * 32;
    for (int idx = tid; idx < 32 * 128; idx += 256) {
        int r = idx >> 7, c = idx & 127;
        x_sm[c * 33 + r] = g_flat[(r0 + r) * 128 + c];
    }
    __syncthreads();
    const int c0 = tid & 127, rg = tid >> 7;
    float acc[16];
#pragma unroll
    for (int r = 0; r < 16; r++) acc[r] = 0.f;
#pragma unroll 4
    for (int k = 0; k < 128; k++) {
        float w = Wa1[k * 128 + c0];
        const float* a = x_sm + k * 33 + rg * 16;
#pragma unroll
        for (int r = 0; r < 16; r++) acc[r] += a[r] * w;
    }
    {
        float bb = ba1[c0];
        float* col = h_sm + c0 * 33 + rg * 16;
#pragma unroll
        for (int r = 0; r < 16; r++) col[r] = fmaxf(acc[r] + bb, 0.f);
    }
    __syncthreads();
#pragma unroll
    for (int r = 0; r < 16; r++) acc[r] = 0.f;
#pragma unroll 4
    for (int k = 0; k < 128; k++) {
        float w = Wa2[k * 128 + c0];
        const float* a = h_sm + k * 33 + rg * 16;
#pragma unroll
        for (int r = 0; r < 16; r++) acc[r] += a[r] * w;
    }
    float bb = ba2[c0];
#pragma unroll
    for (int r = 0; r < 16; r++) {
        int row = r0 + rg * 16 + r;
        int gi = row >> 6, q = row & 63;
        int size = (gi < 256) ? qsz[gi] : csz[gi - 256];
        g_t[row * 128 + c0] = (q < size) ? (acc[r] + bb) : 0.f;
    }
}

// ---------------------------------------------------------------------------
// K7: per-pair logits, dual softmax, hinge alignment scores, min
// ---------------------------------------------------------------------------
#define PAIR_SMEM ((2 * 64 * 129 + 3 * 64 * 65) * 4)
__global__ void __launch_bounds__(256, 1)
k_pair(const int* __restrict__ qsz, const int* __restrict__ csz,
       float* __restrict__ out) {
    extern __shared__ float sm[];
    float* bufA = sm;                  // [64][129]  tq, then sq
    float* bufB = bufA + 64 * 129;     // [64][129]  tc, then sc
    float* L    = bufB + 64 * 129;     // [64][65]   logits
    float* pq   = L + 64 * 65;         // row-softmax * mq
    float* pc   = pq + 64 * 65;        // col-softmax * mc
    __shared__ float redq[8], redc[8];

    const int b = blockIdx.x, tid = threadIdx.x;
    const int qs = qsz[b], cs = csz[b];
    const int qbase = b * 64, cbase = 16384 + b * 64;

    for (int idx = tid; idx < 64 * 128; idx += 256) {
        int r = idx >> 7, k = idx & 127;
        bufA[r * 129 + k] = g_t[(qbase + r) * 128 + k];
        bufB[r * 129 + k] = g_t[(cbase + r) * 128 + k];
    }
    __syncthreads();

    // logits[q][c] = 10 * dot(tq[q], tc[c]) with pair mask
    {
        int q = tid >> 2, cg = tid & 3;
        float acc[16];
#pragma unroll
        for (int j = 0; j < 16; j++) acc[j] = 0.f;
        for (int k = 0; k < 128; k++) {
            float a = bufA[q * 129 + k];
            const float* bp = bufB + (cg * 16) * 129 + k;
#pragma unroll
            for (int j = 0; j < 16; j++) acc[j] += a * bp[j * 129];
        }
        bool qv = q < qs;
#pragma unroll
        for (int j = 0; j < 16; j++) {
            int c = cg * 16 + j;
            L[q * 65 + c] = (qv && c < cs) ? acc[j] * 10.0f : -1e9f;
        }
    }
    __syncthreads();

    // reload raw node states into bufA/bufB (logits done with tq/tc)
    for (int idx = tid; idx < 64 * 128; idx += 256) {
        int r = idx >> 7, k = idx & 127;
        bufA[r * 129 + k] = g_flat[(qbase + r) * 128 + k];
        bufB[r * 129 + k] = g_flat[(cbase + r) * 128 + k];
    }

    if (tid < 64) {           // row softmax (over corpus axis) * mq
        float m = -1e30f;
        for (int c = 0; c < 64; c++) m = fmaxf(m, L[tid * 65 + c]);
        float s = 0.f;
        for (int c = 0; c < 64; c++) {
            float ex = __expf(L[tid * 65 + c] - m);
            s += ex;
            pq[tid * 65 + c] = ex;
        }
        float inv = (tid < qs) ? (1.0f / s) : 0.f;
        for (int c = 0; c < 64; c++) pq[tid * 65 + c] *= inv;
    } else if (tid < 128) {   // col softmax (over query axis) * mc
        int c = tid - 64;
        float m = -1e30f;
        for (int q = 0; q < 64; q++) m = fmaxf(m, L[q * 65 + c]);
        float s = 0.f;
        for (int q = 0; q < 64; q++) {
            float ex = __expf(L[q * 65 + c] - m);
            s += ex;
            pc[q * 65 + c] = ex;
        }
        float inv = (c < cs) ? (1.0f / s) : 0.f;
        for (int q = 0; q < 64; q++) pc[q * 65 + c] *= inv;
    }
    __syncthreads();

    float lq = 0.f, lc = 0.f;
    {
        const int d = tid & 127, gg = tid >> 7;
        float acc[32];
#pragma unroll
        for (int j = 0; j < 32; j++) acc[j] = 0.f;
        for (int c = 0; c < 64; c++) {
            float bb = bufB[c * 129 + d];
            const float* pp = pq + (gg * 32) * 65 + c;
#pragma unroll
            for (int j = 0; j < 32; j++) acc[j] += pp[j * 65] * bb;
        }
#pragma unroll
        for (int j = 0; j < 32; j++) {
            int q = gg * 32 + j;
            lq += fmaxf(bufA[q * 129 + d] - acc[j], 0.f);
        }
#pragma unroll
        for (int j = 0; j < 32; j++) acc[j] = 0.f;
        for (int q = 0; q < 64; q++) {
            float aa = bufA[q * 129 + d];
            const float* pp = pc + q * 65 + gg * 32;
#pragma unroll
            for (int j = 0; j < 32; j++) acc[j] += pp[j] * aa;
        }
#pragma unroll
        for (int j = 0; j < 32; j++) {
            int c = gg * 32 + j;
            lc += fmaxf(bufB[c * 129 + d] - acc[j], 0.f);
        }
    }
    for (int o = 16; o; o >>= 1) {
        lq += __shfl_down_sync(0xffffffffu, lq, o);
        lc += __shfl_down_sync(0xffffffffu, lc, o);
    }
    int w = tid >> 5, lane = tid & 31;
    if (lane == 0) { redq[w] = lq; redc[w] = lc; }
    __syncthreads();
    if (tid == 0) {
        float sq = 0.f, sc = 0.f;
        for (int i = 0; i < 8; i++) { sq += redq[i]; sc += redc[i]; }
        out[b] = fminf(-sq, -sc);
    }
}

// ---------------------------------------------------------------------------
extern "C" void kernel_launch(void* const* d_in, const int* in_sizes, int n_in,
                              void* d_out, int out_size) {
    const float* nf       = (const float*)d_in[0];
    const float* ef       = (const float*)d_in[1];
    const int*   from_idx = (const int*)d_in[2];
    const int*   to_idx   = (const int*)d_in[3];
    const int*   pos      = (const int*)d_in[4];
    const int*   qsz      = (const int*)d_in[5];
    const int*   csz      = (const int*)d_in[6];
    const float* W_node = (const float*)d_in[7];
    const float* b_node = (const float*)d_in[8];
    const float* W_edge = (const float*)d_in[9];
    const float* b_edge = (const float*)d_in[10];
    const float* W_msg1 = (const float*)d_in[11];
    const float* b_msg1 = (const float*)d_in[12];
    const float* W_msg2 = (const float*)d_in[13];
    const float* b_msg2 = (const float*)d_in[14];
    const float* W_upd  = (const float*)d_in[15];
    const float* b_upd  = (const float*)d_in[16];
    const float* Wa1    = (const float*)d_in[17];
    const float* ba1    = (const float*)d_in[18];
    const float* Wa2    = (const float*)d_in[19];
    const float* ba2    = (const float*)d_in[20];

    const int N = in_sizes[0] / 32;
    const int E = in_sizes[1] / 16;

    cudaFuncSetAttribute(k_msg,  cudaFuncAttributeMaxDynamicSharedMemorySize, MSG_SMEM);
    cudaFuncSetAttribute(k_upd,  cudaFuncAttributeMaxDynamicSharedMemorySize, UPD_SMEM);
    cudaFuncSetAttribute(k_pair, cudaFuncAttributeMaxDynamicSharedMemorySize, PAIR_SMEM);

    void* aggp = nullptr;
    void* flatp = nullptr;
    cudaGetSymbolAddress(&aggp, g_agg);
    cudaGetSymbolAddress(&flatp, g_flat);

    k_enc_node<<<(N * 128 + 255) / 256, 256>>>(nf, W_node, b_node, N);
    k_enc_edge<<<(E * 64 + 255) / 256, 256>>>(ef, W_edge, b_edge, E);

    for (int s = 0; s < 3; s++) {
        cudaMemsetAsync(aggp, 0, (size_t)N * 256 * sizeof(float));
        k_msg<<<(E + 63) / 64, 256, MSG_SMEM>>>(W_msg1, b_msg1, W_msg2, b_msg2,
                                                from_idx, to_idx, E);
        k_upd<<<(N + 31) / 32, 256, UPD_SMEM>>>(W_upd, b_upd, N);
    }

    cudaMemsetAsync(flatp, 0, (size_t)2 * 256 * 64 * 128 * sizeof(float));
    k_scatter<<<(N * 128 + 255) / 256, 256>>>(pos, N);
    k_att<<<(2 * 256 * 64) / 32, 256>>>(Wa1, ba1, Wa2, ba2, qsz, csz);
    k_pair<<<256, 256, PAIR_SMEM>>>(qsz, csz, (float*)d_out);
}

// round 3
// speedup vs baseline: 2.5459x; 2.5459x over previous
#include <cuda_runtime.h>
#include <cuda_bf16.h>
#include <cstdint>

// ---------------------------------------------------------------------------
// Constants: B=256 pairs, MAX=64, D=128, E_DIM=64, 3 prop steps
// ---------------------------------------------------------------------------
#define NMAX 32768
#define EMAX 262144

// Scratch
__device__ float g_h   [NMAX * 128];
__device__ float g_agg [NMAX * 256];
__device__ float g_flat[2 * 256 * 64 * 128];
__device__ float g_t   [2 * 256 * 64 * 128];
__device__ float g_P   [NMAX * 512];   // per-step node products [P1|P2]
__device__ float g_pe  [(size_t)EMAX * 256]; // edge part of GEMM1 (+b1), step-invariant
__device__ __align__(16) __nv_bfloat16 g_h_hi[NMAX * 128];
__device__ __align__(16) __nv_bfloat16 g_h_lo[NMAX * 128];
__device__ __align__(16) __nv_bfloat16 g_e_hi[EMAX * 64];
__device__ __align__(16) __nv_bfloat16 g_e_lo[EMAX * 64];
// Pre-split transposed weights Bt[n][k] (row-major, bf16 hi/lo)
__device__ __align__(16) __nv_bfloat16 g_w1p_hi[512 * 128], g_w1p_lo[512 * 128];
__device__ __align__(16) __nv_bfloat16 g_w1e_hi[256 * 64],  g_w1e_lo[256 * 64];
__device__ __align__(16) __nv_bfloat16 g_w2t_hi[256 * 256], g_w2t_lo[256 * 256];
__device__ __align__(16) __nv_bfloat16 g_wut_hi[128 * 384], g_wut_lo[128 * 384];

// ---------------------------------------------------------------------------
// helpers
// ---------------------------------------------------------------------------
__device__ __forceinline__ uint32_t smem_to_u32(const void* p) {
    uint32_t a;
    asm("{ .reg .u64 t; cvta.to.shared.u64 t, %1; cvt.u32.u64 %0, t; }"
        : "=r"(a) : "l"(p));
    return a;
}
__device__ __forceinline__ void ldsm_x4(uint32_t r[4], uint32_t addr) {
    asm volatile("ldmatrix.sync.aligned.m8n8.x4.shared.b16 {%0,%1,%2,%3}, [%4];"
                 : "=r"(r[0]), "=r"(r[1]), "=r"(r[2]), "=r"(r[3]) : "r"(addr));
}
__device__ __forceinline__ void mma_bf16(float c[4], const uint32_t a[4],
                                         uint32_t b0, uint32_t b1) {
    asm volatile(
        "mma.sync.aligned.m16n8k16.row.col.f32.bf16.bf16.f32 "
        "{%0,%1,%2,%3}, {%4,%5,%6,%7}, {%8,%9}, {%0,%1,%2,%3};"
        : "+f"(c[0]), "+f"(c[1]), "+f"(c[2]), "+f"(c[3])
        : "r"(a[0]), "r"(a[1]), "r"(a[2]), "r"(a[3]), "r"(b0), "r"(b1));
}
__device__ __forceinline__ void cp_async16(uint32_t smem, const void* g) {
    asm volatile("cp.async.ca.shared.global [%0], [%1], 16;"
                 :: "r"(smem), "l"(g));
}
#define CP_COMMIT() asm volatile("cp.async.commit_group;" ::: "memory")
#define CP_WAIT1()  asm volatile("cp.async.wait_group 1;" ::: "memory")
#define CP_WAIT0()  asm volatile("cp.async.wait_group 0;" ::: "memory")

__device__ __forceinline__ uint32_t pkbf(float a, float b) {
    __nv_bfloat162 t = __floats2bfloat162_rn(a, b);
    return *reinterpret_cast<uint32_t*>(&t);
}

// One 64-k chunk of warp MMA. A tile row stride SA (bf16 elems), B stride 72.
// NT = number of 8-wide n subtiles (8 -> 64 cols, 4 -> 32 cols per warp).
template <int SA, int NT>
__device__ __forceinline__ void mma_chunk(float (&acc)[4][NT][4],
                                          uint32_t aw, uint32_t bw, int lane) {
    const int arow = lane & 15, ak = (lane >> 4) << 3;
    const int brow = (lane & 7) + ((lane >> 4) << 3);
    const int bk = ((lane >> 3) & 1) << 3;
#pragma unroll
    for (int kt = 0; kt < 4; kt++) {
        uint32_t a[4][4], b[NT / 2][4];
#pragma unroll
        for (int mt = 0; mt < 4; mt++)
            ldsm_x4(a[mt], aw + ((mt * 16 + arow) * SA + kt * 16 + ak) * 2);
#pragma unroll
        for (int nb = 0; nb < NT / 2; nb++)
            ldsm_x4(b[nb], bw + ((nb * 16 + brow) * 72 + kt * 16 + bk) * 2);
#pragma unroll
        for (int mt = 0; mt < 4; mt++)
#pragma unroll
            for (int nb = 0; nb < NT / 2; nb++) {
                mma_bf16(acc[mt][2 * nb],     a[mt], b[nb][0], b[nb][1]);
                mma_bf16(acc[mt][2 * nb + 1], a[mt], b[nb][2], b[nb][3]);
            }
    }
}

// ---------------------------------------------------------------------------
// K0: weight prep — transpose + hi/lo split
// ---------------------------------------------------------------------------
__global__ void k_prep(const float* __restrict__ W1, const float* __restrict__ W2,
                       const float* __restrict__ Wu) {
    int idx = blockIdx.x * 256 + threadIdx.x;
    float v;
    __nv_bfloat16 *dh, *dl;
    int off;
    if (idx < 65536) {                       // g_w1p [512n][128k]
        int n = idx >> 7, k = idx & 127;
        v = (n < 256) ? W1[k * 256 + n] : W1[(128 + k) * 256 + (n - 256)];
        dh = g_w1p_hi; dl = g_w1p_lo; off = idx;
    } else if (idx < 81920) {                // g_w1e [256n][64k]
        int i = idx - 65536;
        int n = i >> 6, k = i & 63;
        v = W1[(256 + k) * 256 + n];
        dh = g_w1e_hi; dl = g_w1e_lo; off = i;
    } else if (idx < 147456) {               // g_w2t [256n][256k]
        int i = idx - 81920;
        int n = i >> 8, k = i & 255;
        v = W2[k * 256 + n];
        dh = g_w2t_hi; dl = g_w2t_lo; off = i;
    } else {                                 // g_wut [128n][384k]
        int i = idx - 147456;
        if (i >= 49152) return;
        int n = i / 384, k = i - n * 384;
        v = Wu[k * 128 + n];
        dh = g_wut_hi; dl = g_wut_lo; off = i;
    }
    __nv_bfloat16 hi = __float2bfloat16(v);
    dh[off] = hi;
    dl[off] = __float2bfloat16(v - __bfloat162float(hi));
}

// ---------------------------------------------------------------------------
// K1: node encoder -> g_h (+ hi/lo)
// ---------------------------------------------------------------------------
__global__ void k_enc_node(const float* __restrict__ nf,
                           const float* __restrict__ Wn,
                           const float* __restrict__ bn, int N) {
    __shared__ float Ws[32 * 128];
    for (int i = threadIdx.x; i < 32 * 128; i += 256) Ws[i] = Wn[i];
    __syncthreads();
    int idx = blockIdx.x * 256 + threadIdx.x;
    if (idx >= N * 128) return;
    int n = idx >> 7, c = idx & 127;
    const float* row = nf + n * 32;
    float s = bn[c];
#pragma unroll
    for (int k = 0; k < 32; k++) s += row[k] * Ws[k * 128 + c];
    g_h[idx] = s;
    __nv_bfloat16 hi = __float2bfloat16(s);
    g_h_hi[idx] = hi;
    g_h_lo[idx] = __float2bfloat16(s - __bfloat162float(hi));
}

// ---------------------------------------------------------------------------
// K2: edge encoder -> bf16 hi/lo
// ---------------------------------------------------------------------------
__global__ void k_enc_edge(const float* __restrict__ ef,
                           const float* __restrict__ We,
                           const float* __restrict__ be, int E) {
    __shared__ float Ws[16 * 64];
    for (int i = threadIdx.x; i < 16 * 64; i += 256) Ws[i] = We[i];
    __syncthreads();
    int idx = blockIdx.x * 256 + threadIdx.x;
    if (idx >= E * 64) return;
    int ed = idx >> 6, c = idx & 63;
    const float* row = ef + ed * 16;
    float s = be[c];
#pragma unroll
    for (int k = 0; k < 16; k++) s += row[k] * Ws[k * 64 + c];
    __nv_bfloat16 hi = __float2bfloat16(s);
    g_e_hi[idx] = hi;
    g_e_lo[idx] = __float2bfloat16(s - __bfloat162float(hi));
}

// ---------------------------------------------------------------------------
// K3: Pe = e @ W1_bot + b1   (once; [E,256], K=64, 3 hi/lo passes)
// ---------------------------------------------------------------------------
#define PE_AHI 0
#define PE_ALO 18432
#define PE_BHI 36864
#define PE_BLO 73728
#define PE_SMEM 110592
__global__ void __launch_bounds__(256, 1)
k_pe(const float* __restrict__ b1, int E) {
    extern __shared__ unsigned char sm[];
    const uint32_t base = smem_to_u32(sm);
    const int tid = threadIdx.x, lane = tid & 31, wid = tid >> 5;
    const int e0 = blockIdx.x * 128;
    // A: e rows hi/lo [128][72]
    {
        int row = tid & 127, which = tid >> 7;
        const __nv_bfloat16* src =
            (which ? g_e_lo : g_e_hi) + (size_t)(e0 + row) * 64;
        unsigned char* dst = sm + (which ? PE_ALO : PE_AHI) + row * 144;
#pragma unroll
        for (int j = 0; j < 8; j++)
            *(uint4*)(dst + j * 16) = *(const uint4*)(src + j * 8);
    }
    // B: W1e rows hi/lo [256][72] each
    {
        const __nv_bfloat16* src = (tid < 256 ? g_w1e_hi : g_w1e_hi);
        for (int t = tid; t < 512; t += 256) {
            int n = t & 255, which = t >> 8;
            const __nv_bfloat16* s2 = (which ? g_w1e_lo : g_w1e_hi) + n * 64;
            unsigned char* dst = sm + (which ? PE_BLO : PE_BHI) + n * 144;
#pragma unroll
            for (int j = 0; j < 8; j++)
                *(uint4*)(dst + j * 16) = *(const uint4*)(s2 + j * 8);
        }
        (void)src;
    }
    __syncthreads();
    const int wm = wid >> 2, wn = wid & 3;
    float acc[4][8][4];
#pragma unroll
    for (int i = 0; i < 4; i++)
#pragma unroll
        for (int j = 0; j < 8; j++)
#pragma unroll
            for (int k = 0; k < 4; k++) acc[i][j][k] = 0.f;
#pragma unroll
    for (int p = 0; p < 3; p++) {
        uint32_t aw = base + (p == 1 ? PE_ALO : PE_AHI) + (wm * 64 * 72) * 2;
        uint32_t bw = base + (p == 2 ? PE_BLO : PE_BHI) + (wn * 64) * 144;
        mma_chunk<72, 8>(acc, aw, bw, lane);
    }
#pragma unroll
    for (int mt = 0; mt < 4; mt++) {
        int r0 = wm * 64 + mt * 16 + (lane >> 2);
#pragma unroll
        for (int nt = 0; nt < 8; nt++) {
            int col = wn * 64 + nt * 8 + 2 * (lane & 3);
            float2 bb = *(const float2*)(b1 + col);
            *(float2*)(g_pe + (size_t)(e0 + r0) * 256 + col) =
                make_float2(acc[mt][nt][0] + bb.x, acc[mt][nt][1] + bb.y);
            *(float2*)(g_pe + (size_t)(e0 + r0 + 8) * 256 + col) =
                make_float2(acc[mt][nt][2] + bb.x, acc[mt][nt][3] + bb.y);
        }
    }
}

// ---------------------------------------------------------------------------
// K4: P12 = h @ [W1_top|W1_mid]   ([N,128]x[128,512]), per step
// ---------------------------------------------------------------------------
#define NP_AHI 0
#define NP_ALO 34816
#define NP_B   69632
#define NP_SMEM 143360
__global__ void __launch_bounds__(256, 1)
k_nodeprod(int N) {
    extern __shared__ unsigned char sm[];
    const uint32_t base = smem_to_u32(sm);
    const int tid = threadIdx.x, lane = tid & 31, wid = tid >> 5;
    const int rb = blockIdx.x >> 1, cb = blockIdx.x & 1;
    const int n0 = rb * 128;
    // A: h rows hi/lo [128][136]
#pragma unroll
    for (int i = 0; i < 2; i++) {
        int t = tid + 256 * i;                 // 512 tasks
        int which = t >> 8, r2 = t & 255;
        int row = r2 >> 1, half = r2 & 1;
        const __nv_bfloat16* src =
            (which ? g_h_lo : g_h_hi) + (size_t)(n0 + row) * 128 + half * 64;
        unsigned char* dst =
            sm + (which ? NP_ALO : NP_AHI) + (row * 136 + half * 64) * 2;
#pragma unroll
        for (int j = 0; j < 8; j++)
            *(uint4*)(dst + j * 16) = *(const uint4*)(src + j * 8);
    }
    // prefetch B chunk 0
    {
        const __nv_bfloat16* src = g_w1p_hi + ((size_t)(cb * 256 + tid)) * 128;
        uint32_t dst = base + NP_B + tid * 144;
#pragma unroll
        for (int j = 0; j < 8; j++) cp_async16(dst + j * 16, src + j * 8);
        CP_COMMIT();
    }
    const int wm = wid >> 2, wn = wid & 3;
    float acc[4][8][4];
#pragma unroll
    for (int i = 0; i < 4; i++)
#pragma unroll
        for (int j = 0; j < 8; j++)
#pragma unroll
            for (int k = 0; k < 4; k++) acc[i][j][k] = 0.f;

    for (int c = 0; c < 6; c++) {
        int buf = c & 1;
        if (c + 1 < 6) {
            int p1 = (c + 1) >> 1, kc1 = (c + 1) & 1;
            const __nv_bfloat16* src =
                (p1 < 2 ? g_w1p_hi : g_w1p_lo) +
                ((size_t)(cb * 256 + tid)) * 128 + kc1 * 64;
            uint32_t dst = base + NP_B + ((c + 1) & 1) * 36864 + tid * 144;
#pragma unroll
            for (int j = 0; j < 8; j++) cp_async16(dst + j * 16, src + j * 8);
            CP_COMMIT();
            CP_WAIT1();
        } else {
            CP_WAIT0();
        }
        __syncthreads();
        int p = c >> 1, kc = c & 1;
        uint32_t aw = base + (p == 1 ? NP_ALO : NP_AHI) +
                      (wm * 64 * 136 + kc * 64) * 2;
        uint32_t bw = base + NP_B + buf * 36864 + (wn * 64) * 144;
        mma_chunk<136, 8>(acc, aw, bw, lane);
        __syncthreads();
    }
#pragma unroll
    for (int mt = 0; mt < 4; mt++) {
        int r0 = wm * 64 + mt * 16 + (lane >> 2);
        int n1 = n0 + r0, n2 = n1 + 8;
#pragma unroll
        for (int nt = 0; nt < 8; nt++) {
            int col = cb * 256 + wn * 64 + nt * 8 + 2 * (lane & 3);
            if (n1 < N)
                *(float2*)(g_P + (size_t)n1 * 512 + col) =
                    make_float2(acc[mt][nt][0], acc[mt][nt][1]);
            if (n2 < N)
                *(float2*)(g_P + (size_t)n2 * 512 + col) =
                    make_float2(acc[mt][nt][2], acc[mt][nt][3]);
        }
    }
}

// ---------------------------------------------------------------------------
// K5: edge GEMM2 + segment-sum.  hidden = relu(P1[from]+P2[to]+Pe),
//     msg = hidden @ W2 (3-term hi/lo, ext-K=768), atomicAdd into g_agg.
// ---------------------------------------------------------------------------
#define MS_AHI  0
#define MS_ALO  67584
#define MS_B    135168
#define MS_FROM 208896
#define MS_TO   209408
#define MS_SMEM 209920
__global__ void __launch_bounds__(256, 1)
k_msg2(const float* __restrict__ b2, const int* __restrict__ from_idx,
       const int* __restrict__ to_idx, int E) {
    extern __shared__ unsigned char sm[];
    const uint32_t base = smem_to_u32(sm);
    const int tid = threadIdx.x, lane = tid & 31, wid = tid >> 5;
    const int e0 = blockIdx.x * 128;
    int* from_sm = (int*)(sm + MS_FROM);
    int* to_sm   = (int*)(sm + MS_TO);
    if (tid < 128) {
        int ed = e0 + tid;
        from_sm[tid] = (ed < E) ? from_idx[ed] : 0;
        to_sm[tid]   = (ed < E) ? to_idx[ed] : 0;
    }
    __syncthreads();
    // A build: relu(P1[from]+P2[to]+Pe) -> hi/lo bf16, stride 264
#pragma unroll 2
    for (int i = 0; i < 32; i++) {
        int idx = tid + 256 * i;
        int row = idx >> 6, q = idx & 63;
        const float4 v1 = *(const float4*)(g_P + (size_t)from_sm[row] * 512 + q * 4);
        const float4 v2 = *(const float4*)(g_P + (size_t)to_sm[row] * 512 + 256 + q * 4);
        const float4 ve = *(const float4*)(g_pe + (size_t)(e0 + row) * 256 + q * 4);
        float s0 = fmaxf(v1.x + v2.x + ve.x, 0.f);
        float s1 = fmaxf(v1.y + v2.y + ve.y, 0.f);
        float s2 = fmaxf(v1.z + v2.z + ve.z, 0.f);
        float s3 = fmaxf(v1.w + v2.w + ve.w, 0.f);
        __nv_bfloat16 h0 = __float2bfloat16(s0), h1 = __float2bfloat16(s1);
        __nv_bfloat16 h2 = __float2bfloat16(s2), h3 = __float2bfloat16(s3);
        uint2 hp, lp;
        hp.x = pkbf(s0, s1); hp.y = pkbf(s2, s3);
        lp.x = pkbf(s0 - __bfloat162float(h0), s1 - __bfloat162float(h1));
        lp.y = pkbf(s2 - __bfloat162float(h2), s3 - __bfloat162float(h3));
        int boff = (row * 264 + q * 4) * 2;
        *(uint2*)(sm + MS_AHI + boff) = hp;
        *(uint2*)(sm + MS_ALO + boff) = lp;
    }
    // prefetch B chunk 0
    {
        const __nv_bfloat16* src = g_w2t_hi + (size_t)tid * 256;
        uint32_t dst = base + MS_B + tid * 144;
#pragma unroll
        for (int j = 0; j < 8; j++) cp_async16(dst + j * 16, src + j * 8);
        CP_COMMIT();
    }
    const int wm = wid >> 2, wn = wid & 3;
    float acc[4][8][4];
#pragma unroll
    for (int i = 0; i < 4; i++)
#pragma unroll
        for (int j = 0; j < 8; j++)
#pragma unroll
            for (int k = 0; k < 4; k++) acc[i][j][k] = 0.f;

    for (int c = 0; c < 12; c++) {
        int buf = c & 1;
        if (c + 1 < 12) {
            int p1 = (c + 1) >> 2, kc1 = (c + 1) & 3;
            const __nv_bfloat16* src = (p1 < 2 ? g_w2t_hi : g_w2t_lo) +
                                       (size_t)tid * 256 + kc1 * 64;
            uint32_t dst = base + MS_B + ((c + 1) & 1) * 36864 + tid * 144;
#pragma unroll
            for (int j = 0; j < 8; j++) cp_async16(dst + j * 16, src + j * 8);
            CP_COMMIT();
            CP_WAIT1();
        } else {
            CP_WAIT0();
        }
        __syncthreads();
        int p = c >> 2, kc = c & 3;
        uint32_t aw = base + (p == 1 ? MS_ALO : MS_AHI) +
                      (wm * 64 * 264 + kc * 64) * 2;
        uint32_t bw = base + MS_B + buf * 36864 + (wn * 64) * 144;
        mma_chunk<264, 8>(acc, aw, bw, lane);
        __syncthreads();
    }
    // epilogue: atomic segment-sum
#pragma unroll
    for (int mt = 0; mt < 4; mt++) {
        int r0 = wm * 64 + mt * 16 + (lane >> 2);
        int r1 = r0 + 8;
        bool ok0 = (e0 + r0) < E, ok1 = (e0 + r1) < E;
        int t0 = to_sm[r0], t1 = to_sm[r1];
#pragma unroll
        for (int nt = 0; nt < 8; nt++) {
            int col = wn * 64 + nt * 8 + 2 * (lane & 3);
            float2 bb = *(const float2*)(b2 + col);
            if (ok0) {
                atomicAdd(&g_agg[(size_t)t0 * 256 + col],     acc[mt][nt][0] + bb.x);
                atomicAdd(&g_agg[(size_t)t0 * 256 + col + 1], acc[mt][nt][1] + bb.y);
            }
            if (ok1) {
                atomicAdd(&g_agg[(size_t)t1 * 256 + col],     acc[mt][nt][2] + bb.x);
                atomicAdd(&g_agg[(size_t)t1 * 256 + col + 1], acc[mt][nt][3] + bb.y);
            }
        }
    }
}

// ---------------------------------------------------------------------------
// K6: node update  h += [h|agg] @ Wut + bu   (ext-K = 1152, 18 chunks)
// ---------------------------------------------------------------------------
#define UP_A 0
#define UP_B 18432
#define UP_SMEM 55296
__global__ void __launch_bounds__(256, 1)
k_upd2(const float* __restrict__ bu, int N) {
    extern __shared__ unsigned char sm[];
    const uint32_t base = smem_to_u32(sm);
    const int tid = threadIdx.x, lane = tid & 31, wid = tid >> 5;
    const int n0 = blockIdx.x * 128;
    // prefetch B chunk 0
    {
        int row = tid >> 1, half = tid & 1;
        const __nv_bfloat16* src = g_wut_hi + (size_t)row * 384 + half * 32;
        uint32_t dst = base + UP_B + row * 144 + half * 64;
#pragma unroll
        for (int j = 0; j < 4; j++) cp_async16(dst + j * 16, src + j * 8);
        CP_COMMIT();
    }
    const int wm = wid >> 2, wn = wid & 3;
    float acc[4][4][4];
#pragma unroll
    for (int i = 0; i < 4; i++)
#pragma unroll
        for (int j = 0; j < 4; j++)
#pragma unroll
            for (int k = 0; k < 4; k++) acc[i][j][k] = 0.f;

    for (int c = 0; c < 18; c++) {
        int buf = c & 1;
        __syncthreads();  // prior mma done with A and B buffers
        if (c + 1 < 18) {
            int p1 = (c + 1) / 6, kc1 = (c + 1) % 6;
            int row = tid >> 1, half = tid & 1;
            const __nv_bfloat16* src = (p1 < 2 ? g_wut_hi : g_wut_lo) +
                                       (size_t)row * 384 + kc1 * 64 + half * 32;
            uint32_t dst =
                base + UP_B + ((c + 1) & 1) * 18432 + row * 144 + half * 64;
#pragma unroll
            for (int j = 0; j < 4; j++) cp_async16(dst + j * 16, src + j * 8);
            CP_COMMIT();
        }
        // build A chunk (fp32 -> hi or lo bf16)
        int p = c / 6, kc = c % 6, k0 = kc * 64;
        __nv_bfloat16* A = (__nv_bfloat16*)(sm + UP_A);
#pragma unroll 2
        for (int i = 0; i < 32; i++) {
            int idx = tid + 256 * i;
            int row = idx >> 6, cc = idx & 63;
            int kk = k0 + cc;
            float v = (kk < 128) ? g_h[(size_t)(n0 + row) * 128 + kk]
                                 : g_agg[(size_t)(n0 + row) * 256 + kk - 128];
            __nv_bfloat16 hi = __float2bfloat16(v);
            A[row * 72 + cc] =
                (p == 1) ? __float2bfloat16(v - __bfloat162float(hi)) : hi;
        }
        if (c + 1 < 18) CP_WAIT1(); else CP_WAIT0();
        __syncthreads();
        uint32_t aw = base + UP_A + (wm * 64 * 72) * 2;
        uint32_t bw = base + UP_B + buf * 18432 + (wn * 32) * 144;
        mma_chunk<72, 4>(acc, aw, bw, lane);
    }
    __syncthreads();
#pragma unroll
    for (int mt = 0; mt < 4; mt++) {
        int r0 = wm * 64 + mt * 16 + (lane >> 2);
        int n1 = n0 + r0, n2 = n1 + 8;
#pragma unroll
        for (int nt = 0; nt < 4; nt++) {
            int col = wn * 32 + nt * 8 + 2 * (lane & 3);
            float2 bb = *(const float2*)(bu + col);
            if (n1 < N) {
#pragma unroll
                for (int z = 0; z < 2; z++) {
                    float v = g_h[(size_t)n1 * 128 + col + z] + acc[mt][nt][z] +
                              (z ? bb.y : bb.x);
                    g_h[(size_t)n1 * 128 + col + z] = v;
                    __nv_bfloat16 hi = __float2bfloat16(v);
                    g_h_hi[(size_t)n1 * 128 + col + z] = hi;
                    g_h_lo[(size_t)n1 * 128 + col + z] =
                        __float2bfloat16(v - __bfloat162float(hi));
                }
            }
            if (n2 < N) {
#pragma unroll
                for (int z = 0; z < 2; z++) {
                    float v = g_h[(size_t)n2 * 128 + col + z] +
                              acc[mt][nt][2 + z] + (z ? bb.y : bb.x);
                    g_h[(size_t)n2 * 128 + col + z] = v;
                    __nv_bfloat16 hi = __float2bfloat16(v);
                    g_h_hi[(size_t)n2 * 128 + col + z] = hi;
                    g_h_lo[(size_t)n2 * 128 + col + z] =
                        __float2bfloat16(v - __bfloat162float(hi));
                }
            }
        }
    }
}

// ---------------------------------------------------------------------------
// K7: scatter into padded stacks
// ---------------------------------------------------------------------------
__global__ void k_scatter(const int* __restrict__ pos, int N) {
    int idx = blockIdx.x * 256 + threadIdx.x;
    if (idx >= N * 128) return;
    int n = idx >> 7, c = idx & 127;
    g_flat[pos[n] * 128 + c] = g_h[idx];
}

// ---------------------------------------------------------------------------
// K8: attention features (fp32, as in R1)
// ---------------------------------------------------------------------------
__global__ void __launch_bounds__(256, 1)
k_att(const float* __restrict__ Wa1, const float* __restrict__ ba1,
      const float* __restrict__ Wa2, const float* __restrict__ ba2,
      const int* __restrict__ qsz, const int* __restrict__ csz) {
    __shared__ float x_sm[128 * 33];
    __shared__ float h_sm[128 * 33];
    const int tid = threadIdx.x;
    const int r0 = blockIdx.x * 32;
    for (int idx = tid; idx < 32 * 128; idx += 256) {
        int r = idx >> 7, c = idx & 127;
        x_sm[c * 33 + r] = g_flat[(r0 + r) * 128 + c];
    }
    __syncthreads();
    const int c0 = tid & 127, rg = tid >> 7;
    float acc[16];
#pragma unroll
    for (int r = 0; r < 16; r++) acc[r] = 0.f;
#pragma unroll 4
    for (int k = 0; k < 128; k++) {
        float w = Wa1[k * 128 + c0];
        const float* a = x_sm + k * 33 + rg * 16;
#pragma unroll
        for (int r = 0; r < 16; r++) acc[r] += a[r] * w;
    }
    {
        float bb = ba1[c0];
        float* col = h_sm + c0 * 33 + rg * 16;
#pragma unroll
        for (int r = 0; r < 16; r++) col[r] = fmaxf(acc[r] + bb, 0.f);
    }
    __syncthreads();
#pragma unroll
    for (int r = 0; r < 16; r++) acc[r] = 0.f;
#pragma unroll 4
    for (int k = 0; k < 128; k++) {
        float w = Wa2[k * 128 + c0];
        const float* a = h_sm + k * 33 + rg * 16;
#pragma unroll
        for (int r = 0; r < 16; r++) acc[r] += a[r] * w;
    }
    float bb = ba2[c0];
#pragma unroll
    for (int r = 0; r < 16; r++) {
        int row = r0 + rg * 16 + r;
        int gi = row >> 6, q = row & 63;
        int size = (gi < 256) ? qsz[gi] : csz[gi - 256];
        g_t[row * 128 + c0] = (q < size) ? (acc[r] + bb) : 0.f;
    }
}

// ---------------------------------------------------------------------------
// K9: per-pair logits, dual softmax, hinge alignment, min
// ---------------------------------------------------------------------------
#define PAIR_SMEM ((2 * 64 * 129 + 3 * 64 * 65) * 4)
__global__ void __launch_bounds__(256, 1)
k_pair(const int* __restrict__ qsz, const int* __restrict__ csz,
       float* __restrict__ out) {
    extern __shared__ float smf[];
    float* bufA = smf;
    float* bufB = bufA + 64 * 129;
    float* L    = bufB + 64 * 129;
    float* pq   = L + 64 * 65;
    float* pc   = pq + 64 * 65;
    __shared__ float redq[8], redc[8];

    const int b = blockIdx.x, tid = threadIdx.x;
    const int qs = qsz[b], cs = csz[b];
    const int qbase = b * 64, cbase = 16384 + b * 64;

    for (int idx = tid; idx < 64 * 128; idx += 256) {
        int r = idx >> 7, k = idx & 127;
        bufA[r * 129 + k] = g_t[(qbase + r) * 128 + k];
        bufB[r * 129 + k] = g_t[(cbase + r) * 128 + k];
    }
    __syncthreads();
    {
        int q = tid >> 2, cg = tid & 3;
        float acc[16];
#pragma unroll
        for (int j = 0; j < 16; j++) acc[j] = 0.f;
        for (int k = 0; k < 128; k++) {
            float a = bufA[q * 129 + k];
            const float* bp = bufB + (cg * 16) * 129 + k;
#pragma unroll
            for (int j = 0; j < 16; j++) acc[j] += a * bp[j * 129];
        }
        bool qv = q < qs;
#pragma unroll
        for (int j = 0; j < 16; j++) {
            int c = cg * 16 + j;
            L[q * 65 + c] = (qv && c < cs) ? acc[j] * 10.0f : -1e9f;
        }
    }
    __syncthreads();
    for (int idx = tid; idx < 64 * 128; idx += 256) {
        int r = idx >> 7, k = idx & 127;
        bufA[r * 129 + k] = g_flat[(qbase + r) * 128 + k];
        bufB[r * 129 + k] = g_flat[(cbase + r) * 128 + k];
    }
    if (tid < 64) {
        float m = -1e30f;
        for (int c = 0; c < 64; c++) m = fmaxf(m, L[tid * 65 + c]);
        float s = 0.f;
        for (int c = 0; c < 64; c++) {
            float ex = __expf(L[tid * 65 + c] - m);
            s += ex;
            pq[tid * 65 + c] = ex;
        }
        float inv = (tid < qs) ? (1.0f / s) : 0.f;
        for (int c = 0; c < 64; c++) pq[tid * 65 + c] *= inv;
    } else if (tid < 128) {
        int c = tid - 64;
        float m = -1e30f;
        for (int q = 0; q < 64; q++) m = fmaxf(m, L[q * 65 + c]);
        float s = 0.f;
        for (int q = 0; q < 64; q++) {
            float ex = __expf(L[q * 65 + c] - m);
            s += ex;
            pc[q * 65 + c] = ex;
        }
        float inv = (c < cs) ? (1.0f / s) : 0.f;
        for (int q = 0; q < 64; q++) pc[q * 65 + c] *= inv;
    }
    __syncthreads();
    float lq = 0.f, lc = 0.f;
    {
        const int d = tid & 127, gg = tid >> 7;
        float acc[32];
#pragma unroll
        for (int j = 0; j < 32; j++) acc[j] = 0.f;
        for (int c = 0; c < 64; c++) {
            float bb = bufB[c * 129 + d];
            const float* pp = pq + (gg * 32) * 65 + c;
#pragma unroll
            for (int j = 0; j < 32; j++) acc[j] += pp[j * 65] * bb;
        }
#pragma unroll
        for (int j = 0; j < 32; j++) {
            int q = gg * 32 + j;
            lq += fmaxf(bufA[q * 129 + d] - acc[j], 0.f);
        }
#pragma unroll
        for (int j = 0; j < 32; j++) acc[j] = 0.f;
        for (int q = 0; q < 64; q++) {
            float aa = bufA[q * 129 + d];
            const float* pp = pc + q * 65 + gg * 32;
#pragma unroll
            for (int j = 0; j < 32; j++) acc[j] += pp[j] * aa;
        }
#pragma unroll
        for (int j = 0; j < 32; j++) {
            int c = gg * 32 + j;
            lc += fmaxf(bufB[c * 129 + d] - acc[j], 0.f);
        }
    }
    for (int o = 16; o; o >>= 1) {
        lq += __shfl_down_sync(0xffffffffu, lq, o);
        lc += __shfl_down_sync(0xffffffffu, lc, o);
    }
    int w = tid >> 5, lane = tid & 31;
    if (lane == 0) { redq[w] = lq; redc[w] = lc; }
    __syncthreads();
    if (tid == 0) {
        float sq = 0.f, sc = 0.f;
        for (int i = 0; i < 8; i++) { sq += redq[i]; sc += redc[i]; }
        out[b] = fminf(-sq, -sc);
    }
}

// ---------------------------------------------------------------------------
extern "C" void kernel_launch(void* const* d_in, const int* in_sizes, int n_in,
                              void* d_out, int out_size) {
    const float* nf       = (const float*)d_in[0];
    const float* ef       = (const float*)d_in[1];
    const int*   from_idx = (const int*)d_in[2];
    const int*   to_idx   = (const int*)d_in[3];
    const int*   pos      = (const int*)d_in[4];
    const int*   qsz      = (const int*)d_in[5];
    const int*   csz      = (const int*)d_in[6];
    const float* W_node = (const float*)d_in[7];
    const float* b_node = (const float*)d_in[8];
    const float* W_edge = (const float*)d_in[9];
    const float* b_edge = (const float*)d_in[10];
    const float* W_msg1 = (const float*)d_in[11];
    const float* b_msg1 = (const float*)d_in[12];
    const float* W_msg2 = (const float*)d_in[13];
    const float* b_msg2 = (const float*)d_in[14];
    const float* W_upd  = (const float*)d_in[15];
    const float* b_upd  = (const float*)d_in[16];
    const float* Wa1    = (const float*)d_in[17];
    const float* ba1    = (const float*)d_in[18];
    const float* Wa2    = (const float*)d_in[19];
    const float* ba2    = (const float*)d_in[20];

    const int N = in_sizes[0] / 32;
    const int E = in_sizes[1] / 16;

    cudaFuncSetAttribute(k_pe,       cudaFuncAttributeMaxDynamicSharedMemorySize, PE_SMEM);
    cudaFuncSetAttribute(k_nodeprod, cudaFuncAttributeMaxDynamicSharedMemorySize, NP_SMEM);
    cudaFuncSetAttribute(k_msg2,     cudaFuncAttributeMaxDynamicSharedMemorySize, MS_SMEM);
    cudaFuncSetAttribute(k_upd2,     cudaFuncAttributeMaxDynamicSharedMemorySize, UP_SMEM);
    cudaFuncSetAttribute(k_pair,     cudaFuncAttributeMaxDynamicSharedMemorySize, PAIR_SMEM);

    void* aggp = nullptr;
    void* flatp = nullptr;
    cudaGetSymbolAddress(&aggp, g_agg);
    cudaGetSymbolAddress(&flatp, g_flat);

    const int egrid = (E + 127) / 128;
    const int ngrid = (N + 127) / 128;

    k_prep<<<768, 256>>>(W_msg1, W_msg2, W_upd);
    k_enc_node<<<(N * 128 + 255) / 256, 256>>>(nf, W_node, b_node, N);
    k_enc_edge<<<(E * 64 + 255) / 256, 256>>>(ef, W_edge, b_edge, E);
    k_pe<<<egrid, 256, PE_SMEM>>>(b_msg1, E);

    for (int s = 0; s < 3; s++) {
        cudaMemsetAsync(aggp, 0, (size_t)N * 256 * sizeof(float));
        k_nodeprod<<<ngrid * 2, 256, NP_SMEM>>>(N);
        k_msg2<<<egrid, 256, MS_SMEM>>>(b_msg2, from_idx, to_idx, E);
        k_upd2<<<ngrid, 256, UP_SMEM>>>(b_upd, N);
    }

    cudaMemsetAsync(flatp, 0, (size_t)2 * 256 * 64 * 128 * sizeof(float));
    k_scatter<<<(N * 128 + 255) / 256, 256>>>(pos, N);
    k_att<<<(2 * 256 * 64) / 32, 256>>>(Wa1, ba1, Wa2, ba2, qsz, csz);
    k_pair<<<256, 256, PAIR_SMEM>>>(qsz, csz, (float*)d_out);
}

// round 4
// speedup vs baseline: 3.3064x; 1.2987x over previous
#include <cuda_runtime.h>
#include <cuda_bf16.h>
#include <cstdint>

// ---------------------------------------------------------------------------
// Constants: B=256 pairs, MAX=64, D=128, E_DIM=64, 3 prop steps
// ---------------------------------------------------------------------------
#define NMAX 32768
#define EMAX 262144

// Scratch
__device__ float g_h   [NMAX * 128];
__device__ float g_agg [NMAX * 256];
__device__ float g_flat[2 * 256 * 64 * 128];
__device__ float g_t   [2 * 256 * 64 * 128];
__device__ float g_P   [NMAX * 512];          // per-step node products [P1|P2]
__device__ float g_pe  [(size_t)EMAX * 256];  // edge part of GEMM1 (+b1)
__device__ __align__(16) __nv_bfloat16 g_h_hi[NMAX * 128];
__device__ __align__(16) __nv_bfloat16 g_h_lo[NMAX * 128];
__device__ __align__(16) __nv_bfloat16 g_e_hi[EMAX * 64];
__device__ __align__(16) __nv_bfloat16 g_e_lo[EMAX * 64];
// Pre-split transposed weights Bt[n][k] (row-major, bf16 hi/lo)
__device__ __align__(16) __nv_bfloat16 g_w1p_hi[512 * 128], g_w1p_lo[512 * 128];
__device__ __align__(16) __nv_bfloat16 g_w1e_hi[256 * 64],  g_w1e_lo[256 * 64];
__device__ __align__(16) __nv_bfloat16 g_w2t_hi[256 * 256], g_w2t_lo[256 * 256];
__device__ __align__(16) __nv_bfloat16 g_wut_hi[128 * 384], g_wut_lo[128 * 384];
__device__ __align__(16) __nv_bfloat16 g_wa1t_hi[128 * 128], g_wa1t_lo[128 * 128];
__device__ __align__(16) __nv_bfloat16 g_wa2t_hi[128 * 128], g_wa2t_lo[128 * 128];

// ---------------------------------------------------------------------------
// helpers
// ---------------------------------------------------------------------------
__device__ __forceinline__ uint32_t smem_to_u32(const void* p) {
    uint32_t a;
    asm("{ .reg .u64 t; cvta.to.shared.u64 t, %1; cvt.u32.u64 %0, t; }"
        : "=r"(a) : "l"(p));
    return a;
}
__device__ __forceinline__ void ldsm_x4(uint32_t r[4], uint32_t addr) {
    asm volatile("ldmatrix.sync.aligned.m8n8.x4.shared.b16 {%0,%1,%2,%3}, [%4];"
                 : "=r"(r[0]), "=r"(r[1]), "=r"(r[2]), "=r"(r[3]) : "r"(addr));
}
__device__ __forceinline__ void mma_bf16(float c[4], const uint32_t a[4],
                                         uint32_t b0, uint32_t b1) {
    asm volatile(
        "mma.sync.aligned.m16n8k16.row.col.f32.bf16.bf16.f32 "
        "{%0,%1,%2,%3}, {%4,%5,%6,%7}, {%8,%9}, {%0,%1,%2,%3};"
        : "+f"(c[0]), "+f"(c[1]), "+f"(c[2]), "+f"(c[3])
        : "r"(a[0]), "r"(a[1]), "r"(a[2]), "r"(a[3]), "r"(b0), "r"(b1));
}
__device__ __forceinline__ void cp_async16(uint32_t smem, const void* g) {
    asm volatile("cp.async.ca.shared.global [%0], [%1], 16;"
                 :: "r"(smem), "l"(g));
}
#define CP_COMMIT() asm volatile("cp.async.commit_group;" ::: "memory")
#define CP_WAIT0()  asm volatile("cp.async.wait_group 0;" ::: "memory")

__device__ __forceinline__ uint32_t pkbf(float a, float b) {
    __nv_bfloat162 t = __floats2bfloat162_rn(a, b);
    return *reinterpret_cast<uint32_t*>(&t);
}

// One 64-k chunk of warp MMA: warp tile 64 rows x (NT*8) cols.
// A stride SA (bf16 elems), B stride 72.
template <int SA, int NT>
__device__ __forceinline__ void mma_chunk(float (&acc)[4][NT][4],
                                          uint32_t aw, uint32_t bw, int lane) {
    const int arow = lane & 15, ak = (lane >> 4) << 3;
    const int brow = (lane & 7) + ((lane >> 4) << 3);
    const int bk = ((lane >> 3) & 1) << 3;
#pragma unroll
    for (int kt = 0; kt < 4; kt++) {
        uint32_t a[4][4], b[NT / 2][4];
#pragma unroll
        for (int mt = 0; mt < 4; mt++)
            ldsm_x4(a[mt], aw + ((mt * 16 + arow) * SA + kt * 16 + ak) * 2);
#pragma unroll
        for (int nb = 0; nb < NT / 2; nb++)
            ldsm_x4(b[nb], bw + ((nb * 16 + brow) * 72 + kt * 16 + bk) * 2);
#pragma unroll
        for (int mt = 0; mt < 4; mt++)
#pragma unroll
            for (int nb = 0; nb < NT / 2; nb++) {
                mma_bf16(acc[mt][2 * nb],     a[mt], b[nb][0], b[nb][1]);
                mma_bf16(acc[mt][2 * nb + 1], a[mt], b[nb][2], b[nb][3]);
            }
    }
}

// Common smem layout for the 64-k sliced kernels
#define SL_AHI 0
#define SL_ALO 18432
#define SL_BHI 36864
#define SL_BLO 55296
#define SL_END 73728

// ---------------------------------------------------------------------------
// K0: weight prep — transpose + hi/lo split
// ---------------------------------------------------------------------------
__global__ void k_prep(const float* __restrict__ W1, const float* __restrict__ W2,
                       const float* __restrict__ Wu, const float* __restrict__ Wa1,
                       const float* __restrict__ Wa2) {
    int idx = blockIdx.x * 256 + threadIdx.x;
    float v;
    __nv_bfloat16 *dh, *dl;
    int off;
    if (idx < 65536) {                       // g_w1p [512n][128k]
        int n = idx >> 7, k = idx & 127;
        v = (n < 256) ? W1[k * 256 + n] : W1[(128 + k) * 256 + (n - 256)];
        dh = g_w1p_hi; dl = g_w1p_lo; off = idx;
    } else if (idx < 81920) {                // g_w1e [256n][64k]
        int i = idx - 65536;
        int n = i >> 6, k = i & 63;
        v = W1[(256 + k) * 256 + n];
        dh = g_w1e_hi; dl = g_w1e_lo; off = i;
    } else if (idx < 147456) {               // g_w2t [256n][256k]
        int i = idx - 81920;
        int n = i >> 8, k = i & 255;
        v = W2[k * 256 + n];
        dh = g_w2t_hi; dl = g_w2t_lo; off = i;
    } else if (idx < 196608) {               // g_wut [128n][384k]
        int i = idx - 147456;
        int n = i / 384, k = i - n * 384;
        v = Wu[k * 128 + n];
        dh = g_wut_hi; dl = g_wut_lo; off = i;
    } else if (idx < 212992) {               // g_wa1t [128n][128k]
        int i = idx - 196608;
        int n = i >> 7, k = i & 127;
        v = Wa1[k * 128 + n];
        dh = g_wa1t_hi; dl = g_wa1t_lo; off = i;
    } else {                                 // g_wa2t
        int i = idx - 212992;
        if (i >= 16384) return;
        int n = i >> 7, k = i & 127;
        v = Wa2[k * 128 + n];
        dh = g_wa2t_hi; dl = g_wa2t_lo; off = i;
    }
    __nv_bfloat16 hi = __float2bfloat16(v);
    dh[off] = hi;
    dl[off] = __float2bfloat16(v - __bfloat162float(hi));
}

// ---------------------------------------------------------------------------
// K1/K2: encoders
// ---------------------------------------------------------------------------
__global__ void k_enc_node(const float* __restrict__ nf,
                           const float* __restrict__ Wn,
                           const float* __restrict__ bn, int N) {
    __shared__ float Ws[32 * 128];
    for (int i = threadIdx.x; i < 32 * 128; i += 256) Ws[i] = Wn[i];
    __syncthreads();
    int idx = blockIdx.x * 256 + threadIdx.x;
    if (idx >= N * 128) return;
    int n = idx >> 7, c = idx & 127;
    const float* row = nf + n * 32;
    float s = bn[c];
#pragma unroll
    for (int k = 0; k < 32; k++) s += row[k] * Ws[k * 128 + c];
    g_h[idx] = s;
    __nv_bfloat16 hi = __float2bfloat16(s);
    g_h_hi[idx] = hi;
    g_h_lo[idx] = __float2bfloat16(s - __bfloat162float(hi));
}

__global__ void k_enc_edge(const float* __restrict__ ef,
                           const float* __restrict__ We,
                           const float* __restrict__ be, int E) {
    __shared__ float Ws[16 * 64];
    for (int i = threadIdx.x; i < 16 * 64; i += 256) Ws[i] = We[i];
    __syncthreads();
    int idx = blockIdx.x * 256 + threadIdx.x;
    if (idx >= E * 64) return;
    int ed = idx >> 6, c = idx & 63;
    const float* row = ef + ed * 16;
    float s = be[c];
#pragma unroll
    for (int k = 0; k < 16; k++) s += row[k] * Ws[k * 64 + c];
    __nv_bfloat16 hi = __float2bfloat16(s);
    g_e_hi[idx] = hi;
    g_e_lo[idx] = __float2bfloat16(s - __bfloat162float(hi));
}

// ---------------------------------------------------------------------------
// K3: Pe = e @ W1_bot + b1  (once).  Tile: 128 edges x 128 cols, K=64.
// ---------------------------------------------------------------------------
__global__ void __launch_bounds__(256, 2)
k_pe2(const float* __restrict__ b1, int E) {
    extern __shared__ unsigned char sm[];
    const uint32_t base = smem_to_u32(sm);
    const int tid = threadIdx.x, lane = tid & 31, wid = tid >> 5;
    const int cb = blockIdx.x & 1, eb = blockIdx.x >> 1;
    const int e0 = eb * 128;
    // B cp.async: rows cb*128..+128 of w1e, hi/lo
    {
        int row = tid & 127, which = tid >> 7;
        const __nv_bfloat16* src =
            (which ? g_w1e_lo : g_w1e_hi) + (size_t)(cb * 128 + row) * 64;
        uint32_t dst = base + (which ? SL_BLO : SL_BHI) + row * 144;
#pragma unroll
        for (int j = 0; j < 8; j++) cp_async16(dst + j * 16, src + j * 8);
        CP_COMMIT();
    }
    // A copy: e rows hi/lo
    {
        int row = tid & 127, which = tid >> 7;
        const __nv_bfloat16* src =
            (which ? g_e_lo : g_e_hi) + (size_t)(e0 + row) * 64;
        unsigned char* dst = sm + (which ? SL_ALO : SL_AHI) + row * 144;
#pragma unroll
        for (int j = 0; j < 8; j++)
            *(uint4*)(dst + j * 16) = *(const uint4*)(src + j * 8);
    }
    CP_WAIT0();
    __syncthreads();
    const int wm = wid >> 2, wn = wid & 3;
    float acc[4][4][4];
#pragma unroll
    for (int i = 0; i < 4; i++)
#pragma unroll
        for (int j = 0; j < 4; j++)
#pragma unroll
            for (int k = 0; k < 4; k++) acc[i][j][k] = 0.f;
#pragma unroll
    for (int p = 0; p < 3; p++) {
        uint32_t aw = base + (p == 1 ? SL_ALO : SL_AHI) + (wm * 64 * 72) * 2;
        uint32_t bw = base + (p == 2 ? SL_BLO : SL_BHI) + (wn * 32) * 144;
        mma_chunk<72, 4>(acc, aw, bw, lane);
    }
#pragma unroll
    for (int mt = 0; mt < 4; mt++) {
        int r0 = wm * 64 + mt * 16 + (lane >> 2);
#pragma unroll
        for (int nt = 0; nt < 4; nt++) {
            int col = cb * 128 + wn * 32 + nt * 8 + 2 * (lane & 3);
            float2 bb = *(const float2*)(b1 + col);
            *(float2*)(g_pe + (size_t)(e0 + r0) * 256 + col) =
                make_float2(acc[mt][nt][0] + bb.x, acc[mt][nt][1] + bb.y);
            *(float2*)(g_pe + (size_t)(e0 + r0 + 8) * 256 + col) =
                make_float2(acc[mt][nt][2] + bb.x, acc[mt][nt][3] + bb.y);
        }
    }
}

// ---------------------------------------------------------------------------
// K4: P12 = h @ [W1_top|W1_mid].  Tile: 128 nodes x 128 cols, K=128 (2 slices)
// ---------------------------------------------------------------------------
__global__ void __launch_bounds__(256, 2)
k_nodeprod(int N) {
    extern __shared__ unsigned char sm[];
    const uint32_t base = smem_to_u32(sm);
    const int tid = threadIdx.x, lane = tid & 31, wid = tid >> 5;
    const int cb = blockIdx.x & 3, rb = blockIdx.x >> 2;
    const int n0 = rb * 128;
    const int wm = wid >> 2, wn = wid & 3;
    float acc[4][4][4];
#pragma unroll
    for (int i = 0; i < 4; i++)
#pragma unroll
        for (int j = 0; j < 4; j++)
#pragma unroll
            for (int k = 0; k < 4; k++) acc[i][j][k] = 0.f;

    for (int kc = 0; kc < 2; kc++) {
        // B cp.async
        {
            int row = tid & 127, which = tid >> 7;
            const __nv_bfloat16* src =
                (which ? g_w1p_lo : g_w1p_hi) +
                (size_t)(cb * 128 + row) * 128 + kc * 64;
            uint32_t dst = base + (which ? SL_BLO : SL_BHI) + row * 144;
#pragma unroll
            for (int j = 0; j < 8; j++) cp_async16(dst + j * 16, src + j * 8);
            CP_COMMIT();
        }
        // A copy
        {
            int row = tid & 127, which = tid >> 7;
            const __nv_bfloat16* src =
                (which ? g_h_lo : g_h_hi) + (size_t)(n0 + row) * 128 + kc * 64;
            unsigned char* dst = sm + (which ? SL_ALO : SL_AHI) + row * 144;
#pragma unroll
            for (int j = 0; j < 8; j++)
                *(uint4*)(dst + j * 16) = *(const uint4*)(src + j * 8);
        }
        CP_WAIT0();
        __syncthreads();
#pragma unroll
        for (int p = 0; p < 3; p++) {
            uint32_t aw = base + (p == 1 ? SL_ALO : SL_AHI) + (wm * 64 * 72) * 2;
            uint32_t bw = base + (p == 2 ? SL_BLO : SL_BHI) + (wn * 32) * 144;
            mma_chunk<72, 4>(acc, aw, bw, lane);
        }
        __syncthreads();
    }
#pragma unroll
    for (int mt = 0; mt < 4; mt++) {
        int r0 = wm * 64 + mt * 16 + (lane >> 2);
        int n1 = n0 + r0, n2 = n1 + 8;
#pragma unroll
        for (int nt = 0; nt < 4; nt++) {
            int col = cb * 128 + wn * 32 + nt * 8 + 2 * (lane & 3);
            if (n1 < N)
                *(float2*)(g_P + (size_t)n1 * 512 + col) =
                    make_float2(acc[mt][nt][0], acc[mt][nt][1]);
            if (n2 < N)
                *(float2*)(g_P + (size_t)n2 * 512 + col) =
                    make_float2(acc[mt][nt][2], acc[mt][nt][3]);
        }
    }
}

// ---------------------------------------------------------------------------
// K5: msg = relu(P1[from]+P2[to]+Pe) @ W2 + segment-sum.
//     Tile: 128 edges x 128 cols, ext-K sliced (4 x 64, 3 passes each).
// ---------------------------------------------------------------------------
#define MS_FROM SL_END
#define MS_TO   (SL_END + 512)
#define MS_SMEM (SL_END + 1024)
__global__ void __launch_bounds__(256, 2)
k_msg2(const float* __restrict__ b2, const int* __restrict__ from_idx,
       const int* __restrict__ to_idx, int E) {
    extern __shared__ unsigned char sm[];
    const uint32_t base = smem_to_u32(sm);
    const int tid = threadIdx.x, lane = tid & 31, wid = tid >> 5;
    const int cb = blockIdx.x & 1, eb = blockIdx.x >> 1;
    const int e0 = eb * 128;
    int* from_sm = (int*)(sm + MS_FROM);
    int* to_sm   = (int*)(sm + MS_TO);
    if (tid < 128) {
        int ed = e0 + tid;
        from_sm[tid] = (ed < E) ? from_idx[ed] : 0;
        to_sm[tid]   = (ed < E) ? to_idx[ed] : 0;
    }
    __syncthreads();
    const int wm = wid >> 2, wn = wid & 3;
    float acc[4][4][4];
#pragma unroll
    for (int i = 0; i < 4; i++)
#pragma unroll
        for (int j = 0; j < 4; j++)
#pragma unroll
            for (int k = 0; k < 4; k++) acc[i][j][k] = 0.f;

    for (int kc = 0; kc < 4; kc++) {
        // B cp.async: W2t rows cb*128..+128, k slice kc
        {
            int row = tid & 127, which = tid >> 7;
            const __nv_bfloat16* src =
                (which ? g_w2t_lo : g_w2t_hi) +
                (size_t)(cb * 128 + row) * 256 + kc * 64;
            uint32_t dst = base + (which ? SL_BLO : SL_BHI) + row * 144;
#pragma unroll
            for (int j = 0; j < 8; j++) cp_async16(dst + j * 16, src + j * 8);
            CP_COMMIT();
        }
        // A build: hidden slice = relu(P1[from]+P2[to]+Pe), split hi/lo
#pragma unroll 2
        for (int i = 0; i < 8; i++) {
            int idx = tid + 256 * i;
            int row = idx >> 4, q = idx & 15;
            int col = kc * 64 + q * 4;
            const float4 v1 =
                *(const float4*)(g_P + (size_t)from_sm[row] * 512 + col);
            const float4 v2 =
                *(const float4*)(g_P + (size_t)to_sm[row] * 512 + 256 + col);
            const float4 ve =
                *(const float4*)(g_pe + (size_t)(e0 + row) * 256 + col);
            float s0 = fmaxf(v1.x + v2.x + ve.x, 0.f);
            float s1 = fmaxf(v1.y + v2.y + ve.y, 0.f);
            float s2 = fmaxf(v1.z + v2.z + ve.z, 0.f);
            float s3 = fmaxf(v1.w + v2.w + ve.w, 0.f);
            __nv_bfloat16 h0 = __float2bfloat16(s0), h1 = __float2bfloat16(s1);
            __nv_bfloat16 h2 = __float2bfloat16(s2), h3 = __float2bfloat16(s3);
            uint2 hp, lp;
            hp.x = pkbf(s0, s1); hp.y = pkbf(s2, s3);
            lp.x = pkbf(s0 - __bfloat162float(h0), s1 - __bfloat162float(h1));
            lp.y = pkbf(s2 - __bfloat162float(h2), s3 - __bfloat162float(h3));
            int boff = (row * 72 + q * 4) * 2;
            *(uint2*)(sm + SL_AHI + boff) = hp;
            *(uint2*)(sm + SL_ALO + boff) = lp;
        }
        CP_WAIT0();
        __syncthreads();
#pragma unroll
        for (int p = 0; p < 3; p++) {
            uint32_t aw = base + (p == 1 ? SL_ALO : SL_AHI) + (wm * 64 * 72) * 2;
            uint32_t bw = base + (p == 2 ? SL_BLO : SL_BHI) + (wn * 32) * 144;
            mma_chunk<72, 4>(acc, aw, bw, lane);
        }
        __syncthreads();
    }
    // epilogue: atomic segment-sum
#pragma unroll
    for (int mt = 0; mt < 4; mt++) {
        int r0 = wm * 64 + mt * 16 + (lane >> 2);
        int r1 = r0 + 8;
        bool ok0 = (e0 + r0) < E, ok1 = (e0 + r1) < E;
        int t0 = to_sm[r0], t1 = to_sm[r1];
#pragma unroll
        for (int nt = 0; nt < 4; nt++) {
            int col = cb * 128 + wn * 32 + nt * 8 + 2 * (lane & 3);
            float2 bb = *(const float2*)(b2 + col);
            if (ok0) {
                atomicAdd(&g_agg[(size_t)t0 * 256 + col],     acc[mt][nt][0] + bb.x);
                atomicAdd(&g_agg[(size_t)t0 * 256 + col + 1], acc[mt][nt][1] + bb.y);
            }
            if (ok1) {
                atomicAdd(&g_agg[(size_t)t1 * 256 + col],     acc[mt][nt][2] + bb.x);
                atomicAdd(&g_agg[(size_t)t1 * 256 + col + 1], acc[mt][nt][3] + bb.y);
            }
        }
    }
}

// ---------------------------------------------------------------------------
// K6: node update  h += [h|agg] @ Wut + bu.  Tile: 128 nodes x 128 cols,
//     K=384 (6 slices, 3 passes each), A split on the fly.
// ---------------------------------------------------------------------------
__global__ void __launch_bounds__(256, 2)
k_upd2(const float* __restrict__ bu, int N) {
    extern __shared__ unsigned char sm[];
    const uint32_t base = smem_to_u32(sm);
    const int tid = threadIdx.x, lane = tid & 31, wid = tid >> 5;
    const int n0 = blockIdx.x * 128;
    const int wm = wid >> 2, wn = wid & 3;
    float acc[4][4][4];
#pragma unroll
    for (int i = 0; i < 4; i++)
#pragma unroll
        for (int j = 0; j < 4; j++)
#pragma unroll
            for (int k = 0; k < 4; k++) acc[i][j][k] = 0.f;

    for (int kc = 0; kc < 6; kc++) {
        // B cp.async: Wut rows 0..127, k slice kc
        {
            int row = tid & 127, which = tid >> 7;
            const __nv_bfloat16* src =
                (which ? g_wut_lo : g_wut_hi) + (size_t)row * 384 + kc * 64;
            uint32_t dst = base + (which ? SL_BLO : SL_BHI) + row * 144;
#pragma unroll
            for (int j = 0; j < 8; j++) cp_async16(dst + j * 16, src + j * 8);
            CP_COMMIT();
        }
        // A build from fp32 [h|agg]
#pragma unroll 2
        for (int i = 0; i < 8; i++) {
            int idx = tid + 256 * i;
            int row = idx >> 4, q = idx & 15;
            float4 v;
            if (kc < 2)
                v = *(const float4*)(g_h + (size_t)(n0 + row) * 128 +
                                     kc * 64 + q * 4);
            else
                v = *(const float4*)(g_agg + (size_t)(n0 + row) * 256 +
                                     (kc - 2) * 64 + q * 4);
            __nv_bfloat16 h0 = __float2bfloat16(v.x), h1 = __float2bfloat16(v.y);
            __nv_bfloat16 h2 = __float2bfloat16(v.z), h3 = __float2bfloat16(v.w);
            uint2 hp, lp;
            hp.x = pkbf(v.x, v.y); hp.y = pkbf(v.z, v.w);
            lp.x = pkbf(v.x - __bfloat162float(h0), v.y - __bfloat162float(h1));
            lp.y = pkbf(v.z - __bfloat162float(h2), v.w - __bfloat162float(h3));
            int boff = (row * 72 + q * 4) * 2;
            *(uint2*)(sm + SL_AHI + boff) = hp;
            *(uint2*)(sm + SL_ALO + boff) = lp;
        }
        CP_WAIT0();
        __syncthreads();
#pragma unroll
        for (int p = 0; p < 3; p++) {
            uint32_t aw = base + (p == 1 ? SL_ALO : SL_AHI) + (wm * 64 * 72) * 2;
            uint32_t bw = base + (p == 2 ? SL_BLO : SL_BHI) + (wn * 32) * 144;
            mma_chunk<72, 4>(acc, aw, bw, lane);
        }
        __syncthreads();
    }
#pragma unroll
    for (int mt = 0; mt < 4; mt++) {
        int rr[2];
        rr[0] = wm * 64 + mt * 16 + (lane >> 2);
        rr[1] = rr[0] + 8;
#pragma unroll
        for (int nt = 0; nt < 4; nt++) {
            int col = wn * 32 + nt * 8 + 2 * (lane & 3);
            float2 bb = *(const float2*)(bu + col);
#pragma unroll
            for (int h = 0; h < 2; h++) {
                int n = n0 + rr[h];
                if (n < N) {
#pragma unroll
                    for (int z = 0; z < 2; z++) {
                        float v = g_h[(size_t)n * 128 + col + z] +
                                  acc[mt][nt][2 * h + z] + (z ? bb.y : bb.x);
                        g_h[(size_t)n * 128 + col + z] = v;
                        __nv_bfloat16 hi = __float2bfloat16(v);
                        g_h_hi[(size_t)n * 128 + col + z] = hi;
                        g_h_lo[(size_t)n * 128 + col + z] =
                            __float2bfloat16(v - __bfloat162float(hi));
                    }
                }
            }
        }
    }
}

// ---------------------------------------------------------------------------
// K7: scatter into padded stacks (padded rows stay zero from load)
// ---------------------------------------------------------------------------
__global__ void k_scatter(const int* __restrict__ pos, int N) {
    int idx = blockIdx.x * 256 + threadIdx.x;
    if (idx >= N * 128) return;
    int n = idx >> 7, c = idx & 127;
    g_flat[pos[n] * 128 + c] = g_h[idx];
}

// ---------------------------------------------------------------------------
// K8: attention features via MMA.  t = relu(x@Wa1+ba1)@Wa2+ba2, masked.
//     Tile: 128 rows x 128 cols.  Stage1 buffers aliased by hidden tile.
// ---------------------------------------------------------------------------
#define AT_HIDHI 0
#define AT_HIDLO 34816
#define AT_B2HI  73728
#define AT_B2LO  92160
#define AT_SMEM  110592
__global__ void __launch_bounds__(256, 2)
k_att2(const float* __restrict__ ba1, const float* __restrict__ ba2,
       const int* __restrict__ qsz, const int* __restrict__ csz) {
    extern __shared__ unsigned char sm[];
    const uint32_t base = smem_to_u32(sm);
    const int tid = threadIdx.x, lane = tid & 31, wid = tid >> 5;
    const int r0 = blockIdx.x * 128;
    const int wm = wid >> 2, wn = wid & 3;
    float acc[4][4][4];
#pragma unroll
    for (int i = 0; i < 4; i++)
#pragma unroll
        for (int j = 0; j < 4; j++)
#pragma unroll
            for (int k = 0; k < 4; k++) acc[i][j][k] = 0.f;

    // ---- stage 1: hidden = relu(x @ Wa1 + ba1) ----
    for (int kc = 0; kc < 2; kc++) {
        {
            int row = tid & 127, which = tid >> 7;
            const __nv_bfloat16* src =
                (which ? g_wa1t_lo : g_wa1t_hi) + (size_t)row * 128 + kc * 64;
            uint32_t dst = base + (which ? AT_B2LO : AT_B2HI) + row * 144;
#pragma unroll
            for (int j = 0; j < 8; j++) cp_async16(dst + j * 16, src + j * 8);
            CP_COMMIT();
        }
#pragma unroll 2
        for (int i = 0; i < 8; i++) {
            int idx = tid + 256 * i;
            int row = idx >> 4, q = idx & 15;
            float4 v = *(const float4*)(g_flat + (size_t)(r0 + row) * 128 +
                                        kc * 64 + q * 4);
            __nv_bfloat16 h0 = __float2bfloat16(v.x), h1 = __float2bfloat16(v.y);
            __nv_bfloat16 h2 = __float2bfloat16(v.z), h3 = __float2bfloat16(v.w);
            uint2 hp, lp;
            hp.x = pkbf(v.x, v.y); hp.y = pkbf(v.z, v.w);
            lp.x = pkbf(v.x - __bfloat162float(h0), v.y - __bfloat162float(h1));
            lp.y = pkbf(v.z - __bfloat162float(h2), v.w - __bfloat162float(h3));
            int boff = (row * 72 + q * 4) * 2;
            *(uint2*)(sm + SL_AHI + boff) = hp;
            *(uint2*)(sm + SL_ALO + boff) = lp;
        }
        CP_WAIT0();
        __syncthreads();
#pragma unroll
        for (int p = 0; p < 3; p++) {
            uint32_t aw = base + (p == 1 ? SL_ALO : SL_AHI) + (wm * 64 * 72) * 2;
            uint32_t bw = base + (p == 2 ? AT_B2LO : AT_B2HI) + (wn * 32) * 144;
            mma_chunk<72, 4>(acc, aw, bw, lane);
        }
        __syncthreads();
    }
    // relu+bias -> hidden hi/lo (aliases stage-1 A buffers; stride 136)
#pragma unroll
    for (int mt = 0; mt < 4; mt++) {
        int rr0 = wm * 64 + mt * 16 + (lane >> 2);
#pragma unroll
        for (int nt = 0; nt < 4; nt++) {
            int col = wn * 32 + nt * 8 + 2 * (lane & 3);
            float2 bb = *(const float2*)(ba1 + col);
#pragma unroll
            for (int h = 0; h < 2; h++) {
                int row = rr0 + h * 8;
                float v0 = fmaxf(acc[mt][nt][2 * h]     + bb.x, 0.f);
                float v1 = fmaxf(acc[mt][nt][2 * h + 1] + bb.y, 0.f);
                __nv_bfloat16 b0 = __float2bfloat16(v0), b1 = __float2bfloat16(v1);
                int boff = (row * 136 + col) * 2;
                *(uint32_t*)(sm + AT_HIDHI + boff) = pkbf(v0, v1);
                *(uint32_t*)(sm + AT_HIDLO + boff) =
                    pkbf(v0 - __bfloat162float(b0), v1 - __bfloat162float(b1));
            }
            acc[mt][nt][0] = acc[mt][nt][1] = acc[mt][nt][2] = acc[mt][nt][3] = 0.f;
        }
    }
    __syncthreads();
    // ---- stage 2: t = hidden @ Wa2 + ba2 ----
    for (int kc = 0; kc < 2; kc++) {
        {
            int row = tid & 127, which = tid >> 7;
            const __nv_bfloat16* src =
                (which ? g_wa2t_lo : g_wa2t_hi) + (size_t)row * 128 + kc * 64;
            uint32_t dst = base + (which ? AT_B2LO : AT_B2HI) + row * 144;
#pragma unroll
            for (int j = 0; j < 8; j++) cp_async16(dst + j * 16, src + j * 8);
            CP_COMMIT();
        }
        CP_WAIT0();
        __syncthreads();
#pragma unroll
        for (int p = 0; p < 3; p++) {
            uint32_t aw = base + (p == 1 ? AT_HIDLO : AT_HIDHI) +
                          (wm * 64 * 136 + kc * 64) * 2;
            uint32_t bw = base + (p == 2 ? AT_B2LO : AT_B2HI) + (wn * 32) * 144;
            mma_chunk<136, 4>(acc, aw, bw, lane);
        }
        __syncthreads();
    }
    // masked store
#pragma unroll
    for (int mt = 0; mt < 4; mt++) {
        int rr0 = wm * 64 + mt * 16 + (lane >> 2);
#pragma unroll
        for (int nt = 0; nt < 4; nt++) {
            int col = wn * 32 + nt * 8 + 2 * (lane & 3);
            float2 bb = *(const float2*)(ba2 + col);
#pragma unroll
            for (int h = 0; h < 2; h++) {
                int row = r0 + rr0 + h * 8;
                int gi = row >> 6, q = row & 63;
                int size = (gi < 256) ? qsz[gi] : csz[gi - 256];
                bool ok = q < size;
                float v0 = ok ? acc[mt][nt][2 * h]     + bb.x : 0.f;
                float v1 = ok ? acc[mt][nt][2 * h + 1] + bb.y : 0.f;
                *(float2*)(g_t + (size_t)row * 128 + col) = make_float2(v0, v1);
            }
        }
    }
}

// ---------------------------------------------------------------------------
// K9: per-pair logits, dual softmax, hinge alignment, min
// ---------------------------------------------------------------------------
#define PAIR_SMEM ((2 * 64 * 129 + 3 * 64 * 65) * 4)
__global__ void __launch_bounds__(256, 1)
k_pair(const int* __restrict__ qsz, const int* __restrict__ csz,
       float* __restrict__ out) {
    extern __shared__ float smf[];
    float* bufA = smf;
    float* bufB = bufA + 64 * 129;
    float* L    = bufB + 64 * 129;
    float* pq   = L + 64 * 65;
    float* pc   = pq + 64 * 65;
    __shared__ float redq[8], redc[8];

    const int b = blockIdx.x, tid = threadIdx.x;
    const int qs = qsz[b], cs = csz[b];
    const int qbase = b * 64, cbase = 16384 + b * 64;

    for (int idx = tid; idx < 64 * 128; idx += 256) {
        int r = idx >> 7, k = idx & 127;
        bufA[r * 129 + k] = g_t[(qbase + r) * 128 + k];
        bufB[r * 129 + k] = g_t[(cbase + r) * 128 + k];
    }
    __syncthreads();
    {
        int q = tid >> 2, cg = tid & 3;
        float acc[16];
#pragma unroll
        for (int j = 0; j < 16; j++) acc[j] = 0.f;
        for (int k = 0; k < 128; k++) {
            float a = bufA[q * 129 + k];
            const float* bp = bufB + (cg * 16) * 129 + k;
#pragma unroll
            for (int j = 0; j < 16; j++) acc[j] += a * bp[j * 129];
        }
        bool qv = q < qs;
#pragma unroll
        for (int j = 0; j < 16; j++) {
            int c = cg * 16 + j;
            L[q * 65 + c] = (qv && c < cs) ? acc[j] * 10.0f : -1e9f;
        }
    }
    __syncthreads();
    for (int idx = tid; idx < 64 * 128; idx += 256) {
        int r = idx >> 7, k = idx & 127;
        bufA[r * 129 + k] = g_flat[(qbase + r) * 128 + k];
        bufB[r * 129 + k] = g_flat[(cbase + r) * 128 + k];
    }
    if (tid < 64) {
        float m = -1e30f;
        for (int c = 0; c < 64; c++) m = fmaxf(m, L[tid * 65 + c]);
        float s = 0.f;
        for (int c = 0; c < 64; c++) {
            float ex = __expf(L[tid * 65 + c] - m);
            s += ex;
            pq[tid * 65 + c] = ex;
        }
        float inv = (tid < qs) ? (1.0f / s) : 0.f;
        for (int c = 0; c < 64; c++) pq[tid * 65 + c] *= inv;
    } else if (tid < 128) {
        int c = tid - 64;
        float m = -1e30f;
        for (int q = 0; q < 64; q++) m = fmaxf(m, L[q * 65 + c]);
        float s = 0.f;
        for (int q = 0; q < 64; q++) {
            float ex = __expf(L[q * 65 + c] - m);
            s += ex;
            pc[q * 65 + c] = ex;
        }
        float inv = (c < cs) ? (1.0f / s) : 0.f;
        for (int q = 0; q < 64; q++) pc[q * 65 + c] *= inv;
    }
    __syncthreads();
    float lq = 0.f, lc = 0.f;
    {
        const int d = tid & 127, gg = tid >> 7;
        float acc[32];
#pragma unroll
        for (int j = 0; j < 32; j++) acc[j] = 0.f;
        for (int c = 0; c < 64; c++) {
            float bb = bufB[c * 129 + d];
            const float* pp = pq + (gg * 32) * 65 + c;
#pragma unroll
            for (int j = 0; j < 32; j++) acc[j] += pp[j * 65] * bb;
        }
#pragma unroll
        for (int j = 0; j < 32; j++) {
            int q = gg * 32 + j;
            lq += fmaxf(bufA[q * 129 + d] - acc[j], 0.f);
        }
#pragma unroll
        for (int j = 0; j < 32; j++) acc[j] = 0.f;
        for (int q = 0; q < 64; q++) {
            float aa = bufA[q * 129 + d];
            const float* pp = pc + q * 65 + gg * 32;
#pragma unroll
            for (int j = 0; j < 32; j++) acc[j] += pp[j] * aa;
        }
#pragma unroll
        for (int j = 0; j < 32; j++) {
            int c = gg * 32 + j;
            lc += fmaxf(bufB[c * 129 + d] - acc[j], 0.f);
        }
    }
    for (int o = 16; o; o >>= 1) {
        lq += __shfl_down_sync(0xffffffffu, lq, o);
        lc += __shfl_down_sync(0xffffffffu, lc, o);
    }
    int w = tid >> 5, lane = tid & 31;
    if (lane == 0) { redq[w] = lq; redc[w] = lc; }
    __syncthreads();
    if (tid == 0) {
        float sq = 0.f, sc = 0.f;
        for (int i = 0; i < 8; i++) { sq += redq[i]; sc += redc[i]; }
        out[b] = fminf(-sq, -sc);
    }
}

// ---------------------------------------------------------------------------
extern "C" void kernel_launch(void* const* d_in, const int* in_sizes, int n_in,
                              void* d_out, int out_size) {
    const float* nf       = (const float*)d_in[0];
    const float* ef       = (const float*)d_in[1];
    const int*   from_idx = (const int*)d_in[2];
    const int*   to_idx   = (const int*)d_in[3];
    const int*   pos      = (const int*)d_in[4];
    const int*   qsz      = (const int*)d_in[5];
    const int*   csz      = (const int*)d_in[6];
    const float* W_node = (const float*)d_in[7];
    const float* b_node = (const float*)d_in[8];
    const float* W_edge = (const float*)d_in[9];
    const float* b_edge = (const float*)d_in[10];
    const float* W_msg1 = (const float*)d_in[11];
    const float* b_msg1 = (const float*)d_in[12];
    const float* W_msg2 = (const float*)d_in[13];
    const float* b_msg2 = (const float*)d_in[14];
    const float* W_upd  = (const float*)d_in[15];
    const float* b_upd  = (const float*)d_in[16];
    const float* Wa1    = (const float*)d_in[17];
    const float* ba1    = (const float*)d_in[18];
    const float* Wa2    = (const float*)d_in[19];
    const float* ba2    = (const float*)d_in[20];

    const int N = in_sizes[0] / 32;
    const int E = in_sizes[1] / 16;

    cudaFuncSetAttribute(k_pe2,      cudaFuncAttributeMaxDynamicSharedMemorySize, SL_END);
    cudaFuncSetAttribute(k_nodeprod, cudaFuncAttributeMaxDynamicSharedMemorySize, SL_END);
    cudaFuncSetAttribute(k_msg2,     cudaFuncAttributeMaxDynamicSharedMemorySize, MS_SMEM);
    cudaFuncSetAttribute(k_upd2,     cudaFuncAttributeMaxDynamicSharedMemorySize, SL_END);
    cudaFuncSetAttribute(k_att2,     cudaFuncAttributeMaxDynamicSharedMemorySize, AT_SMEM);
    cudaFuncSetAttribute(k_pair,     cudaFuncAttributeMaxDynamicSharedMemorySize, PAIR_SMEM);

    void* aggp = nullptr;
    cudaGetSymbolAddress(&aggp, g_agg);

    const int egrid = (E + 127) / 128;
    const int ngrid = (N + 127) / 128;

    k_prep<<<896, 256>>>(W_msg1, W_msg2, W_upd, Wa1, Wa2);
    k_enc_node<<<(N * 128 + 255) / 256, 256>>>(nf, W_node, b_node, N);
    k_enc_edge<<<(E * 64 + 255) / 256, 256>>>(ef, W_edge, b_edge, E);
    k_pe2<<<egrid * 2, 256, SL_END>>>(b_msg1, E);

    for (int s = 0; s < 3; s++) {
        cudaMemsetAsync(aggp, 0, (size_t)N * 256 * sizeof(float));
        k_nodeprod<<<ngrid * 4, 256, SL_END>>>(N);
        k_msg2<<<egrid * 2, 256, MS_SMEM>>>(b_msg2, from_idx, to_idx, E);
        k_upd2<<<ngrid, 256, SL_END>>>(b_upd, N);
    }

    k_scatter<<<(N * 128 + 255) / 256, 256>>>(pos, N);
    k_att2<<<256, 256, AT_SMEM>>>(ba1, ba2, qsz, csz);
    k_pair<<<256, 256, PAIR_SMEM>>>(qsz, csz, (float*)d_out);
}

// round 5
// speedup vs baseline: 7.1112x; 2.1507x over previous
#include <cuda_runtime.h>
#include <cuda_bf16.h>
#include <cstdint>

// ---------------------------------------------------------------------------
// Constants: B=256 pairs, MAX=64, D=128, E_DIM=64, 3 prop steps
// ---------------------------------------------------------------------------
#define NMAX 32768
#define EMAX 262144

// Scratch
__device__ float g_h   [NMAX * 128];
__device__ float g_aggH[NMAX * 256];          // segment-summed hidden
__device__ float g_flat[2 * 256 * 64 * 128];
__device__ float g_t   [2 * 256 * 64 * 128];
__device__ float g_P   [NMAX * 512];          // per-step node products [P1|P2]
__device__ float g_pe  [(size_t)EMAX * 256];  // edge part of GEMM1 (+b1)
__device__ float g_wc  [256 * 128];           // Wc = W2 @ Wu_bot (fp32)
__device__ float g_bc  [128];                 // bc = b2 @ Wu_bot
__device__ int   g_deg [NMAX];
__device__ __align__(16) __nv_bfloat16 g_h_hi[NMAX * 128];
__device__ __align__(16) __nv_bfloat16 g_h_lo[NMAX * 128];
__device__ __align__(16) __nv_bfloat16 g_e_hi[EMAX * 64];
__device__ __align__(16) __nv_bfloat16 g_e_lo[EMAX * 64];
// Pre-split transposed weights Bt[n][k] (row-major, bf16 hi/lo)
__device__ __align__(16) __nv_bfloat16 g_w1p_hi[512 * 128], g_w1p_lo[512 * 128];
__device__ __align__(16) __nv_bfloat16 g_w1e_hi[256 * 64],  g_w1e_lo[256 * 64];
__device__ __align__(16) __nv_bfloat16 g_wut2_hi[128 * 384], g_wut2_lo[128 * 384];
__device__ __align__(16) __nv_bfloat16 g_wa1t_hi[128 * 128], g_wa1t_lo[128 * 128];
__device__ __align__(16) __nv_bfloat16 g_wa2t_hi[128 * 128], g_wa2t_lo[128 * 128];

// ---------------------------------------------------------------------------
// helpers
// ---------------------------------------------------------------------------
__device__ __forceinline__ uint32_t smem_to_u32(const void* p) {
    uint32_t a;
    asm("{ .reg .u64 t; cvta.to.shared.u64 t, %1; cvt.u32.u64 %0, t; }"
        : "=r"(a) : "l"(p));
    return a;
}
__device__ __forceinline__ void ldsm_x4(uint32_t r[4], uint32_t addr) {
    asm volatile("ldmatrix.sync.aligned.m8n8.x4.shared.b16 {%0,%1,%2,%3}, [%4];"
                 : "=r"(r[0]), "=r"(r[1]), "=r"(r[2]), "=r"(r[3]) : "r"(addr));
}
__device__ __forceinline__ void mma_bf16(float c[4], const uint32_t a[4],
                                         uint32_t b0, uint32_t b1) {
    asm volatile(
        "mma.sync.aligned.m16n8k16.row.col.f32.bf16.bf16.f32 "
        "{%0,%1,%2,%3}, {%4,%5,%6,%7}, {%8,%9}, {%0,%1,%2,%3};"
        : "+f"(c[0]), "+f"(c[1]), "+f"(c[2]), "+f"(c[3])
        : "r"(a[0]), "r"(a[1]), "r"(a[2]), "r"(a[3]), "r"(b0), "r"(b1));
}
__device__ __forceinline__ void cp_async16(uint32_t smem, const void* g) {
    asm volatile("cp.async.ca.shared.global [%0], [%1], 16;"
                 :: "r"(smem), "l"(g));
}
#define CP_COMMIT() asm volatile("cp.async.commit_group;" ::: "memory")
#define CP_WAIT0()  asm volatile("cp.async.wait_group 0;" ::: "memory")

__device__ __forceinline__ uint32_t pkbf(float a, float b) {
    __nv_bfloat162 t = __floats2bfloat162_rn(a, b);
    return *reinterpret_cast<uint32_t*>(&t);
}
__device__ __forceinline__ void red4(float* addr, float x, float y, float z,
                                     float w) {
    asm volatile("red.global.add.v4.f32 [%0], {%1, %2, %3, %4};"
                 :: "l"(addr), "f"(x), "f"(y), "f"(z), "f"(w) : "memory");
}

// One 64-k chunk of warp MMA: warp tile 64 rows x (NT*8) cols.
template <int SA, int NT>
__device__ __forceinline__ void mma_chunk(float (&acc)[4][NT][4],
                                          uint32_t aw, uint32_t bw, int lane) {
    const int arow = lane & 15, ak = (lane >> 4) << 3;
    const int brow = (lane & 7) + ((lane >> 4) << 3);
    const int bk = ((lane >> 3) & 1) << 3;
#pragma unroll
    for (int kt = 0; kt < 4; kt++) {
        uint32_t a[4][4], b[NT / 2][4];
#pragma unroll
        for (int mt = 0; mt < 4; mt++)
            ldsm_x4(a[mt], aw + ((mt * 16 + arow) * SA + kt * 16 + ak) * 2);
#pragma unroll
        for (int nb = 0; nb < NT / 2; nb++)
            ldsm_x4(b[nb], bw + ((nb * 16 + brow) * 72 + kt * 16 + bk) * 2);
#pragma unroll
        for (int mt = 0; mt < 4; mt++)
#pragma unroll
            for (int nb = 0; nb < NT / 2; nb++) {
                mma_bf16(acc[mt][2 * nb],     a[mt], b[nb][0], b[nb][1]);
                mma_bf16(acc[mt][2 * nb + 1], a[mt], b[nb][2], b[nb][3]);
            }
    }
}

// Common smem layout for the 64-k sliced kernels
#define SL_AHI 0
#define SL_ALO 18432
#define SL_BHI 36864
#define SL_BLO 55296
#define SL_END 73728

// ---------------------------------------------------------------------------
// K0: weight prep — transpose + hi/lo split (w1p, w1e, wa1, wa2)
// ---------------------------------------------------------------------------
__global__ void k_prep(const float* __restrict__ W1, const float* __restrict__ Wa1,
                       const float* __restrict__ Wa2) {
    int idx = blockIdx.x * 256 + threadIdx.x;
    float v;
    __nv_bfloat16 *dh, *dl;
    int off;
    if (idx < 65536) {                       // g_w1p [512n][128k]
        int n = idx >> 7, k = idx & 127;
        v = (n < 256) ? W1[k * 256 + n] : W1[(128 + k) * 256 + (n - 256)];
        dh = g_w1p_hi; dl = g_w1p_lo; off = idx;
    } else if (idx < 81920) {                // g_w1e [256n][64k]
        int i = idx - 65536;
        int n = i >> 6, k = i & 63;
        v = W1[(256 + k) * 256 + n];
        dh = g_w1e_hi; dl = g_w1e_lo; off = i;
    } else if (idx < 98304) {                // g_wa1t [128n][128k]
        int i = idx - 81920;
        int n = i >> 7, k = i & 127;
        v = Wa1[k * 128 + n];
        dh = g_wa1t_hi; dl = g_wa1t_lo; off = i;
    } else {                                 // g_wa2t
        int i = idx - 98304;
        if (i >= 16384) return;
        int n = i >> 7, k = i & 127;
        v = Wa2[k * 128 + n];
        dh = g_wa2t_hi; dl = g_wa2t_lo; off = i;
    }
    __nv_bfloat16 hi = __float2bfloat16(v);
    dh[off] = hi;
    dl[off] = __float2bfloat16(v - __bfloat162float(hi));
}

// Wc[k][c] = sum_j W2[k][j] * Wu[128+j][c]   (fp32, 256 blocks x 128 thr)
__global__ void k_wc(const float* __restrict__ W2, const float* __restrict__ Wu) {
    int k = blockIdx.x, c = threadIdx.x;
    __shared__ float w2row[256];
    w2row[c] = W2[k * 256 + c];
    w2row[c + 128] = W2[k * 256 + c + 128];
    __syncthreads();
    float s = 0.f;
#pragma unroll 4
    for (int j = 0; j < 256; j++) s += w2row[j] * Wu[(128 + j) * 128 + c];
    g_wc[k * 128 + c] = s;
}

// Pack combined update weight [128n][384k]: k<128 -> Wu_top, else Wc.
// Also bc[c] = sum_j b2[j] * Wu[128+j][c].
__global__ void k_pack(const float* __restrict__ Wu, const float* __restrict__ b2) {
    int idx = blockIdx.x * 256 + threadIdx.x;
    if (idx < 49152) {
        int n = idx / 384, k = idx - n * 384;
        float v = (k < 128) ? Wu[k * 128 + n] : g_wc[(k - 128) * 128 + n];
        __nv_bfloat16 hi = __float2bfloat16(v);
        g_wut2_hi[idx] = hi;
        g_wut2_lo[idx] = __float2bfloat16(v - __bfloat162float(hi));
    } else if (idx < 49280) {
        int c = idx - 49152;
        float s = 0.f;
        for (int j = 0; j < 256; j++) s += b2[j] * Wu[(128 + j) * 128 + c];
        g_bc[c] = s;
    }
}

__global__ void k_deg(const int* __restrict__ to_idx, int E) {
    int i = blockIdx.x * 256 + threadIdx.x;
    if (i < E) atomicAdd(&g_deg[to_idx[i]], 1);
}

// ---------------------------------------------------------------------------
// K1/K2: encoders
// ---------------------------------------------------------------------------
__global__ void k_enc_node(const float* __restrict__ nf,
                           const float* __restrict__ Wn,
                           const float* __restrict__ bn, int N) {
    __shared__ float Ws[32 * 128];
    for (int i = threadIdx.x; i < 32 * 128; i += 256) Ws[i] = Wn[i];
    __syncthreads();
    int idx = blockIdx.x * 256 + threadIdx.x;
    if (idx >= N * 128) return;
    int n = idx >> 7, c = idx & 127;
    const float* row = nf + n * 32;
    float s = bn[c];
#pragma unroll
    for (int k = 0; k < 32; k++) s += row[k] * Ws[k * 128 + c];
    g_h[idx] = s;
    __nv_bfloat16 hi = __float2bfloat16(s);
    g_h_hi[idx] = hi;
    g_h_lo[idx] = __float2bfloat16(s - __bfloat162float(hi));
}

__global__ void k_enc_edge(const float* __restrict__ ef,
                           const float* __restrict__ We,
                           const float* __restrict__ be, int E) {
    __shared__ float Ws[16 * 64];
    for (int i = threadIdx.x; i < 16 * 64; i += 256) Ws[i] = We[i];
    __syncthreads();
    int idx = blockIdx.x * 256 + threadIdx.x;
    if (idx >= E * 64) return;
    int ed = idx >> 6, c = idx & 63;
    const float* row = ef + ed * 16;
    float s = be[c];
#pragma unroll
    for (int k = 0; k < 16; k++) s += row[k] * Ws[k * 64 + c];
    __nv_bfloat16 hi = __float2bfloat16(s);
    g_e_hi[idx] = hi;
    g_e_lo[idx] = __float2bfloat16(s - __bfloat162float(hi));
}

// ---------------------------------------------------------------------------
// K3: Pe = e @ W1_bot + b1  (once).  Tile: 128 edges x 128 cols, K=64.
// ---------------------------------------------------------------------------
__global__ void __launch_bounds__(256, 2)
k_pe2(const float* __restrict__ b1, int E) {
    extern __shared__ unsigned char sm[];
    const uint32_t base = smem_to_u32(sm);
    const int tid = threadIdx.x, lane = tid & 31, wid = tid >> 5;
    const int cb = blockIdx.x & 1, eb = blockIdx.x >> 1;
    const int e0 = eb * 128;
    {
        int row = tid & 127, which = tid >> 7;
        const __nv_bfloat16* src =
            (which ? g_w1e_lo : g_w1e_hi) + (size_t)(cb * 128 + row) * 64;
        uint32_t dst = base + (which ? SL_BLO : SL_BHI) + row * 144;
#pragma unroll
        for (int j = 0; j < 8; j++) cp_async16(dst + j * 16, src + j * 8);
        CP_COMMIT();
    }
    {
        int row = tid & 127, which = tid >> 7;
        const __nv_bfloat16* src =
            (which ? g_e_lo : g_e_hi) + (size_t)(e0 + row) * 64;
        unsigned char* dst = sm + (which ? SL_ALO : SL_AHI) + row * 144;
#pragma unroll
        for (int j = 0; j < 8; j++)
            *(uint4*)(dst + j * 16) = *(const uint4*)(src + j * 8);
    }
    CP_WAIT0();
    __syncthreads();
    const int wm = wid >> 2, wn = wid & 3;
    float acc[4][4][4];
#pragma unroll
    for (int i = 0; i < 4; i++)
#pragma unroll
        for (int j = 0; j < 4; j++)
#pragma unroll
            for (int k = 0; k < 4; k++) acc[i][j][k] = 0.f;
#pragma unroll
    for (int p = 0; p < 3; p++) {
        uint32_t aw = base + (p == 1 ? SL_ALO : SL_AHI) + (wm * 64 * 72) * 2;
        uint32_t bw = base + (p == 2 ? SL_BLO : SL_BHI) + (wn * 32) * 144;
        mma_chunk<72, 4>(acc, aw, bw, lane);
    }
#pragma unroll
    for (int mt = 0; mt < 4; mt++) {
        int r0 = wm * 64 + mt * 16 + (lane >> 2);
#pragma unroll
        for (int nt = 0; nt < 4; nt++) {
            int col = cb * 128 + wn * 32 + nt * 8 + 2 * (lane & 3);
            float2 bb = *(const float2*)(b1 + col);
            *(float2*)(g_pe + (size_t)(e0 + r0) * 256 + col) =
                make_float2(acc[mt][nt][0] + bb.x, acc[mt][nt][1] + bb.y);
            *(float2*)(g_pe + (size_t)(e0 + r0 + 8) * 256 + col) =
                make_float2(acc[mt][nt][2] + bb.x, acc[mt][nt][3] + bb.y);
        }
    }
}

// ---------------------------------------------------------------------------
// K4: P12 = h @ [W1_top|W1_mid].  Tile: 128 nodes x 128 cols, K=128 (2 slices)
// ---------------------------------------------------------------------------
__global__ void __launch_bounds__(256, 2)
k_nodeprod(int N) {
    extern __shared__ unsigned char sm[];
    const uint32_t base = smem_to_u32(sm);
    const int tid = threadIdx.x, lane = tid & 31, wid = tid >> 5;
    const int cb = blockIdx.x & 3, rb = blockIdx.x >> 2;
    const int n0 = rb * 128;
    const int wm = wid >> 2, wn = wid & 3;
    float acc[4][4][4];
#pragma unroll
    for (int i = 0; i < 4; i++)
#pragma unroll
        for (int j = 0; j < 4; j++)
#pragma unroll
            for (int k = 0; k < 4; k++) acc[i][j][k] = 0.f;

    for (int kc = 0; kc < 2; kc++) {
        {
            int row = tid & 127, which = tid >> 7;
            const __nv_bfloat16* src =
                (which ? g_w1p_lo : g_w1p_hi) +
                (size_t)(cb * 128 + row) * 128 + kc * 64;
            uint32_t dst = base + (which ? SL_BLO : SL_BHI) + row * 144;
#pragma unroll
            for (int j = 0; j < 8; j++) cp_async16(dst + j * 16, src + j * 8);
            CP_COMMIT();
        }
        {
            int row = tid & 127, which = tid >> 7;
            const __nv_bfloat16* src =
                (which ? g_h_lo : g_h_hi) + (size_t)(n0 + row) * 128 + kc * 64;
            unsigned char* dst = sm + (which ? SL_ALO : SL_AHI) + row * 144;
#pragma unroll
            for (int j = 0; j < 8; j++)
                *(uint4*)(dst + j * 16) = *(const uint4*)(src + j * 8);
        }
        CP_WAIT0();
        __syncthreads();
#pragma unroll
        for (int p = 0; p < 3; p++) {
            uint32_t aw = base + (p == 1 ? SL_ALO : SL_AHI) + (wm * 64 * 72) * 2;
            uint32_t bw = base + (p == 2 ? SL_BLO : SL_BHI) + (wn * 32) * 144;
            mma_chunk<72, 4>(acc, aw, bw, lane);
        }
        __syncthreads();
    }
#pragma unroll
    for (int mt = 0; mt < 4; mt++) {
        int r0 = wm * 64 + mt * 16 + (lane >> 2);
        int n1 = n0 + r0, n2 = n1 + 8;
#pragma unroll
        for (int nt = 0; nt < 4; nt++) {
            int col = cb * 128 + wn * 32 + nt * 8 + 2 * (lane & 3);
            if (n1 < N)
                *(float2*)(g_P + (size_t)n1 * 512 + col) =
                    make_float2(acc[mt][nt][0], acc[mt][nt][1]);
            if (n2 < N)
                *(float2*)(g_P + (size_t)n2 * 512 + col) =
                    make_float2(acc[mt][nt][2], acc[mt][nt][3]);
        }
    }
}

// ---------------------------------------------------------------------------
// K5: hidden = relu(P1[from]+P2[to]+Pe); aggH[to] += hidden  (v4 reduction)
// ---------------------------------------------------------------------------
__global__ void k_hidden(const int* __restrict__ from_idx,
                         const int* __restrict__ to_idx, int E) {
    int idx = blockIdx.x * 256 + threadIdx.x;
    int ed = idx >> 6, cg = (idx & 63) * 4;
    if (ed >= E) return;
    int f = __ldg(&from_idx[ed]), t = __ldg(&to_idx[ed]);
    const float4 v1 = *(const float4*)(g_P + (size_t)f * 512 + cg);
    const float4 v2 = *(const float4*)(g_P + (size_t)t * 512 + 256 + cg);
    const float4 ve = *(const float4*)(g_pe + (size_t)ed * 256 + cg);
    float s0 = fmaxf(v1.x + v2.x + ve.x, 0.f);
    float s1 = fmaxf(v1.y + v2.y + ve.y, 0.f);
    float s2 = fmaxf(v1.z + v2.z + ve.z, 0.f);
    float s3 = fmaxf(v1.w + v2.w + ve.w, 0.f);
    red4(g_aggH + (size_t)t * 256 + cg, s0, s1, s2, s3);
}

// ---------------------------------------------------------------------------
// K6: node update  h += [h|aggH] @ Wut2 + bu + deg*bc.
// ---------------------------------------------------------------------------
__global__ void __launch_bounds__(256, 2)
k_upd2(const float* __restrict__ bu, int N) {
    extern __shared__ unsigned char sm[];
    const uint32_t base = smem_to_u32(sm);
    const int tid = threadIdx.x, lane = tid & 31, wid = tid >> 5;
    const int n0 = blockIdx.x * 128;
    const int wm = wid >> 2, wn = wid & 3;
    float acc[4][4][4];
#pragma unroll
    for (int i = 0; i < 4; i++)
#pragma unroll
        for (int j = 0; j < 4; j++)
#pragma unroll
            for (int k = 0; k < 4; k++) acc[i][j][k] = 0.f;

    for (int kc = 0; kc < 6; kc++) {
        {
            int row = tid & 127, which = tid >> 7;
            const __nv_bfloat16* src =
                (which ? g_wut2_lo : g_wut2_hi) + (size_t)row * 384 + kc * 64;
            uint32_t dst = base + (which ? SL_BLO : SL_BHI) + row * 144;
#pragma unroll
            for (int j = 0; j < 8; j++) cp_async16(dst + j * 16, src + j * 8);
            CP_COMMIT();
        }
#pragma unroll 2
        for (int i = 0; i < 8; i++) {
            int idx = tid + 256 * i;
            int row = idx >> 4, q = idx & 15;
            float4 v;
            if (kc < 2)
                v = *(const float4*)(g_h + (size_t)(n0 + row) * 128 +
                                     kc * 64 + q * 4);
            else
                v = *(const float4*)(g_aggH + (size_t)(n0 + row) * 256 +
                                     (kc - 2) * 64 + q * 4);
            __nv_bfloat16 h0 = __float2bfloat16(v.x), h1 = __float2bfloat16(v.y);
            __nv_bfloat16 h2 = __float2bfloat16(v.z), h3 = __float2bfloat16(v.w);
            uint2 hp, lp;
            hp.x = pkbf(v.x, v.y); hp.y = pkbf(v.z, v.w);
            lp.x = pkbf(v.x - __bfloat162float(h0), v.y - __bfloat162float(h1));
            lp.y = pkbf(v.z - __bfloat162float(h2), v.w - __bfloat162float(h3));
            int boff = (row * 72 + q * 4) * 2;
            *(uint2*)(sm + SL_AHI + boff) = hp;
            *(uint2*)(sm + SL_ALO + boff) = lp;
        }
        CP_WAIT0();
        __syncthreads();
#pragma unroll
        for (int p = 0; p < 3; p++) {
            uint32_t aw = base + (p == 1 ? SL_ALO : SL_AHI) + (wm * 64 * 72) * 2;
            uint32_t bw = base + (p == 2 ? SL_BLO : SL_BHI) + (wn * 32) * 144;
            mma_chunk<72, 4>(acc, aw, bw, lane);
        }
        __syncthreads();
    }
#pragma unroll
    for (int mt = 0; mt < 4; mt++) {
        int rr[2];
        rr[0] = wm * 64 + mt * 16 + (lane >> 2);
        rr[1] = rr[0] + 8;
#pragma unroll
        for (int nt = 0; nt < 4; nt++) {
            int col = wn * 32 + nt * 8 + 2 * (lane & 3);
            float2 bb = *(const float2*)(bu + col);
            float2 bc2 = *(const float2*)(g_bc + col);
#pragma unroll
            for (int h = 0; h < 2; h++) {
                int n = n0 + rr[h];
                if (n < N) {
                    float degf = (float)g_deg[n];
#pragma unroll
                    for (int z = 0; z < 2; z++) {
                        float v = g_h[(size_t)n * 128 + col + z] +
                                  acc[mt][nt][2 * h + z] + (z ? bb.y : bb.x) +
                                  degf * (z ? bc2.y : bc2.x);
                        g_h[(size_t)n * 128 + col + z] = v;
                        __nv_bfloat16 hi = __float2bfloat16(v);
                        g_h_hi[(size_t)n * 128 + col + z] = hi;
                        g_h_lo[(size_t)n * 128 + col + z] =
                            __float2bfloat16(v - __bfloat162float(hi));
                    }
                }
            }
        }
    }
}

// ---------------------------------------------------------------------------
// K7: scatter into padded stacks (padded rows stay zero)
// ---------------------------------------------------------------------------
__global__ void k_scatter(const int* __restrict__ pos, int N) {
    int idx = blockIdx.x * 256 + threadIdx.x;
    if (idx >= N * 128) return;
    int n = idx >> 7, c = idx & 127;
    g_flat[pos[n] * 128 + c] = g_h[idx];
}

// ---------------------------------------------------------------------------
// K8: attention features via MMA
// ---------------------------------------------------------------------------
#define AT_HIDHI 0
#define AT_HIDLO 34816
#define AT_B2HI  73728
#define AT_B2LO  92160
#define AT_SMEM  110592
__global__ void __launch_bounds__(256, 2)
k_att2(const float* __restrict__ ba1, const float* __restrict__ ba2,
       const int* __restrict__ qsz, const int* __restrict__ csz) {
    extern __shared__ unsigned char sm[];
    const uint32_t base = smem_to_u32(sm);
    const int tid = threadIdx.x, lane = tid & 31, wid = tid >> 5;
    const int r0 = blockIdx.x * 128;
    const int wm = wid >> 2, wn = wid & 3;
    float acc[4][4][4];
#pragma unroll
    for (int i = 0; i < 4; i++)
#pragma unroll
        for (int j = 0; j < 4; j++)
#pragma unroll
            for (int k = 0; k < 4; k++) acc[i][j][k] = 0.f;

    for (int kc = 0; kc < 2; kc++) {
        {
            int row = tid & 127, which = tid >> 7;
            const __nv_bfloat16* src =
                (which ? g_wa1t_lo : g_wa1t_hi) + (size_t)row * 128 + kc * 64;
            uint32_t dst = base + (which ? AT_B2LO : AT_B2HI) + row * 144;
#pragma unroll
            for (int j = 0; j < 8; j++) cp_async16(dst + j * 16, src + j * 8);
            CP_COMMIT();
        }
#pragma unroll 2
        for (int i = 0; i < 8; i++) {
            int idx = tid + 256 * i;
            int row = idx >> 4, q = idx & 15;
            float4 v = *(const float4*)(g_flat + (size_t)(r0 + row) * 128 +
                                        kc * 64 + q * 4);
            __nv_bfloat16 h0 = __float2bfloat16(v.x), h1 = __float2bfloat16(v.y);
            __nv_bfloat16 h2 = __float2bfloat16(v.z), h3 = __float2bfloat16(v.w);
            uint2 hp, lp;
            hp.x = pkbf(v.x, v.y); hp.y = pkbf(v.z, v.w);
            lp.x = pkbf(v.x - __bfloat162float(h0), v.y - __bfloat162float(h1));
            lp.y = pkbf(v.z - __bfloat162float(h2), v.w - __bfloat162float(h3));
            int boff = (row * 72 + q * 4) * 2;
            *(uint2*)(sm + SL_AHI + boff) = hp;
            *(uint2*)(sm + SL_ALO + boff) = lp;
        }
        CP_WAIT0();
        __syncthreads();
#pragma unroll
        for (int p = 0; p < 3; p++) {
            uint32_t aw = base + (p == 1 ? SL_ALO : SL_AHI) + (wm * 64 * 72) * 2;
            uint32_t bw = base + (p == 2 ? AT_B2LO : AT_B2HI) + (wn * 32) * 144;
            mma_chunk<72, 4>(acc, aw, bw, lane);
        }
        __syncthreads();
    }
#pragma unroll
    for (int mt = 0; mt < 4; mt++) {
        int rr0 = wm * 64 + mt * 16 + (lane >> 2);
#pragma unroll
        for (int nt = 0; nt < 4; nt++) {
            int col = wn * 32 + nt * 8 + 2 * (lane & 3);
            float2 bb = *(const float2*)(ba1 + col);
#pragma unroll
            for (int h = 0; h < 2; h++) {
                int row = rr0 + h * 8;
                float v0 = fmaxf(acc[mt][nt][2 * h]     + bb.x, 0.f);
                float v1 = fmaxf(acc[mt][nt][2 * h + 1] + bb.y, 0.f);
                __nv_bfloat16 b0 = __float2bfloat16(v0), b1 = __float2bfloat16(v1);
                int boff = (row * 136 + col) * 2;
                *(uint32_t*)(sm + AT_HIDHI + boff) = pkbf(v0, v1);
                *(uint32_t*)(sm + AT_HIDLO + boff) =
                    pkbf(v0 - __bfloat162float(b0), v1 - __bfloat162float(b1));
            }
            acc[mt][nt][0] = acc[mt][nt][1] = acc[mt][nt][2] = acc[mt][nt][3] = 0.f;
        }
    }
    __syncthreads();
    for (int kc = 0; kc < 2; kc++) {
        {
            int row = tid & 127, which = tid >> 7;
            const __nv_bfloat16* src =
                (which ? g_wa2t_lo : g_wa2t_hi) + (size_t)row * 128 + kc * 64;
            uint32_t dst = base + (which ? AT_B2LO : AT_B2HI) + row * 144;
#pragma unroll
            for (int j = 0; j < 8; j++) cp_async16(dst + j * 16, src + j * 8);
            CP_COMMIT();
        }
        CP_WAIT0();
        __syncthreads();
#pragma unroll
        for (int p = 0; p < 3; p++) {
            uint32_t aw = base + (p == 1 ? AT_HIDLO : AT_HIDHI) +
                          (wm * 64 * 136 + kc * 64) * 2;
            uint32_t bw = base + (p == 2 ? AT_B2LO : AT_B2HI) + (wn * 32) * 144;
            mma_chunk<136, 4>(acc, aw, bw, lane);
        }
        __syncthreads();
    }
#pragma unroll
    for (int mt = 0; mt < 4; mt++) {
        int rr0 = wm * 64 + mt * 16 + (lane >> 2);
#pragma unroll
        for (int nt = 0; nt < 4; nt++) {
            int col = wn * 32 + nt * 8 + 2 * (lane & 3);
            float2 bb = *(const float2*)(ba2 + col);
#pragma unroll
            for (int h = 0; h < 2; h++) {
                int row = r0 + rr0 + h * 8;
                int gi = row >> 6, q = row & 63;
                int size = (gi < 256) ? qsz[gi] : csz[gi - 256];
                bool ok = q < size;
                float v0 = ok ? acc[mt][nt][2 * h]     + bb.x : 0.f;
                float v1 = ok ? acc[mt][nt][2 * h + 1] + bb.y : 0.f;
                *(float2*)(g_t + (size_t)row * 128 + col) = make_float2(v0, v1);
            }
        }
    }
}

// ---------------------------------------------------------------------------
// K9: per-pair logits, dual softmax, hinge alignment, min
// ---------------------------------------------------------------------------
#define PAIR_SMEM ((2 * 64 * 129 + 3 * 64 * 65) * 4)
__global__ void __launch_bounds__(256, 1)
k_pair(const int* __restrict__ qsz, const int* __restrict__ csz,
       float* __restrict__ out) {
    extern __shared__ float smf[];
    float* bufA = smf;
    float* bufB = bufA + 64 * 129;
    float* L    = bufB + 64 * 129;
    float* pq   = L + 64 * 65;
    float* pc   = pq + 64 * 65;
    __shared__ float redq[8], redc[8];

    const int b = blockIdx.x, tid = threadIdx.x;
    const int qs = qsz[b], cs = csz[b];
    const int qbase = b * 64, cbase = 16384 + b * 64;

    for (int idx = tid; idx < 64 * 128; idx += 256) {
        int r = idx >> 7, k = idx & 127;
        bufA[r * 129 + k] = g_t[(qbase + r) * 128 + k];
        bufB[r * 129 + k] = g_t[(cbase + r) * 128 + k];
    }
    __syncthreads();
    {
        int q = tid >> 2, cg = tid & 3;
        float acc[16];
#pragma unroll
        for (int j = 0; j < 16; j++) acc[j] = 0.f;
        for (int k = 0; k < 128; k++) {
            float a = bufA[q * 129 + k];
            const float* bp = bufB + (cg * 16) * 129 + k;
#pragma unroll
            for (int j = 0; j < 16; j++) acc[j] += a * bp[j * 129];
        }
        bool qv = q < qs;
#pragma unroll
        for (int j = 0; j < 16; j++) {
            int c = cg * 16 + j;
            L[q * 65 + c] = (qv && c < cs) ? acc[j] * 10.0f : -1e9f;
        }
    }
    __syncthreads();
    for (int idx = tid; idx < 64 * 128; idx += 256) {
        int r = idx >> 7, k = idx & 127;
        bufA[r * 129 + k] = g_flat[(qbase + r) * 128 + k];
        bufB[r * 129 + k] = g_flat[(cbase + r) * 128 + k];
    }
    if (tid < 64) {
        float m = -1e30f;
        for (int c = 0; c < 64; c++) m = fmaxf(m, L[tid * 65 + c]);
        float s = 0.f;
        for (int c = 0; c < 64; c++) {
            float ex = __expf(L[tid * 65 + c] - m);
            s += ex;
            pq[tid * 65 + c] = ex;
        }
        float inv = (tid < qs) ? (1.0f / s) : 0.f;
        for (int c = 0; c < 64; c++) pq[tid * 65 + c] *= inv;
    } else if (tid < 128) {
        int c = tid - 64;
        float m = -1e30f;
        for (int q = 0; q < 64; q++) m = fmaxf(m, L[q * 65 + c]);
        float s = 0.f;
        for (int q = 0; q < 64; q++) {
            float ex = __expf(L[q * 65 + c] - m);
            s += ex;
            pc[q * 65 + c] = ex;
        }
        float inv = (c < cs) ? (1.0f / s) : 0.f;
        for (int q = 0; q < 64; q++) pc[q * 65 + c] *= inv;
    }
    __syncthreads();
    float lq = 0.f, lc = 0.f;
    {
        const int d = tid & 127, gg = tid >> 7;
        float acc[32];
#pragma unroll
        for (int j = 0; j < 32; j++) acc[j] = 0.f;
        for (int c = 0; c < 64; c++) {
            float bb = bufB[c * 129 + d];
            const float* pp = pq + (gg * 32) * 65 + c;
#pragma unroll
            for (int j = 0; j < 32; j++) acc[j] += pp[j * 65] * bb;
        }
#pragma unroll
        for (int j = 0; j < 32; j++) {
            int q = gg * 32 + j;
            lq += fmaxf(bufA[q * 129 + d] - acc[j], 0.f);
        }
#pragma unroll
        for (int j = 0; j < 32; j++) acc[j] = 0.f;
        for (int q = 0; q < 64; q++) {
            float aa = bufA[q * 129 + d];
            const float* pp = pc + q * 65 + gg * 32;
#pragma unroll
            for (int j = 0; j < 32; j++) acc[j] += pp[j] * aa;
        }
#pragma unroll
        for (int j = 0; j < 32; j++) {
            int c = gg * 32 + j;
            lc += fmaxf(bufB[c * 129 + d] - acc[j], 0.f);
        }
    }
    for (int o = 16; o; o >>= 1) {
        lq += __shfl_down_sync(0xffffffffu, lq, o);
        lc += __shfl_down_sync(0xffffffffu, lc, o);
    }
    int w = tid >> 5, lane = tid & 31;
    if (lane == 0) { redq[w] = lq; redc[w] = lc; }
    __syncthreads();
    if (tid == 0) {
        float sq = 0.f, sc = 0.f;
        for (int i = 0; i < 8; i++) { sq += redq[i]; sc += redc[i]; }
        out[b] = fminf(-sq, -sc);
    }
}

// ---------------------------------------------------------------------------
extern "C" void kernel_launch(void* const* d_in, const int* in_sizes, int n_in,
                              void* d_out, int out_size) {
    const float* nf       = (const float*)d_in[0];
    const float* ef       = (const float*)d_in[1];
    const int*   from_idx = (const int*)d_in[2];
    const int*   to_idx   = (const int*)d_in[3];
    const int*   pos      = (const int*)d_in[4];
    const int*   qsz      = (const int*)d_in[5];
    const int*   csz      = (const int*)d_in[6];
    const float* W_node = (const float*)d_in[7];
    const float* b_node = (const float*)d_in[8];
    const float* W_edge = (const float*)d_in[9];
    const float* b_edge = (const float*)d_in[10];
    const float* W_msg1 = (const float*)d_in[11];
    const float* b_msg1 = (const float*)d_in[12];
    const float* W_msg2 = (const float*)d_in[13];
    const float* b_msg2 = (const float*)d_in[14];
    const float* W_upd  = (const float*)d_in[15];
    const float* b_upd  = (const float*)d_in[16];
    const float* Wa1    = (const float*)d_in[17];
    const float* ba1    = (const float*)d_in[18];
    const float* Wa2    = (const float*)d_in[19];
    const float* ba2    = (const float*)d_in[20];

    const int N = in_sizes[0] / 32;
    const int E = in_sizes[1] / 16;

    cudaFuncSetAttribute(k_pe2,      cudaFuncAttributeMaxDynamicSharedMemorySize, SL_END);
    cudaFuncSetAttribute(k_nodeprod, cudaFuncAttributeMaxDynamicSharedMemorySize, SL_END);
    cudaFuncSetAttribute(k_upd2,     cudaFuncAttributeMaxDynamicSharedMemorySize, SL_END);
    cudaFuncSetAttribute(k_att2,     cudaFuncAttributeMaxDynamicSharedMemorySize, AT_SMEM);
    cudaFuncSetAttribute(k_pair,     cudaFuncAttributeMaxDynamicSharedMemorySize, PAIR_SMEM);

    void* aggp = nullptr;
    void* degp = nullptr;
    cudaGetSymbolAddress(&aggp, g_aggH);
    cudaGetSymbolAddress(&degp, g_deg);

    const int egrid = (E + 127) / 128;
    const int ngrid = (N + 127) / 128;

    k_prep<<<448, 256>>>(W_msg1, Wa1, Wa2);
    k_wc<<<256, 128>>>(W_msg2, W_upd);
    k_pack<<<193, 256>>>(W_upd, b_msg2);
    cudaMemsetAsync(degp, 0, (size_t)N * sizeof(int));
    k_deg<<<(E + 255) / 256, 256>>>(to_idx, E);
    k_enc_node<<<(N * 128 + 255) / 256, 256>>>(nf, W_node, b_node, N);
    k_enc_edge<<<(E * 64 + 255) / 256, 256>>>(ef, W_edge, b_edge, E);
    k_pe2<<<egrid * 2, 256, SL_END>>>(b_msg1, E);

    for (int s = 0; s < 3; s++) {
        cudaMemsetAsync(aggp, 0, (size_t)N * 256 * sizeof(float));
        k_nodeprod<<<ngrid * 4, 256, SL_END>>>(N);
        k_hidden<<<(E * 64 + 255) / 256, 256>>>(from_idx, to_idx, E);
        k_upd2<<<ngrid, 256, SL_END>>>(b_upd, N);
    }

    k_scatter<<<(N * 128 + 255) / 256, 256>>>(pos, N);
    k_att2<<<256, 256, AT_SMEM>>>(ba1, ba2, qsz, csz);
    k_pair<<<256, 256, PAIR_SMEM>>>(qsz, csz, (float*)d_out);
}

// round 6
// speedup vs baseline: 8.4747x; 1.1917x over previous
#include <cuda_runtime.h>
#include <cuda_bf16.h>
#include <cstdint>

// ---------------------------------------------------------------------------
// Constants: B=256 pairs, MAX=64, D=128, E_DIM=64, 3 prop steps
// ---------------------------------------------------------------------------
#define NMAX 32768
#define EMAX 262144

// Scratch
__device__ float g_h   [NMAX * 128];
__device__ float g_aggH[NMAX * 256];          // segment-summed hidden
__device__ float g_flat[2 * 256 * 64 * 128];
__device__ float g_t   [2 * 256 * 64 * 128];
__device__ float g_P   [NMAX * 512];          // per-step node products [P1|P2+bpe]
__device__ float g_wc  [256 * 128];           // Wc = W2 @ Wu_bot (fp32)
__device__ float g_bc  [128];                 // bc = b2 @ Wu_bot
__device__ float g_wpe [16 * 256];            // Wpe = W_edge @ W1_bot
__device__ float g_bpe [256];                 // bpe = b_edge @ W1_bot + b1
__device__ int   g_deg [NMAX];
__device__ __align__(16) __nv_bfloat16 g_h_hi[NMAX * 128];
__device__ __align__(16) __nv_bfloat16 g_h_lo[NMAX * 128];
// Pre-split transposed weights Bt[n][k] (row-major, bf16 hi/lo)
__device__ __align__(16) __nv_bfloat16 g_w1p_hi[512 * 128], g_w1p_lo[512 * 128];
__device__ __align__(16) __nv_bfloat16 g_wut2_hi[128 * 384], g_wut2_lo[128 * 384];
__device__ __align__(16) __nv_bfloat16 g_wa1t_hi[128 * 128], g_wa1t_lo[128 * 128];
__device__ __align__(16) __nv_bfloat16 g_wa2t_hi[128 * 128], g_wa2t_lo[128 * 128];

// ---------------------------------------------------------------------------
// helpers
// ---------------------------------------------------------------------------
__device__ __forceinline__ uint32_t smem_to_u32(const void* p) {
    uint32_t a;
    asm("{ .reg .u64 t; cvta.to.shared.u64 t, %1; cvt.u32.u64 %0, t; }"
        : "=r"(a) : "l"(p));
    return a;
}
__device__ __forceinline__ void ldsm_x4(uint32_t r[4], uint32_t addr) {
    asm volatile("ldmatrix.sync.aligned.m8n8.x4.shared.b16 {%0,%1,%2,%3}, [%4];"
                 : "=r"(r[0]), "=r"(r[1]), "=r"(r[2]), "=r"(r[3]) : "r"(addr));
}
__device__ __forceinline__ void mma_bf16(float c[4], const uint32_t a[4],
                                         uint32_t b0, uint32_t b1) {
    asm volatile(
        "mma.sync.aligned.m16n8k16.row.col.f32.bf16.bf16.f32 "
        "{%0,%1,%2,%3}, {%4,%5,%6,%7}, {%8,%9}, {%0,%1,%2,%3};"
        : "+f"(c[0]), "+f"(c[1]), "+f"(c[2]), "+f"(c[3])
        : "r"(a[0]), "r"(a[1]), "r"(a[2]), "r"(a[3]), "r"(b0), "r"(b1));
}
__device__ __forceinline__ void cp_async16(uint32_t smem, const void* g) {
    asm volatile("cp.async.ca.shared.global [%0], [%1], 16;"
                 :: "r"(smem), "l"(g));
}
#define CP_COMMIT() asm volatile("cp.async.commit_group;" ::: "memory")
#define CP_WAIT0()  asm volatile("cp.async.wait_group 0;" ::: "memory")

__device__ __forceinline__ uint32_t pkbf(float a, float b) {
    __nv_bfloat162 t = __floats2bfloat162_rn(a, b);
    return *reinterpret_cast<uint32_t*>(&t);
}
__device__ __forceinline__ void red4(float* addr, float x, float y, float z,
                                     float w) {
    asm volatile("red.global.add.v4.f32 [%0], {%1, %2, %3, %4};"
                 :: "l"(addr), "f"(x), "f"(y), "f"(z), "f"(w) : "memory");
}

// One 64-k chunk of warp MMA: warp tile 64 rows x (NT*8) cols.
template <int SA, int NT>
__device__ __forceinline__ void mma_chunk(float (&acc)[4][NT][4],
                                          uint32_t aw, uint32_t bw, int lane) {
    const int arow = lane & 15, ak = (lane >> 4) << 3;
    const int brow = (lane & 7) + ((lane >> 4) << 3);
    const int bk = ((lane >> 3) & 1) << 3;
#pragma unroll
    for (int kt = 0; kt < 4; kt++) {
        uint32_t a[4][4], b[NT / 2][4];
#pragma unroll
        for (int mt = 0; mt < 4; mt++)
            ldsm_x4(a[mt], aw + ((mt * 16 + arow) * SA + kt * 16 + ak) * 2);
#pragma unroll
        for (int nb = 0; nb < NT / 2; nb++)
            ldsm_x4(b[nb], bw + ((nb * 16 + brow) * 72 + kt * 16 + bk) * 2);
#pragma unroll
        for (int mt = 0; mt < 4; mt++)
#pragma unroll
            for (int nb = 0; nb < NT / 2; nb++) {
                mma_bf16(acc[mt][2 * nb],     a[mt], b[nb][0], b[nb][1]);
                mma_bf16(acc[mt][2 * nb + 1], a[mt], b[nb][2], b[nb][3]);
            }
    }
}

// Common smem layout for the 64-k sliced kernels
#define SL_AHI 0
#define SL_ALO 18432
#define SL_BHI 36864
#define SL_BLO 55296
#define SL_END 73728

// ---------------------------------------------------------------------------
// K0: weight prep — transpose + hi/lo split (w1p, wa1, wa2)
// ---------------------------------------------------------------------------
__global__ void k_prep(const float* __restrict__ W1, const float* __restrict__ Wa1,
                       const float* __restrict__ Wa2) {
    int idx = blockIdx.x * 256 + threadIdx.x;
    float v;
    __nv_bfloat16 *dh, *dl;
    int off;
    if (idx < 65536) {                       // g_w1p [512n][128k]
        int n = idx >> 7, k = idx & 127;
        v = (n < 256) ? W1[k * 256 + n] : W1[(128 + k) * 256 + (n - 256)];
        dh = g_w1p_hi; dl = g_w1p_lo; off = idx;
    } else if (idx < 81920) {                // g_wa1t [128n][128k]
        int i = idx - 65536;
        int n = i >> 7, k = i & 127;
        v = Wa1[k * 128 + n];
        dh = g_wa1t_hi; dl = g_wa1t_lo; off = i;
    } else {                                 // g_wa2t
        int i = idx - 81920;
        if (i >= 16384) return;
        int n = i >> 7, k = i & 127;
        v = Wa2[k * 128 + n];
        dh = g_wa2t_hi; dl = g_wa2t_lo; off = i;
    }
    __nv_bfloat16 hi = __float2bfloat16(v);
    dh[off] = hi;
    dl[off] = __float2bfloat16(v - __bfloat162float(hi));
}

// Wc[k][c] = sum_j W2[k][j] * Wu[128+j][c]
__global__ void k_wc(const float* __restrict__ W2, const float* __restrict__ Wu) {
    int k = blockIdx.x, c = threadIdx.x;
    __shared__ float w2row[256];
    w2row[c] = W2[k * 256 + c];
    w2row[c + 128] = W2[k * 256 + c + 128];
    __syncthreads();
    float s = 0.f;
#pragma unroll 4
    for (int j = 0; j < 256; j++) s += w2row[j] * Wu[(128 + j) * 128 + c];
    g_wc[k * 128 + c] = s;
}

// Wpe[k][c] = sum_j W_edge[k][j] * W1[256+j][c]   (16 blocks x 256 thr)
__global__ void k_wpe(const float* __restrict__ We, const float* __restrict__ W1) {
    int k = blockIdx.x, c = threadIdx.x;
    __shared__ float wrow[64];
    if (threadIdx.x < 64) wrow[threadIdx.x] = We[k * 64 + threadIdx.x];
    __syncthreads();
    float s = 0.f;
#pragma unroll 4
    for (int j = 0; j < 64; j++) s += wrow[j] * W1[(256 + j) * 256 + c];
    g_wpe[k * 256 + c] = s;
}

// Pack combined update weight; bc; bpe.
__global__ void k_pack(const float* __restrict__ Wu, const float* __restrict__ b2,
                       const float* __restrict__ W1, const float* __restrict__ b1,
                       const float* __restrict__ be) {
    int idx = blockIdx.x * 256 + threadIdx.x;
    if (idx < 49152) {
        int n = idx / 384, k = idx - n * 384;
        float v = (k < 128) ? Wu[k * 128 + n] : g_wc[(k - 128) * 128 + n];
        __nv_bfloat16 hi = __float2bfloat16(v);
        g_wut2_hi[idx] = hi;
        g_wut2_lo[idx] = __float2bfloat16(v - __bfloat162float(hi));
    } else if (idx < 49280) {
        int c = idx - 49152;
        float s = 0.f;
        for (int j = 0; j < 256; j++) s += b2[j] * Wu[(128 + j) * 128 + c];
        g_bc[c] = s;
    } else if (idx < 49536) {
        int c = idx - 49280;
        float s = b1[c];
        for (int j = 0; j < 64; j++) s += be[j] * W1[(256 + j) * 256 + c];
        g_bpe[c] = s;
    }
}

__global__ void k_deg(const int* __restrict__ to_idx, int E) {
    int i = blockIdx.x * 256 + threadIdx.x;
    if (i < E) atomicAdd(&g_deg[to_idx[i]], 1);
}

// ---------------------------------------------------------------------------
// K1: node encoder
// ---------------------------------------------------------------------------
__global__ void k_enc_node(const float* __restrict__ nf,
                           const float* __restrict__ Wn,
                           const float* __restrict__ bn, int N) {
    __shared__ float Ws[32 * 128];
    for (int i = threadIdx.x; i < 32 * 128; i += 256) Ws[i] = Wn[i];
    __syncthreads();
    int idx = blockIdx.x * 256 + threadIdx.x;
    if (idx >= N * 128) return;
    int n = idx >> 7, c = idx & 127;
    const float* row = nf + n * 32;
    float s = bn[c];
#pragma unroll
    for (int k = 0; k < 32; k++) s += row[k] * Ws[k * 128 + c];
    g_h[idx] = s;
    __nv_bfloat16 hi = __float2bfloat16(s);
    g_h_hi[idx] = hi;
    g_h_lo[idx] = __float2bfloat16(s - __bfloat162float(hi));
}

// ---------------------------------------------------------------------------
// K4: P12 = h @ [W1_top|W1_mid] (+bpe on P2 half).  128 nodes x 128 cols.
// ---------------------------------------------------------------------------
__global__ void __launch_bounds__(256, 2)
k_nodeprod(int N) {
    extern __shared__ unsigned char sm[];
    const uint32_t base = smem_to_u32(sm);
    const int tid = threadIdx.x, lane = tid & 31, wid = tid >> 5;
    const int cb = blockIdx.x & 3, rb = blockIdx.x >> 2;
    const int n0 = rb * 128;
    const int wm = wid >> 2, wn = wid & 3;
    float acc[4][4][4];
#pragma unroll
    for (int i = 0; i < 4; i++)
#pragma unroll
        for (int j = 0; j < 4; j++)
#pragma unroll
            for (int k = 0; k < 4; k++) acc[i][j][k] = 0.f;

    for (int kc = 0; kc < 2; kc++) {
        {
            int row = tid & 127, which = tid >> 7;
            const __nv_bfloat16* src =
                (which ? g_w1p_lo : g_w1p_hi) +
                (size_t)(cb * 128 + row) * 128 + kc * 64;
            uint32_t dst = base + (which ? SL_BLO : SL_BHI) + row * 144;
#pragma unroll
            for (int j = 0; j < 8; j++) cp_async16(dst + j * 16, src + j * 8);
            CP_COMMIT();
        }
        {
            int row = tid & 127, which = tid >> 7;
            const __nv_bfloat16* src =
                (which ? g_h_lo : g_h_hi) + (size_t)(n0 + row) * 128 + kc * 64;
            unsigned char* dst = sm + (which ? SL_ALO : SL_AHI) + row * 144;
#pragma unroll
            for (int j = 0; j < 8; j++)
                *(uint4*)(dst + j * 16) = *(const uint4*)(src + j * 8);
        }
        CP_WAIT0();
        __syncthreads();
#pragma unroll
        for (int p = 0; p < 3; p++) {
            uint32_t aw = base + (p == 1 ? SL_ALO : SL_AHI) + (wm * 64 * 72) * 2;
            uint32_t bw = base + (p == 2 ? SL_BLO : SL_BHI) + (wn * 32) * 144;
            mma_chunk<72, 4>(acc, aw, bw, lane);
        }
        __syncthreads();
    }
#pragma unroll
    for (int mt = 0; mt < 4; mt++) {
        int r0 = wm * 64 + mt * 16 + (lane >> 2);
        int n1 = n0 + r0, n2 = n1 + 8;
#pragma unroll
        for (int nt = 0; nt < 4; nt++) {
            int colp = wn * 32 + nt * 8 + 2 * (lane & 3);
            int col = cb * 128 + colp;
            float2 badd = make_float2(0.f, 0.f);
            if (cb >= 2) badd = *(const float2*)(g_bpe + (cb - 2) * 128 + colp);
            if (n1 < N)
                *(float2*)(g_P + (size_t)n1 * 512 + col) =
                    make_float2(acc[mt][nt][0] + badd.x, acc[mt][nt][1] + badd.y);
            if (n2 < N)
                *(float2*)(g_P + (size_t)n2 * 512 + col) =
                    make_float2(acc[mt][nt][2] + badd.x, acc[mt][nt][3] + badd.y);
        }
    }
}

// ---------------------------------------------------------------------------
// K5: hidden = relu(P1[from]+P2[to]+ef@Wpe); aggH[to] += hidden (red.v4).
//     Per block: 64 edges.  Thread owns 4 fixed cols; Wpe cols in registers.
// ---------------------------------------------------------------------------
__global__ void __launch_bounds__(256)
k_hidden(const int* __restrict__ from_idx, const int* __restrict__ to_idx,
         const float* __restrict__ ef, int E) {
    __shared__ float ef_sm[64 * 16];
    __shared__ int from_sm[64], to_sm[64];
    const int tid = threadIdx.x;
    const int e0 = blockIdx.x * 64;
    const int cg = tid & 63, sub = tid >> 6;

    if (tid < 64) {
        int ed = e0 + tid;
        from_sm[tid] = (ed < E) ? from_idx[ed] : -1;
        to_sm[tid]   = (ed < E) ? to_idx[ed] : 0;
    }
#pragma unroll
    for (int i = 0; i < 4; i++) {
        int idx = tid + 256 * i;
        int ed = e0 + (idx >> 4);
        ef_sm[idx] = (ed < E) ? ef[(size_t)ed * 16 + (idx & 15)] : 0.f;
    }
    float4 w[16];
#pragma unroll
    for (int k = 0; k < 16; k++)
        w[k] = *(const float4*)(g_wpe + k * 256 + cg * 4);
    __syncthreads();

#pragma unroll 2
    for (int i = 0; i < 16; i++) {
        int le = i * 4 + sub;
        int f = from_sm[le];
        if (f < 0) continue;
        int t = to_sm[le];
        const float4 p1 = *(const float4*)(g_P + (size_t)f * 512 + cg * 4);
        const float4 p2 = *(const float4*)(g_P + (size_t)t * 512 + 256 + cg * 4);
        float s0 = p1.x + p2.x, s1 = p1.y + p2.y;
        float s2 = p1.z + p2.z, s3 = p1.w + p2.w;
        const float* er = ef_sm + le * 16;
#pragma unroll
        for (int k = 0; k < 16; k++) {
            float e = er[k];
            s0 = fmaf(e, w[k].x, s0);
            s1 = fmaf(e, w[k].y, s1);
            s2 = fmaf(e, w[k].z, s2);
            s3 = fmaf(e, w[k].w, s3);
        }
        s0 = fmaxf(s0, 0.f); s1 = fmaxf(s1, 0.f);
        s2 = fmaxf(s2, 0.f); s3 = fmaxf(s3, 0.f);
        red4(g_aggH + (size_t)t * 256 + cg * 4, s0, s1, s2, s3);
    }
}

// ---------------------------------------------------------------------------
// K6: node update  h += [h|aggH] @ Wut2 + bu + deg*bc.
// ---------------------------------------------------------------------------
__global__ void __launch_bounds__(256, 2)
k_upd2(const float* __restrict__ bu, int N) {
    extern __shared__ unsigned char sm[];
    const uint32_t base = smem_to_u32(sm);
    const int tid = threadIdx.x, lane = tid & 31, wid = tid >> 5;
    const int n0 = blockIdx.x * 128;
    const int wm = wid >> 2, wn = wid & 3;
    float acc[4][4][4];
#pragma unroll
    for (int i = 0; i < 4; i++)
#pragma unroll
        for (int j = 0; j < 4; j++)
#pragma unroll
            for (int k = 0; k < 4; k++) acc[i][j][k] = 0.f;

    for (int kc = 0; kc < 6; kc++) {
        {
            int row = tid & 127, which = tid >> 7;
            const __nv_bfloat16* src =
                (which ? g_wut2_lo : g_wut2_hi) + (size_t)row * 384 + kc * 64;
            uint32_t dst = base + (which ? SL_BLO : SL_BHI) + row * 144;
#pragma unroll
            for (int j = 0; j < 8; j++) cp_async16(dst + j * 16, src + j * 8);
            CP_COMMIT();
        }
#pragma unroll 2
        for (int i = 0; i < 8; i++) {
            int idx = tid + 256 * i;
            int row = idx >> 4, q = idx & 15;
            float4 v;
            if (kc < 2)
                v = *(const float4*)(g_h + (size_t)(n0 + row) * 128 +
                                     kc * 64 + q * 4);
            else
                v = *(const float4*)(g_aggH + (size_t)(n0 + row) * 256 +
                                     (kc - 2) * 64 + q * 4);
            __nv_bfloat16 h0 = __float2bfloat16(v.x), h1 = __float2bfloat16(v.y);
            __nv_bfloat16 h2 = __float2bfloat16(v.z), h3 = __float2bfloat16(v.w);
            uint2 hp, lp;
            hp.x = pkbf(v.x, v.y); hp.y = pkbf(v.z, v.w);
            lp.x = pkbf(v.x - __bfloat162float(h0), v.y - __bfloat162float(h1));
            lp.y = pkbf(v.z - __bfloat162float(h2), v.w - __bfloat162float(h3));
            int boff = (row * 72 + q * 4) * 2;
            *(uint2*)(sm + SL_AHI + boff) = hp;
            *(uint2*)(sm + SL_ALO + boff) = lp;
        }
        CP_WAIT0();
        __syncthreads();
#pragma unroll
        for (int p = 0; p < 3; p++) {
            uint32_t aw = base + (p == 1 ? SL_ALO : SL_AHI) + (wm * 64 * 72) * 2;
            uint32_t bw = base + (p == 2 ? SL_BLO : SL_BHI) + (wn * 32) * 144;
            mma_chunk<72, 4>(acc, aw, bw, lane);
        }
        __syncthreads();
    }
#pragma unroll
    for (int mt = 0; mt < 4; mt++) {
        int rr[2];
        rr[0] = wm * 64 + mt * 16 + (lane >> 2);
        rr[1] = rr[0] + 8;
#pragma unroll
        for (int nt = 0; nt < 4; nt++) {
            int col = wn * 32 + nt * 8 + 2 * (lane & 3);
            float2 bb = *(const float2*)(bu + col);
            float2 bc2 = *(const float2*)(g_bc + col);
#pragma unroll
            for (int h = 0; h < 2; h++) {
                int n = n0 + rr[h];
                if (n < N) {
                    float degf = (float)g_deg[n];
#pragma unroll
                    for (int z = 0; z < 2; z++) {
                        float v = g_h[(size_t)n * 128 + col + z] +
                                  acc[mt][nt][2 * h + z] + (z ? bb.y : bb.x) +
                                  degf * (z ? bc2.y : bc2.x);
                        g_h[(size_t)n * 128 + col + z] = v;
                        __nv_bfloat16 hi = __float2bfloat16(v);
                        g_h_hi[(size_t)n * 128 + col + z] = hi;
                        g_h_lo[(size_t)n * 128 + col + z] =
                            __float2bfloat16(v - __bfloat162float(hi));
                    }
                }
            }
        }
    }
}

// ---------------------------------------------------------------------------
// K7: scatter into padded stacks
// ---------------------------------------------------------------------------
__global__ void k_scatter(const int* __restrict__ pos, int N) {
    int idx = blockIdx.x * 256 + threadIdx.x;
    if (idx >= N * 128) return;
    int n = idx >> 7, c = idx & 127;
    g_flat[pos[n] * 128 + c] = g_h[idx];
}

// ---------------------------------------------------------------------------
// K8: attention features via MMA
// ---------------------------------------------------------------------------
#define AT_HIDHI 0
#define AT_HIDLO 34816
#define AT_B2HI  73728
#define AT_B2LO  92160
#define AT_SMEM  110592
__global__ void __launch_bounds__(256, 2)
k_att2(const float* __restrict__ ba1, const float* __restrict__ ba2,
       const int* __restrict__ qsz, const int* __restrict__ csz) {
    extern __shared__ unsigned char sm[];
    const uint32_t base = smem_to_u32(sm);
    const int tid = threadIdx.x, lane = tid & 31, wid = tid >> 5;
    const int r0 = blockIdx.x * 128;
    const int wm = wid >> 2, wn = wid & 3;
    float acc[4][4][4];
#pragma unroll
    for (int i = 0; i < 4; i++)
#pragma unroll
        for (int j = 0; j < 4; j++)
#pragma unroll
            for (int k = 0; k < 4; k++) acc[i][j][k] = 0.f;

    for (int kc = 0; kc < 2; kc++) {
        {
            int row = tid & 127, which = tid >> 7;
            const __nv_bfloat16* src =
                (which ? g_wa1t_lo : g_wa1t_hi) + (size_t)row * 128 + kc * 64;
            uint32_t dst = base + (which ? AT_B2LO : AT_B2HI) + row * 144;
#pragma unroll
            for (int j = 0; j < 8; j++) cp_async16(dst + j * 16, src + j * 8);
            CP_COMMIT();
        }
#pragma unroll 2
        for (int i = 0; i < 8; i++) {
            int idx = tid + 256 * i;
            int row = idx >> 4, q = idx & 15;
            float4 v = *(const float4*)(g_flat + (size_t)(r0 + row) * 128 +
                                        kc * 64 + q * 4);
            __nv_bfloat16 h0 = __float2bfloat16(v.x), h1 = __float2bfloat16(v.y);
            __nv_bfloat16 h2 = __float2bfloat16(v.z), h3 = __float2bfloat16(v.w);
            uint2 hp, lp;
            hp.x = pkbf(v.x, v.y); hp.y = pkbf(v.z, v.w);
            lp.x = pkbf(v.x - __bfloat162float(h0), v.y - __bfloat162float(h1));
            lp.y = pkbf(v.z - __bfloat162float(h2), v.w - __bfloat162float(h3));
            int boff = (row * 72 + q * 4) * 2;
            *(uint2*)(sm + SL_AHI + boff) = hp;
            *(uint2*)(sm + SL_ALO + boff) = lp;
        }
        CP_WAIT0();
        __syncthreads();
#pragma unroll
        for (int p = 0; p < 3; p++) {
            uint32_t aw = base + (p == 1 ? SL_ALO : SL_AHI) + (wm * 64 * 72) * 2;
            uint32_t bw = base + (p == 2 ? AT_B2LO : AT_B2HI) + (wn * 32) * 144;
            mma_chunk<72, 4>(acc, aw, bw, lane);
        }
        __syncthreads();
    }
#pragma unroll
    for (int mt = 0; mt < 4; mt++) {
        int rr0 = wm * 64 + mt * 16 + (lane >> 2);
#pragma unroll
        for (int nt = 0; nt < 4; nt++) {
            int col = wn * 32 + nt * 8 + 2 * (lane & 3);
            float2 bb = *(const float2*)(ba1 + col);
#pragma unroll
            for (int h = 0; h < 2; h++) {
                int row = rr0 + h * 8;
                float v0 = fmaxf(acc[mt][nt][2 * h]     + bb.x, 0.f);
                float v1 = fmaxf(acc[mt][nt][2 * h + 1] + bb.y, 0.f);
                __nv_bfloat16 b0 = __float2bfloat16(v0), b1 = __float2bfloat16(v1);
                int boff = (row * 136 + col) * 2;
                *(uint32_t*)(sm + AT_HIDHI + boff) = pkbf(v0, v1);
                *(uint32_t*)(sm + AT_HIDLO + boff) =
                    pkbf(v0 - __bfloat162float(b0), v1 - __bfloat162float(b1));
            }
            acc[mt][nt][0] = acc[mt][nt][1] = acc[mt][nt][2] = acc[mt][nt][3] = 0.f;
        }
    }
    __syncthreads();
    for (int kc = 0; kc < 2; kc++) {
        {
            int row = tid & 127, which = tid >> 7;
            const __nv_bfloat16* src =
                (which ? g_wa2t_lo : g_wa2t_hi) + (size_t)row * 128 + kc * 64;
            uint32_t dst = base + (which ? AT_B2LO : AT_B2HI) + row * 144;
#pragma unroll
            for (int j = 0; j < 8; j++) cp_async16(dst + j * 16, src + j * 8);
            CP_COMMIT();
        }
        CP_WAIT0();
        __syncthreads();
#pragma unroll
        for (int p = 0; p < 3; p++) {
            uint32_t aw = base + (p == 1 ? AT_HIDLO : AT_HIDHI) +
                          (wm * 64 * 136 + kc * 64) * 2;
            uint32_t bw = base + (p == 2 ? AT_B2LO : AT_B2HI) + (wn * 32) * 144;
            mma_chunk<136, 4>(acc, aw, bw, lane);
        }
        __syncthreads();
    }
#pragma unroll
    for (int mt = 0; mt < 4; mt++) {
        int rr0 = wm * 64 + mt * 16 + (lane >> 2);
#pragma unroll
        for (int nt = 0; nt < 4; nt++) {
            int col = wn * 32 + nt * 8 + 2 * (lane & 3);
            float2 bb = *(const float2*)(ba2 + col);
#pragma unroll
            for (int h = 0; h < 2; h++) {
                int row = r0 + rr0 + h * 8;
                int gi = row >> 6, q = row & 63;
                int size = (gi < 256) ? qsz[gi] : csz[gi - 256];
                bool ok = q < size;
                float v0 = ok ? acc[mt][nt][2 * h]     + bb.x : 0.f;
                float v1 = ok ? acc[mt][nt][2 * h + 1] + bb.y : 0.f;
                *(float2*)(g_t + (size_t)row * 128 + col) = make_float2(v0, v1);
            }
        }
    }
}

// ---------------------------------------------------------------------------
// K9: per-pair logits, dual softmax, hinge alignment, min
// ---------------------------------------------------------------------------
#define PAIR_SMEM ((2 * 64 * 129 + 3 * 64 * 65) * 4)
__global__ void __launch_bounds__(256, 1)
k_pair(const int* __restrict__ qsz, const int* __restrict__ csz,
       float* __restrict__ out) {
    extern __shared__ float smf[];
    float* bufA = smf;
    float* bufB = bufA + 64 * 129;
    float* L    = bufB + 64 * 129;
    float* pq   = L + 64 * 65;
    float* pc   = pq + 64 * 65;
    __shared__ float redq[8], redc[8];

    const int b = blockIdx.x, tid = threadIdx.x;
    const int qs = qsz[b], cs = csz[b];
    const int qbase = b * 64, cbase = 16384 + b * 64;

    for (int idx = tid; idx < 64 * 128; idx += 256) {
        int r = idx >> 7, k = idx & 127;
        bufA[r * 129 + k] = g_t[(qbase + r) * 128 + k];
        bufB[r * 129 + k] = g_t[(cbase + r) * 128 + k];
    }
    __syncthreads();
    {
        int q = tid >> 2, cg = tid & 3;
        float acc[16];
#pragma unroll
        for (int j = 0; j < 16; j++) acc[j] = 0.f;
        for (int k = 0; k < 128; k++) {
            float a = bufA[q * 129 + k];
            const float* bp = bufB + (cg * 16) * 129 + k;
#pragma unroll
            for (int j = 0; j < 16; j++) acc[j] += a * bp[j * 129];
        }
        bool qv = q < qs;
#pragma unroll
        for (int j = 0; j < 16; j++) {
            int c = cg * 16 + j;
            L[q * 65 + c] = (qv && c < cs) ? acc[j] * 10.0f : -1e9f;
        }
    }
    __syncthreads();
    for (int idx = tid; idx < 64 * 128; idx += 256) {
        int r = idx >> 7, k = idx & 127;
        bufA[r * 129 + k] = g_flat[(qbase + r) * 128 + k];
        bufB[r * 129 + k] = g_flat[(cbase + r) * 128 + k];
    }
    if (tid < 64) {
        float m = -1e30f;
        for (int c = 0; c < 64; c++) m = fmaxf(m, L[tid * 65 + c]);
        float s = 0.f;
        for (int c = 0; c < 64; c++) {
            float ex = __expf(L[tid * 65 + c] - m);
            s += ex;
            pq[tid * 65 + c] = ex;
        }
        float inv = (tid < qs) ? (1.0f / s) : 0.f;
        for (int c = 0; c < 64; c++) pq[tid * 65 + c] *= inv;
    } else if (tid < 128) {
        int c = tid - 64;
        float m = -1e30f;
        for (int q = 0; q < 64; q++) m = fmaxf(m, L[q * 65 + c]);
        float s = 0.f;
        for (int q = 0; q < 64; q++) {
            float ex = __expf(L[q * 65 + c] - m);
            s += ex;
            pc[q * 65 + c] = ex;
        }
        float inv = (c < cs) ? (1.0f / s) : 0.f;
        for (int q = 0; q < 64; q++) pc[q * 65 + c] *= inv;
    }
    __syncthreads();
    float lq = 0.f, lc = 0.f;
    {
        const int d = tid & 127, gg = tid >> 7;
        float acc[32];
#pragma unroll
        for (int j = 0; j < 32; j++) acc[j] = 0.f;
        for (int c = 0; c < 64; c++) {
            float bb = bufB[c * 129 + d];
            const float* pp = pq + (gg * 32) * 65 + c;
#pragma unroll
            for (int j = 0; j < 32; j++) acc[j] += pp[j * 65] * bb;
        }
#pragma unroll
        for (int j = 0; j < 32; j++) {
            int q = gg * 32 + j;
            lq += fmaxf(bufA[q * 129 + d] - acc[j], 0.f);
        }
#pragma unroll
        for (int j = 0; j < 32; j++) acc[j] = 0.f;
        for (int q = 0; q < 64; q++) {
            float aa = bufA[q * 129 + d];
            const float* pp = pc + q * 65 + gg * 32;
#pragma unroll
            for (int j = 0; j < 32; j++) acc[j] += pp[j] * aa;
        }
#pragma unroll
        for (int j = 0; j < 32; j++) {
            int c = gg * 32 + j;
            lc += fmaxf(bufB[c * 129 + d] - acc[j], 0.f);
        }
    }
    for (int o = 16; o; o >>= 1) {
        lq += __shfl_down_sync(0xffffffffu, lq, o);
        lc += __shfl_down_sync(0xffffffffu, lc, o);
    }
    int w = tid >> 5, lane = tid & 31;
    if (lane == 0) { redq[w] = lq; redc[w] = lc; }
    __syncthreads();
    if (tid == 0) {
        float sq = 0.f, sc = 0.f;
        for (int i = 0; i < 8; i++) { sq += redq[i]; sc += redc[i]; }
        out[b] = fminf(-sq, -sc);
    }
}

// ---------------------------------------------------------------------------
extern "C" void kernel_launch(void* const* d_in, const int* in_sizes, int n_in,
                              void* d_out, int out_size) {
    const float* nf       = (const float*)d_in[0];
    const float* ef       = (const float*)d_in[1];
    const int*   from_idx = (const int*)d_in[2];
    const int*   to_idx   = (const int*)d_in[3];
    const int*   pos      = (const int*)d_in[4];
    const int*   qsz      = (const int*)d_in[5];
    const int*   csz      = (const int*)d_in[6];
    const float* W_node = (const float*)d_in[7];
    const float* b_node = (const float*)d_in[8];
    const float* W_edge = (const float*)d_in[9];
    const float* b_edge = (const float*)d_in[10];
    const float* W_msg1 = (const float*)d_in[11];
    const float* b_msg1 = (const float*)d_in[12];
    const float* W_msg2 = (const float*)d_in[13];
    const float* b_msg2 = (const float*)d_in[14];
    const float* W_upd  = (const float*)d_in[15];
    const float* b_upd  = (const float*)d_in[16];
    const float* Wa1    = (const float*)d_in[17];
    const float* ba1    = (const float*)d_in[18];
    const float* Wa2    = (const float*)d_in[19];
    const float* ba2    = (const float*)d_in[20];

    const int N = in_sizes[0] / 32;
    const int E = in_sizes[1] / 16;

    cudaFuncSetAttribute(k_nodeprod, cudaFuncAttributeMaxDynamicSharedMemorySize, SL_END);
    cudaFuncSetAttribute(k_upd2,     cudaFuncAttributeMaxDynamicSharedMemorySize, SL_END);
    cudaFuncSetAttribute(k_att2,     cudaFuncAttributeMaxDynamicSharedMemorySize, AT_SMEM);
    cudaFuncSetAttribute(k_pair,     cudaFuncAttributeMaxDynamicSharedMemorySize, PAIR_SMEM);

    void* aggp = nullptr;
    void* degp = nullptr;
    cudaGetSymbolAddress(&aggp, g_aggH);
    cudaGetSymbolAddress(&degp, g_deg);

    const int egrid = (E + 63) / 64;
    const int ngrid = (N + 127) / 128;

    k_prep<<<384, 256>>>(W_msg1, Wa1, Wa2);
    k_wc<<<256, 128>>>(W_msg2, W_upd);
    k_wpe<<<16, 256>>>(W_edge, W_msg1);
    k_pack<<<194, 256>>>(W_upd, b_msg2, W_msg1, b_msg1, b_edge);
    cudaMemsetAsync(degp, 0, (size_t)N * sizeof(int));
    k_deg<<<(E + 255) / 256, 256>>>(to_idx, E);
    k_enc_node<<<(N * 128 + 255) / 256, 256>>>(nf, W_node, b_node, N);

    for (int s = 0; s < 3; s++) {
        cudaMemsetAsync(aggp, 0, (size_t)N * 256 * sizeof(float));
        k_nodeprod<<<ngrid * 4, 256, SL_END>>>(N);
        k_hidden<<<egrid, 256>>>(from_idx, to_idx, ef, E);
        k_upd2<<<ngrid, 256, SL_END>>>(b_upd, N);
    }

    k_scatter<<<(N * 128 + 255) / 256, 256>>>(pos, N);
    k_att2<<<256, 256, AT_SMEM>>>(ba1, ba2, qsz, csz);
    k_pair<<<256, 256, PAIR_SMEM>>>(qsz, csz, (float*)d_out);
}

// round 7
// speedup vs baseline: 8.9395x; 1.0548x over previous
#include <cuda_runtime.h>
#include <cuda_bf16.h>
#include <cstdint>

#define NMAX 32768
#define EMAX 262144

// Scratch
__device__ float g_h   [NMAX * 128];
__device__ float g_aggH[NMAX * 256];
__device__ float g_flat[2 * 256 * 64 * 128];
__device__ float g_t   [2 * 256 * 64 * 128];
__device__ float g_P   [NMAX * 512];
__device__ float g_wc  [256 * 128];
__device__ float g_bc  [128];
__device__ float g_wpe [16 * 256];
__device__ float g_bpe [256];
__device__ int   g_deg [NMAX];
__device__ __align__(16) __nv_bfloat16 g_h_hi[NMAX * 128];
__device__ __align__(16) __nv_bfloat16 g_h_lo[NMAX * 128];
__device__ __align__(16) __nv_bfloat16 g_w1p_hi[512 * 128], g_w1p_lo[512 * 128];
__device__ __align__(16) __nv_bfloat16 g_wut2_hi[128 * 384], g_wut2_lo[128 * 384];
__device__ __align__(16) __nv_bfloat16 g_wa1t_hi[128 * 128], g_wa1t_lo[128 * 128];
__device__ __align__(16) __nv_bfloat16 g_wa2t_hi[128 * 128], g_wa2t_lo[128 * 128];

// ---------------------------------------------------------------------------
// helpers
// ---------------------------------------------------------------------------
__device__ __forceinline__ uint32_t smem_to_u32(const void* p) {
    uint32_t a;
    asm("{ .reg .u64 t; cvta.to.shared.u64 t, %1; cvt.u32.u64 %0, t; }"
        : "=r"(a) : "l"(p));
    return a;
}
__device__ __forceinline__ void ldsm_x4(uint32_t r[4], uint32_t addr) {
    asm volatile("ldmatrix.sync.aligned.m8n8.x4.shared.b16 {%0,%1,%2,%3}, [%4];"
                 : "=r"(r[0]), "=r"(r[1]), "=r"(r[2]), "=r"(r[3]) : "r"(addr));
}
__device__ __forceinline__ void mma_bf16(float c[4], const uint32_t a[4],
                                         uint32_t b0, uint32_t b1) {
    asm volatile(
        "mma.sync.aligned.m16n8k16.row.col.f32.bf16.bf16.f32 "
        "{%0,%1,%2,%3}, {%4,%5,%6,%7}, {%8,%9}, {%0,%1,%2,%3};"
        : "+f"(c[0]), "+f"(c[1]), "+f"(c[2]), "+f"(c[3])
        : "r"(a[0]), "r"(a[1]), "r"(a[2]), "r"(a[3]), "r"(b0), "r"(b1));
}
__device__ __forceinline__ void cp_async16(uint32_t smem, const void* g) {
    asm volatile("cp.async.ca.shared.global [%0], [%1], 16;"
                 :: "r"(smem), "l"(g));
}
#define CP_COMMIT() asm volatile("cp.async.commit_group;" ::: "memory")
#define CP_WAIT0()  asm volatile("cp.async.wait_group 0;" ::: "memory")

__device__ __forceinline__ uint32_t pkbf(float a, float b) {
    __nv_bfloat162 t = __floats2bfloat162_rn(a, b);
    return *reinterpret_cast<uint32_t*>(&t);
}
__device__ __forceinline__ void red4(float* addr, float x, float y, float z,
                                     float w) {
    asm volatile("red.global.add.v4.f32 [%0], {%1, %2, %3, %4};"
                 :: "l"(addr), "f"(x), "f"(y), "f"(z), "f"(w) : "memory");
}

template <int SA, int NT>
__device__ __forceinline__ void mma_chunk(float (&acc)[4][NT][4],
                                          uint32_t aw, uint32_t bw, int lane) {
    const int arow = lane & 15, ak = (lane >> 4) << 3;
    const int brow = (lane & 7) + ((lane >> 4) << 3);
    const int bk = ((lane >> 3) & 1) << 3;
#pragma unroll
    for (int kt = 0; kt < 4; kt++) {
        uint32_t a[4][4], b[NT / 2][4];
#pragma unroll
        for (int mt = 0; mt < 4; mt++)
            ldsm_x4(a[mt], aw + ((mt * 16 + arow) * SA + kt * 16 + ak) * 2);
#pragma unroll
        for (int nb = 0; nb < NT / 2; nb++)
            ldsm_x4(b[nb], bw + ((nb * 16 + brow) * 72 + kt * 16 + bk) * 2);
#pragma unroll
        for (int mt = 0; mt < 4; mt++)
#pragma unroll
            for (int nb = 0; nb < NT / 2; nb++) {
                mma_bf16(acc[mt][2 * nb],     a[mt], b[nb][0], b[nb][1]);
                mma_bf16(acc[mt][2 * nb + 1], a[mt], b[nb][2], b[nb][3]);
            }
    }
}

#define SL_AHI 0
#define SL_ALO 18432
#define SL_BHI 36864
#define SL_BLO 55296
#define SL_END 73728

// ---------------------------------------------------------------------------
// K0a: weight transpose + hi/lo split (w1p, wa1t, wa2t)
// ---------------------------------------------------------------------------
__global__ void k_prep(const float* __restrict__ W1, const float* __restrict__ Wa1,
                       const float* __restrict__ Wa2) {
    int idx = blockIdx.x * 256 + threadIdx.x;
    float v;
    __nv_bfloat16 *dh, *dl;
    int off;
    if (idx < 65536) {
        int n = idx >> 7, k = idx & 127;
        v = (n < 256) ? W1[k * 256 + n] : W1[(128 + k) * 256 + (n - 256)];
        dh = g_w1p_hi; dl = g_w1p_lo; off = idx;
    } else if (idx < 81920) {
        int i = idx - 65536;
        int n = i >> 7, k = i & 127;
        v = Wa1[k * 128 + n];
        dh = g_wa1t_hi; dl = g_wa1t_lo; off = i;
    } else {
        int i = idx - 81920;
        if (i >= 16384) return;
        int n = i >> 7, k = i & 127;
        v = Wa2[k * 128 + n];
        dh = g_wa2t_hi; dl = g_wa2t_lo; off = i;
    }
    __nv_bfloat16 hi = __float2bfloat16(v);
    dh[off] = hi;
    dl[off] = __float2bfloat16(v - __bfloat162float(hi));
}

// K0b: fused Wc + Wpe.  bid<128: Wc (2 k-rows/block); else Wpe (bid-128).
__global__ void k_wcpe(const float* __restrict__ W2, const float* __restrict__ Wu,
                       const float* __restrict__ We, const float* __restrict__ W1) {
    int bid = blockIdx.x, tid = threadIdx.x;
    if (bid < 128) {
        int k = bid * 2 + (tid >> 7), c = tid & 127;
        __shared__ float w2row[2][256];
        w2row[tid >> 7][c] = W2[k * 256 + c];
        w2row[tid >> 7][c + 128] = W2[k * 256 + c + 128];
        __syncthreads();
        float s = 0.f;
        const float* wr = w2row[tid >> 7];
#pragma unroll 4
        for (int j = 0; j < 256; j++) s += wr[j] * Wu[(128 + j) * 128 + c];
        g_wc[k * 128 + c] = s;
    } else {
        int k = bid - 128, c = tid;
        __shared__ float wrow[64];
        if (tid < 64) wrow[tid] = We[k * 64 + tid];
        __syncthreads();
        float s = 0.f;
#pragma unroll 4
        for (int j = 0; j < 64; j++) s += wrow[j] * W1[(256 + j) * 256 + c];
        g_wpe[k * 256 + c] = s;
    }
}

// K0c: pack wut2 (coalesced reads) + bc + bpe.
__global__ void k_pack(const float* __restrict__ Wu, const float* __restrict__ b2,
                       const float* __restrict__ W1, const float* __restrict__ b1,
                       const float* __restrict__ be) {
    int idx = blockIdx.x * 256 + threadIdx.x;
    if (idx < 49152) {
        int n = idx & 127, k = idx >> 7;   // k-major: coalesced reads
        float v = (k < 128) ? Wu[k * 128 + n] : g_wc[(k - 128) * 128 + n];
        __nv_bfloat16 hi = __float2bfloat16(v);
        int off = n * 384 + k;
        g_wut2_hi[off] = hi;
        g_wut2_lo[off] = __float2bfloat16(v - __bfloat162float(hi));
    } else if (idx < 49280) {
        int c = idx - 49152;
        float s = 0.f;
#pragma unroll 4
        for (int j = 0; j < 256; j++) s += b2[j] * Wu[(128 + j) * 128 + c];
        g_bc[c] = s;
    } else if (idx < 49536) {
        int c = idx - 49280;
        float s = b1[c];
#pragma unroll 4
        for (int j = 0; j < 64; j++) s += be[j] * W1[(256 + j) * 256 + c];
        g_bpe[c] = s;
    }
}

__global__ void k_deg(const int* __restrict__ to_idx, int E) {
    int i = blockIdx.x * 256 + threadIdx.x;
    if (i < E) atomicAdd(&g_deg[to_idx[i]], 1);
}

// ---------------------------------------------------------------------------
// K1: node encoder, tiled: 16 nodes/block, nf staged in smem
// ---------------------------------------------------------------------------
__global__ void __launch_bounds__(256)
k_enc_node(const float* __restrict__ nf, const float* __restrict__ Wn,
           const float* __restrict__ bn, int N) {
    __shared__ float Ws[32 * 128];
    __shared__ float nfs[16 * 32];
    __shared__ float bns[128];
    const int tid = threadIdx.x;
    const int n0 = blockIdx.x * 16;
#pragma unroll
    for (int i = 0; i < 16; i++) Ws[tid + 256 * i] = Wn[tid + 256 * i];
    if (tid < 128) bns[tid] = bn[tid];
#pragma unroll
    for (int i = 0; i < 2; i++) {
        int idx = tid + 256 * i;
        int node = idx >> 5, k = idx & 31;
        int n = n0 + node;
        nfs[idx] = (n < N) ? nf[(size_t)n * 32 + k] : 0.f;
    }
    __syncthreads();
#pragma unroll
    for (int i = 0; i < 8; i++) {
        int o = tid + 256 * i;
        int node = o >> 7, c = o & 127;
        int n = n0 + node;
        if (n >= N) continue;
        float s = bns[c];
        const float* nr = nfs + node * 32;
#pragma unroll
        for (int k = 0; k < 32; k++) s = fmaf(nr[k], Ws[k * 128 + c], s);
        size_t gi = (size_t)n * 128 + c;
        g_h[gi] = s;
        __nv_bfloat16 hi = __float2bfloat16(s);
        g_h_hi[gi] = hi;
        g_h_lo[gi] = __float2bfloat16(s - __bfloat162float(hi));
    }
}

// ---------------------------------------------------------------------------
// K4: P12 = h @ [W1_top|W1_mid] (+bpe on P2 half); cb<2 also zero aggH half.
// ---------------------------------------------------------------------------
__global__ void __launch_bounds__(256, 2)
k_nodeprod(int N) {
    extern __shared__ unsigned char sm[];
    const uint32_t base = smem_to_u32(sm);
    const int tid = threadIdx.x, lane = tid & 31, wid = tid >> 5;
    const int cb = blockIdx.x & 3, rb = blockIdx.x >> 2;
    const int n0 = rb * 128;
    const int wm = wid >> 2, wn = wid & 3;

    // zero aggH for this 128-node tile (cb 0/1 each take a 128-col half)
    if (cb < 2) {
        const float4 z = make_float4(0.f, 0.f, 0.f, 0.f);
#pragma unroll
        for (int i = 0; i < 16; i++) {
            int idx = tid + 256 * i;          // 4096 float4 slots
            int row = idx >> 5, q = idx & 31;
            int n = n0 + row;
            if (n < N)
                *(float4*)(g_aggH + (size_t)n * 256 + cb * 128 + q * 4) = z;
        }
    }

    float acc[4][4][4];
#pragma unroll
    for (int i = 0; i < 4; i++)
#pragma unroll
        for (int j = 0; j < 4; j++)
#pragma unroll
            for (int k = 0; k < 4; k++) acc[i][j][k] = 0.f;

    for (int kc = 0; kc < 2; kc++) {
        {
            int row = tid & 127, which = tid >> 7;
            const __nv_bfloat16* src =
                (which ? g_w1p_lo : g_w1p_hi) +
                (size_t)(cb * 128 + row) * 128 + kc * 64;
            uint32_t dst = base + (which ? SL_BLO : SL_BHI) + row * 144;
#pragma unroll
            for (int j = 0; j < 8; j++) cp_async16(dst + j * 16, src + j * 8);
            CP_COMMIT();
        }
        {
            int row = tid & 127, which = tid >> 7;
            const __nv_bfloat16* src =
                (which ? g_h_lo : g_h_hi) + (size_t)(n0 + row) * 128 + kc * 64;
            unsigned char* dst = sm + (which ? SL_ALO : SL_AHI) + row * 144;
#pragma unroll
            for (int j = 0; j < 8; j++)
                *(uint4*)(dst + j * 16) = *(const uint4*)(src + j * 8);
        }
        CP_WAIT0();
        __syncthreads();
#pragma unroll
        for (int p = 0; p < 3; p++) {
            uint32_t aw = base + (p == 1 ? SL_ALO : SL_AHI) + (wm * 64 * 72) * 2;
            uint32_t bw = base + (p == 2 ? SL_BLO : SL_BHI) + (wn * 32) * 144;
            mma_chunk<72, 4>(acc, aw, bw, lane);
        }
        __syncthreads();
    }
#pragma unroll
    for (int mt = 0; mt < 4; mt++) {
        int r0 = wm * 64 + mt * 16 + (lane >> 2);
        int n1 = n0 + r0, n2 = n1 + 8;
#pragma unroll
        for (int nt = 0; nt < 4; nt++) {
            int colp = wn * 32 + nt * 8 + 2 * (lane & 3);
            int col = cb * 128 + colp;
            float2 badd = make_float2(0.f, 0.f);
            if (cb >= 2) badd = *(const float2*)(g_bpe + (cb - 2) * 128 + colp);
            if (n1 < N)
                *(float2*)(g_P + (size_t)n1 * 512 + col) =
                    make_float2(acc[mt][nt][0] + badd.x, acc[mt][nt][1] + badd.y);
            if (n2 < N)
                *(float2*)(g_P + (size_t)n2 * 512 + col) =
                    make_float2(acc[mt][nt][2] + badd.x, acc[mt][nt][3] + badd.y);
        }
    }
}

// ---------------------------------------------------------------------------
// K5: hidden = relu(P1[from]+P2[to]+ef@Wpe); aggH[to] += hidden (red.v4)
// ---------------------------------------------------------------------------
__global__ void __launch_bounds__(256)
k_hidden(const int* __restrict__ from_idx, const int* __restrict__ to_idx,
         const float* __restrict__ ef, int E) {
    __shared__ float ef_sm[64 * 16];
    __shared__ int from_sm[64], to_sm[64];
    const int tid = threadIdx.x;
    const int e0 = blockIdx.x * 64;
    const int cg = tid & 63, sub = tid >> 6;

    if (tid < 64) {
        int ed = e0 + tid;
        from_sm[tid] = (ed < E) ? from_idx[ed] : -1;
        to_sm[tid]   = (ed < E) ? to_idx[ed] : 0;
    }
#pragma unroll
    for (int i = 0; i < 4; i++) {
        int idx = tid + 256 * i;
        int ed = e0 + (idx >> 4);
        ef_sm[idx] = (ed < E) ? ef[(size_t)ed * 16 + (idx & 15)] : 0.f;
    }
    float4 w[16];
#pragma unroll
    for (int k = 0; k < 16; k++)
        w[k] = *(const float4*)(g_wpe + k * 256 + cg * 4);
    __syncthreads();

#pragma unroll 2
    for (int i = 0; i < 16; i++) {
        int le = i * 4 + sub;
        int f = from_sm[le];
        if (f < 0) continue;
        int t = to_sm[le];
        const float4 p1 = *(const float4*)(g_P + (size_t)f * 512 + cg * 4);
        const float4 p2 = *(const float4*)(g_P + (size_t)t * 512 + 256 + cg * 4);
        float s0 = p1.x + p2.x, s1 = p1.y + p2.y;
        float s2 = p1.z + p2.z, s3 = p1.w + p2.w;
        const float* er = ef_sm + le * 16;
#pragma unroll
        for (int k = 0; k < 16; k++) {
            float e = er[k];
            s0 = fmaf(e, w[k].x, s0);
            s1 = fmaf(e, w[k].y, s1);
            s2 = fmaf(e, w[k].z, s2);
            s3 = fmaf(e, w[k].w, s3);
        }
        s0 = fmaxf(s0, 0.f); s1 = fmaxf(s1, 0.f);
        s2 = fmaxf(s2, 0.f); s3 = fmaxf(s3, 0.f);
        red4(g_aggH + (size_t)t * 256 + cg * 4, s0, s1, s2, s3);
    }
}

// ---------------------------------------------------------------------------
// K6: node update  h += [h|aggH] @ Wut2 + bu + deg*bc.
//     last!=0: write result to g_flat[pos[n]] instead of g_h/hi/lo.
// ---------------------------------------------------------------------------
__global__ void __launch_bounds__(256, 2)
k_upd2(const float* __restrict__ bu, const int* __restrict__ pos, int last,
       int N) {
    extern __shared__ unsigned char sm[];
    const uint32_t base = smem_to_u32(sm);
    const int tid = threadIdx.x, lane = tid & 31, wid = tid >> 5;
    const int n0 = blockIdx.x * 128;
    const int wm = wid >> 2, wn = wid & 3;
    float acc[4][4][4];
#pragma unroll
    for (int i = 0; i < 4; i++)
#pragma unroll
        for (int j = 0; j < 4; j++)
#pragma unroll
            for (int k = 0; k < 4; k++) acc[i][j][k] = 0.f;

    for (int kc = 0; kc < 6; kc++) {
        {
            int row = tid & 127, which = tid >> 7;
            const __nv_bfloat16* src =
                (which ? g_wut2_lo : g_wut2_hi) + (size_t)row * 384 + kc * 64;
            uint32_t dst = base + (which ? SL_BLO : SL_BHI) + row * 144;
#pragma unroll
            for (int j = 0; j < 8; j++) cp_async16(dst + j * 16, src + j * 8);
            CP_COMMIT();
        }
#pragma unroll 2
        for (int i = 0; i < 8; i++) {
            int idx = tid + 256 * i;
            int row = idx >> 4, q = idx & 15;
            float4 v;
            if (kc < 2)
                v = *(const float4*)(g_h + (size_t)(n0 + row) * 128 +
                                     kc * 64 + q * 4);
            else
                v = *(const float4*)(g_aggH + (size_t)(n0 + row) * 256 +
                                     (kc - 2) * 64 + q * 4);
            __nv_bfloat16 h0 = __float2bfloat16(v.x), h1 = __float2bfloat16(v.y);
            __nv_bfloat16 h2 = __float2bfloat16(v.z), h3 = __float2bfloat16(v.w);
            uint2 hp, lp;
            hp.x = pkbf(v.x, v.y); hp.y = pkbf(v.z, v.w);
            lp.x = pkbf(v.x - __bfloat162float(h0), v.y - __bfloat162float(h1));
            lp.y = pkbf(v.z - __bfloat162float(h2), v.w - __bfloat162float(h3));
            int boff = (row * 72 + q * 4) * 2;
            *(uint2*)(sm + SL_AHI + boff) = hp;
            *(uint2*)(sm + SL_ALO + boff) = lp;
        }
        CP_WAIT0();
        __syncthreads();
#pragma unroll
        for (int p = 0; p < 3; p++) {
            uint32_t aw = base + (p == 1 ? SL_ALO : SL_AHI) + (wm * 64 * 72) * 2;
            uint32_t bw = base + (p == 2 ? SL_BLO : SL_BHI) + (wn * 32) * 144;
            mma_chunk<72, 4>(acc, aw, bw, lane);
        }
        __syncthreads();
    }
#pragma unroll
    for (int mt = 0; mt < 4; mt++) {
        int rr[2];
        rr[0] = wm * 64 + mt * 16 + (lane >> 2);
        rr[1] = rr[0] + 8;
#pragma unroll
        for (int nt = 0; nt < 4; nt++) {
            int col = wn * 32 + nt * 8 + 2 * (lane & 3);
            float2 bb = *(const float2*)(bu + col);
            float2 bc2 = *(const float2*)(g_bc + col);
#pragma unroll
            for (int h = 0; h < 2; h++) {
                int n = n0 + rr[h];
                if (n < N) {
                    float degf = (float)g_deg[n];
                    int pn = last ? pos[n] : 0;
#pragma unroll
                    for (int z = 0; z < 2; z++) {
                        float v = g_h[(size_t)n * 128 + col + z] +
                                  acc[mt][nt][2 * h + z] + (z ? bb.y : bb.x) +
                                  degf * (z ? bc2.y : bc2.x);
                        if (last) {
                            g_flat[(size_t)pn * 128 + col + z] = v;
                        } else {
                            g_h[(size_t)n * 128 + col + z] = v;
                            __nv_bfloat16 hi = __float2bfloat16(v);
                            g_h_hi[(size_t)n * 128 + col + z] = hi;
                            g_h_lo[(size_t)n * 128 + col + z] =
                                __float2bfloat16(v - __bfloat162float(hi));
                        }
                    }
                }
            }
        }
    }
}

// ---------------------------------------------------------------------------
// K8: attention features via MMA
// ---------------------------------------------------------------------------
#define AT_HIDHI 0
#define AT_HIDLO 34816
#define AT_B2HI  73728
#define AT_B2LO  92160
#define AT_SMEM  110592
__global__ void __launch_bounds__(256, 2)
k_att2(const float* __restrict__ ba1, const float* __restrict__ ba2,
       const int* __restrict__ qsz, const int* __restrict__ csz) {
    extern __shared__ unsigned char sm[];
    const uint32_t base = smem_to_u32(sm);
    const int tid = threadIdx.x, lane = tid & 31, wid = tid >> 5;
    const int r0 = blockIdx.x * 128;
    const int wm = wid >> 2, wn = wid & 3;
    float acc[4][4][4];
#pragma unroll
    for (int i = 0; i < 4; i++)
#pragma unroll
        for (int j = 0; j < 4; j++)
#pragma unroll
            for (int k = 0; k < 4; k++) acc[i][j][k] = 0.f;

    for (int kc = 0; kc < 2; kc++) {
        {
            int row = tid & 127, which = tid >> 7;
            const __nv_bfloat16* src =
                (which ? g_wa1t_lo : g_wa1t_hi) + (size_t)row * 128 + kc * 64;
            uint32_t dst = base + (which ? AT_B2LO : AT_B2HI) + row * 144;
#pragma unroll
            for (int j = 0; j < 8; j++) cp_async16(dst + j * 16, src + j * 8);
            CP_COMMIT();
        }
#pragma unroll 2
        for (int i = 0; i < 8; i++) {
            int idx = tid + 256 * i;
            int row = idx >> 4, q = idx & 15;
            float4 v = *(const float4*)(g_flat + (size_t)(r0 + row) * 128 +
                                        kc * 64 + q * 4);
            __nv_bfloat16 h0 = __float2bfloat16(v.x), h1 = __float2bfloat16(v.y);
            __nv_bfloat16 h2 = __float2bfloat16(v.z), h3 = __float2bfloat16(v.w);
            uint2 hp, lp;
            hp.x = pkbf(v.x, v.y); hp.y = pkbf(v.z, v.w);
            lp.x = pkbf(v.x - __bfloat162float(h0), v.y - __bfloat162float(h1));
            lp.y = pkbf(v.z - __bfloat162float(h2), v.w - __bfloat162float(h3));
            int boff = (row * 72 + q * 4) * 2;
            *(uint2*)(sm + SL_AHI + boff) = hp;
            *(uint2*)(sm + SL_ALO + boff) = lp;
        }
        CP_WAIT0();
        __syncthreads();
#pragma unroll
        for (int p = 0; p < 3; p++) {
            uint32_t aw = base + (p == 1 ? SL_ALO : SL_AHI) + (wm * 64 * 72) * 2;
            uint32_t bw = base + (p == 2 ? AT_B2LO : AT_B2HI) + (wn * 32) * 144;
            mma_chunk<72, 4>(acc, aw, bw, lane);
        }
        __syncthreads();
    }
#pragma unroll
    for (int mt = 0; mt < 4; mt++) {
        int rr0 = wm * 64 + mt * 16 + (lane >> 2);
#pragma unroll
        for (int nt = 0; nt < 4; nt++) {
            int col = wn * 32 + nt * 8 + 2 * (lane & 3);
            float2 bb = *(const float2*)(ba1 + col);
#pragma unroll
            for (int h = 0; h < 2; h++) {
                int row = rr0 + h * 8;
                float v0 = fmaxf(acc[mt][nt][2 * h]     + bb.x, 0.f);
                float v1 = fmaxf(acc[mt][nt][2 * h + 1] + bb.y, 0.f);
                __nv_bfloat16 b0 = __float2bfloat16(v0), b1 = __float2bfloat16(v1);
                int boff = (row * 136 + col) * 2;
                *(uint32_t*)(sm + AT_HIDHI + boff) = pkbf(v0, v1);
                *(uint32_t*)(sm + AT_HIDLO + boff) =
                    pkbf(v0 - __bfloat162float(b0), v1 - __bfloat162float(b1));
            }
            acc[mt][nt][0] = acc[mt][nt][1] = acc[mt][nt][2] = acc[mt][nt][3] = 0.f;
        }
    }
    __syncthreads();
    for (int kc = 0; kc < 2; kc++) {
        {
            int row = tid & 127, which = tid >> 7;
            const __nv_bfloat16* src =
                (which ? g_wa2t_lo : g_wa2t_hi) + (size_t)row * 128 + kc * 64;
            uint32_t dst = base + (which ? AT_B2LO : AT_B2HI) + row * 144;
#pragma unroll
            for (int j = 0; j < 8; j++) cp_async16(dst + j * 16, src + j * 8);
            CP_COMMIT();
        }
        CP_WAIT0();
        __syncthreads();
#pragma unroll
        for (int p = 0; p < 3; p++) {
            uint32_t aw = base + (p == 1 ? AT_HIDLO : AT_HIDHI) +
                          (wm * 64 * 136 + kc * 64) * 2;
            uint32_t bw = base + (p == 2 ? AT_B2LO : AT_B2HI) + (wn * 32) * 144;
            mma_chunk<136, 4>(acc, aw, bw, lane);
        }
        __syncthreads();
    }
#pragma unroll
    for (int mt = 0; mt < 4; mt++) {
        int rr0 = wm * 64 + mt * 16 + (lane >> 2);
#pragma unroll
        for (int nt = 0; nt < 4; nt++) {
            int col = wn * 32 + nt * 8 + 2 * (lane & 3);
            float2 bb = *(const float2*)(ba2 + col);
#pragma unroll
            for (int h = 0; h < 2; h++) {
                int row = r0 + rr0 + h * 8;
                int gi = row >> 6, q = row & 63;
                int size = (gi < 256) ? qsz[gi] : csz[gi - 256];
                bool ok = q < size;
                float v0 = ok ? acc[mt][nt][2 * h]     + bb.x : 0.f;
                float v1 = ok ? acc[mt][nt][2 * h + 1] + bb.y : 0.f;
                *(float2*)(g_t + (size_t)row * 128 + col) = make_float2(v0, v1);
            }
        }
    }
}

// ---------------------------------------------------------------------------
// K9: per-pair logits, dual softmax, hinge alignment, min
// ---------------------------------------------------------------------------
#define PAIR_SMEM ((2 * 64 * 129 + 3 * 64 * 65) * 4)
__global__ void __launch_bounds__(256, 1)
k_pair(const int* __restrict__ qsz, const int* __restrict__ csz,
       float* __restrict__ out) {
    extern __shared__ float smf[];
    float* bufA = smf;
    float* bufB = bufA + 64 * 129;
    float* L    = bufB + 64 * 129;
    float* pq   = L + 64 * 65;
    float* pc   = pq + 64 * 65;
    __shared__ float redq[8], redc[8];

    const int b = blockIdx.x, tid = threadIdx.x;
    const int qs = qsz[b], cs = csz[b];
    const int qbase = b * 64, cbase = 16384 + b * 64;

    for (int idx = tid; idx < 64 * 128; idx += 256) {
        int r = idx >> 7, k = idx & 127;
        bufA[r * 129 + k] = g_t[(qbase + r) * 128 + k];
        bufB[r * 129 + k] = g_t[(cbase + r) * 128 + k];
    }
    __syncthreads();
    {
        int q = tid >> 2, cg = tid & 3;
        float acc[16];
#pragma unroll
        for (int j = 0; j < 16; j++) acc[j] = 0.f;
        for (int k = 0; k < 128; k++) {
            float a = bufA[q * 129 + k];
            const float* bp = bufB + (cg * 16) * 129 + k;
#pragma unroll
            for (int j = 0; j < 16; j++) acc[j] += a * bp[j * 129];
        }
        bool qv = q < qs;
#pragma unroll
        for (int j = 0; j < 16; j++) {
            int c = cg * 16 + j;
            L[q * 65 + c] = (qv && c < cs) ? acc[j] * 10.0f : -1e9f;
        }
    }
    __syncthreads();
    for (int idx = tid; idx < 64 * 128; idx += 256) {
        int r = idx >> 7, k = idx & 127;
        bufA[r * 129 + k] = g_flat[(qbase + r) * 128 + k];
        bufB[r * 129 + k] = g_flat[(cbase + r) * 128 + k];
    }
    if (tid < 64) {
        float m = -1e30f;
        for (int c = 0; c < 64; c++) m = fmaxf(m, L[tid * 65 + c]);
        float s = 0.f;
        for (int c = 0; c < 64; c++) {
            float ex = __expf(L[tid * 65 + c] - m);
            s += ex;
            pq[tid * 65 + c] = ex;
        }
        float inv = (tid < qs) ? (1.0f / s) : 0.f;
        for (int c = 0; c < 64; c++) pq[tid * 65 + c] *= inv;
    } else if (tid < 128) {
        int c = tid - 64;
        float m = -1e30f;
        for (int q = 0; q < 64; q++) m = fmaxf(m, L[q * 65 + c]);
        float s = 0.f;
        for (int q = 0; q < 64; q++) {
            float ex = __expf(L[q * 65 + c] - m);
            s += ex;
            pc[q * 65 + c] = ex;
        }
        float inv = (c < cs) ? (1.0f / s) : 0.f;
        for (int q = 0; q < 64; q++) pc[q * 65 + c] *= inv;
    }
    __syncthreads();
    float lq = 0.f, lc = 0.f;
    {
        const int d = tid & 127, gg = tid >> 7;
        float acc[32];
#pragma unroll
        for (int j = 0; j < 32; j++) acc[j] = 0.f;
        for (int c = 0; c < 64; c++) {
            float bb = bufB[c * 129 + d];
            const float* pp = pq + (gg * 32) * 65 + c;
#pragma unroll
            for (int j = 0; j < 32; j++) acc[j] += pp[j * 65] * bb;
        }
#pragma unroll
        for (int j = 0; j < 32; j++) {
            int q = gg * 32 + j;
            lq += fmaxf(bufA[q * 129 + d] - acc[j], 0.f);
        }
#pragma unroll
        for (int j = 0; j < 32; j++) acc[j] = 0.f;
        for (int q = 0; q < 64; q++) {
            float aa = bufA[q * 129 + d];
            const float* pp = pc + q * 65 + gg * 32;
#pragma unroll
            for (int j = 0; j < 32; j++) acc[j] += pp[j] * aa;
        }
#pragma unroll
        for (int j = 0; j < 32; j++) {
            int c = gg * 32 + j;
            lc += fmaxf(bufB[c * 129 + d] - acc[j], 0.f);
        }
    }
    for (int o = 16; o; o >>= 1) {
        lq += __shfl_down_sync(0xffffffffu, lq, o);
        lc += __shfl_down_sync(0xffffffffu, lc, o);
    }
    int w = tid >> 5, lane = tid & 31;
    if (lane == 0) { redq[w] = lq; redc[w] = lc; }
    __syncthreads();
    if (tid == 0) {
        float sq = 0.f, sc = 0.f;
        for (int i = 0; i < 8; i++) { sq += redq[i]; sc += redc[i]; }
        out[b] = fminf(-sq, -sc);
    }
}

// ---------------------------------------------------------------------------
extern "C" void kernel_launch(void* const* d_in, const int* in_sizes, int n_in,
                              void* d_out, int out_size) {
    const float* nf       = (const float*)d_in[0];
    const float* ef       = (const float*)d_in[1];
    const int*   from_idx = (const int*)d_in[2];
    const int*   to_idx   = (const int*)d_in[3];
    const int*   pos      = (const int*)d_in[4];
    const int*   qsz      = (const int*)d_in[5];
    const int*   csz      = (const int*)d_in[6];
    const float* W_node = (const float*)d_in[7];
    const float* b_node = (const float*)d_in[8];
    const float* W_edge = (const float*)d_in[9];
    const float* b_edge = (const float*)d_in[10];
    const float* W_msg1 = (const float*)d_in[11];
    const float* b_msg1 = (const float*)d_in[12];
    const float* W_msg2 = (const float*)d_in[13];
    const float* b_msg2 = (const float*)d_in[14];
    const float* W_upd  = (const float*)d_in[15];
    const float* b_upd  = (const float*)d_in[16];
    const float* Wa1    = (const float*)d_in[17];
    const float* ba1    = (const float*)d_in[18];
    const float* Wa2    = (const float*)d_in[19];
    const float* ba2    = (const float*)d_in[20];

    const int N = in_sizes[0] / 32;
    const int E = in_sizes[1] / 16;

    cudaFuncSetAttribute(k_nodeprod, cudaFuncAttributeMaxDynamicSharedMemorySize, SL_END);
    cudaFuncSetAttribute(k_upd2,     cudaFuncAttributeMaxDynamicSharedMemorySize, SL_END);
    cudaFuncSetAttribute(k_att2,     cudaFuncAttributeMaxDynamicSharedMemorySize, AT_SMEM);
    cudaFuncSetAttribute(k_pair,     cudaFuncAttributeMaxDynamicSharedMemorySize, PAIR_SMEM);

    void* degp = nullptr;
    cudaGetSymbolAddress(&degp, g_deg);

    const int egrid = (E + 63) / 64;
    const int ngrid = (N + 127) / 128;

    k_prep<<<384, 256>>>(W_msg1, Wa1, Wa2);
    k_wcpe<<<144, 256>>>(W_msg2, W_upd, W_edge, W_msg1);
    k_pack<<<194, 256>>>(W_upd, b_msg2, W_msg1, b_msg1, b_edge);
    cudaMemsetAsync(degp, 0, (size_t)N * sizeof(int));
    k_deg<<<(E + 255) / 256, 256>>>(to_idx, E);
    k_enc_node<<<(N + 15) / 16, 256>>>(nf, W_node, b_node, N);

    for (int s = 0; s < 3; s++) {
        k_nodeprod<<<ngrid * 4, 256, SL_END>>>(N);
        k_hidden<<<egrid, 256>>>(from_idx, to_idx, ef, E);
        k_upd2<<<ngrid, 256, SL_END>>>(b_upd, pos, s == 2 ? 1 : 0, N);
    }

    k_att2<<<256, 256, AT_SMEM>>>(ba1, ba2, qsz, csz);
    k_pair<<<256, 256, PAIR_SMEM>>>(qsz, csz, (float*)d_out);
}

// round 8
// speedup vs baseline: 9.0898x; 1.0168x over previous
#include <cuda_runtime.h>
#include <cuda_bf16.h>
#include <cstdint>

#define NMAX 32768
#define EMAX 262144

// Scratch
__device__ float g_h   [NMAX * 128];
__device__ float g_aggH[NMAX * 256];
__device__ float g_flat[2 * 256 * 64 * 128];   // layout: pair*128 + (q | 64+c)
__device__ float g_P   [NMAX * 512];
__device__ float g_wc  [256 * 128];
__device__ float g_bc  [128];
__device__ float g_wpe [16 * 256];
__device__ float g_bpe [256];
__device__ int   g_deg [NMAX];
__device__ __align__(16) __nv_bfloat16 g_h_hi[NMAX * 128];
__device__ __align__(16) __nv_bfloat16 g_h_lo[NMAX * 128];
__device__ __align__(16) __nv_bfloat16 g_w1p_hi[512 * 128], g_w1p_lo[512 * 128];
__device__ __align__(16) __nv_bfloat16 g_wut2_hi[128 * 384], g_wut2_lo[128 * 384];
__device__ __align__(16) __nv_bfloat16 g_wa1t_hi[128 * 128], g_wa1t_lo[128 * 128];
__device__ __align__(16) __nv_bfloat16 g_wa2t_hi[128 * 128], g_wa2t_lo[128 * 128];

// ---------------------------------------------------------------------------
// helpers
// ---------------------------------------------------------------------------
__device__ __forceinline__ uint32_t smem_to_u32(const void* p) {
    uint32_t a;
    asm("{ .reg .u64 t; cvta.to.shared.u64 t, %1; cvt.u32.u64 %0, t; }"
        : "=r"(a) : "l"(p));
    return a;
}
__device__ __forceinline__ void ldsm_x4(uint32_t r[4], uint32_t addr) {
    asm volatile("ldmatrix.sync.aligned.m8n8.x4.shared.b16 {%0,%1,%2,%3}, [%4];"
                 : "=r"(r[0]), "=r"(r[1]), "=r"(r[2]), "=r"(r[3]) : "r"(addr));
}
__device__ __forceinline__ void mma_bf16(float c[4], const uint32_t a[4],
                                         uint32_t b0, uint32_t b1) {
    asm volatile(
        "mma.sync.aligned.m16n8k16.row.col.f32.bf16.bf16.f32 "
        "{%0,%1,%2,%3}, {%4,%5,%6,%7}, {%8,%9}, {%0,%1,%2,%3};"
        : "+f"(c[0]), "+f"(c[1]), "+f"(c[2]), "+f"(c[3])
        : "r"(a[0]), "r"(a[1]), "r"(a[2]), "r"(a[3]), "r"(b0), "r"(b1));
}
__device__ __forceinline__ void cp_async16(uint32_t smem, const void* g) {
    asm volatile("cp.async.ca.shared.global [%0], [%1], 16;"
                 :: "r"(smem), "l"(g));
}
#define CP_COMMIT() asm volatile("cp.async.commit_group;" ::: "memory")
#define CP_WAIT0()  asm volatile("cp.async.wait_group 0;" ::: "memory")

__device__ __forceinline__ uint32_t pkbf(float a, float b) {
    __nv_bfloat162 t = __floats2bfloat162_rn(a, b);
    return *reinterpret_cast<uint32_t*>(&t);
}
__device__ __forceinline__ void red4(float* addr, float x, float y, float z,
                                     float w) {
    asm volatile("red.global.add.v4.f32 [%0], {%1, %2, %3, %4};"
                 :: "l"(addr), "f"(x), "f"(y), "f"(z), "f"(w) : "memory");
}

template <int SA, int NT>
__device__ __forceinline__ void mma_chunk(float (&acc)[4][NT][4],
                                          uint32_t aw, uint32_t bw, int lane) {
    const int arow = lane & 15, ak = (lane >> 4) << 3;
    const int brow = (lane & 7) + ((lane >> 4) << 3);
    const int bk = ((lane >> 3) & 1) << 3;
#pragma unroll
    for (int kt = 0; kt < 4; kt++) {
        uint32_t a[4][4], b[NT / 2][4];
#pragma unroll
        for (int mt = 0; mt < 4; mt++)
            ldsm_x4(a[mt], aw + ((mt * 16 + arow) * SA + kt * 16 + ak) * 2);
#pragma unroll
        for (int nb = 0; nb < NT / 2; nb++)
            ldsm_x4(b[nb], bw + ((nb * 16 + brow) * 72 + kt * 16 + bk) * 2);
#pragma unroll
        for (int mt = 0; mt < 4; mt++)
#pragma unroll
            for (int nb = 0; nb < NT / 2; nb++) {
                mma_bf16(acc[mt][2 * nb],     a[mt], b[nb][0], b[nb][1]);
                mma_bf16(acc[mt][2 * nb + 1], a[mt], b[nb][2], b[nb][3]);
            }
    }
}

#define SL_AHI 0
#define SL_ALO 18432
#define SL_BHI 36864
#define SL_BLO 55296
#define SL_END 73728

// ---------------------------------------------------------------------------
// K0a: weight transpose + hi/lo split (w1p, wa1t, wa2t)
// ---------------------------------------------------------------------------
__global__ void k_prep(const float* __restrict__ W1, const float* __restrict__ Wa1,
                       const float* __restrict__ Wa2) {
    int idx = blockIdx.x * 256 + threadIdx.x;
    float v;
    __nv_bfloat16 *dh, *dl;
    int off;
    if (idx < 65536) {
        int n = idx >> 7, k = idx & 127;
        v = (n < 256) ? W1[k * 256 + n] : W1[(128 + k) * 256 + (n - 256)];
        dh = g_w1p_hi; dl = g_w1p_lo; off = idx;
    } else if (idx < 81920) {
        int i = idx - 65536;
        int n = i >> 7, k = i & 127;
        v = Wa1[k * 128 + n];
        dh = g_wa1t_hi; dl = g_wa1t_lo; off = i;
    } else {
        int i = idx - 81920;
        if (i >= 16384) return;
        int n = i >> 7, k = i & 127;
        v = Wa2[k * 128 + n];
        dh = g_wa2t_hi; dl = g_wa2t_lo; off = i;
    }
    __nv_bfloat16 hi = __float2bfloat16(v);
    dh[off] = hi;
    dl[off] = __float2bfloat16(v - __bfloat162float(hi));
}

// K0b: fused Wc + Wpe
__global__ void k_wcpe(const float* __restrict__ W2, const float* __restrict__ Wu,
                       const float* __restrict__ We, const float* __restrict__ W1) {
    int bid = blockIdx.x, tid = threadIdx.x;
    if (bid < 128) {
        int k = bid * 2 + (tid >> 7), c = tid & 127;
        __shared__ float w2row[2][256];
        w2row[tid >> 7][c] = W2[k * 256 + c];
        w2row[tid >> 7][c + 128] = W2[k * 256 + c + 128];
        __syncthreads();
        float s = 0.f;
        const float* wr = w2row[tid >> 7];
#pragma unroll 4
        for (int j = 0; j < 256; j++) s += wr[j] * Wu[(128 + j) * 128 + c];
        g_wc[k * 128 + c] = s;
    } else {
        int k = bid - 128, c = tid;
        __shared__ float wrow[64];
        if (tid < 64) wrow[tid] = We[k * 64 + tid];
        __syncthreads();
        float s = 0.f;
#pragma unroll 4
        for (int j = 0; j < 64; j++) s += wrow[j] * W1[(256 + j) * 256 + c];
        g_wpe[k * 256 + c] = s;
    }
}

// K0c: pack wut2 + bc + bpe
__global__ void k_pack(const float* __restrict__ Wu, const float* __restrict__ b2,
                       const float* __restrict__ W1, const float* __restrict__ b1,
                       const float* __restrict__ be) {
    int idx = blockIdx.x * 256 + threadIdx.x;
    if (idx < 49152) {
        int n = idx & 127, k = idx >> 7;
        float v = (k < 128) ? Wu[k * 128 + n] : g_wc[(k - 128) * 128 + n];
        __nv_bfloat16 hi = __float2bfloat16(v);
        int off = n * 384 + k;
        g_wut2_hi[off] = hi;
        g_wut2_lo[off] = __float2bfloat16(v - __bfloat162float(hi));
    } else if (idx < 49280) {
        int c = idx - 49152;
        float s = 0.f;
#pragma unroll 4
        for (int j = 0; j < 256; j++) s += b2[j] * Wu[(128 + j) * 128 + c];
        g_bc[c] = s;
    } else if (idx < 49536) {
        int c = idx - 49280;
        float s = b1[c];
#pragma unroll 4
        for (int j = 0; j < 64; j++) s += be[j] * W1[(256 + j) * 256 + c];
        g_bpe[c] = s;
    }
}

__global__ void k_deg(const int* __restrict__ to_idx, int E) {
    int i = blockIdx.x * 256 + threadIdx.x;
    if (i < E) atomicAdd(&g_deg[to_idx[i]], 1);
}

// ---------------------------------------------------------------------------
// K1: node encoder, tiled
// ---------------------------------------------------------------------------
__global__ void __launch_bounds__(256)
k_enc_node(const float* __restrict__ nf, const float* __restrict__ Wn,
           const float* __restrict__ bn, int N) {
    __shared__ float Ws[32 * 128];
    __shared__ float nfs[16 * 32];
    __shared__ float bns[128];
    const int tid = threadIdx.x;
    const int n0 = blockIdx.x * 16;
#pragma unroll
    for (int i = 0; i < 16; i++) Ws[tid + 256 * i] = Wn[tid + 256 * i];
    if (tid < 128) bns[tid] = bn[tid];
#pragma unroll
    for (int i = 0; i < 2; i++) {
        int idx = tid + 256 * i;
        int node = idx >> 5, k = idx & 31;
        int n = n0 + node;
        nfs[idx] = (n < N) ? nf[(size_t)n * 32 + k] : 0.f;
    }
    __syncthreads();
#pragma unroll
    for (int i = 0; i < 8; i++) {
        int o = tid + 256 * i;
        int node = o >> 7, c = o & 127;
        int n = n0 + node;
        if (n >= N) continue;
        float s = bns[c];
        const float* nr = nfs + node * 32;
#pragma unroll
        for (int k = 0; k < 32; k++) s = fmaf(nr[k], Ws[k * 128 + c], s);
        size_t gi = (size_t)n * 128 + c;
        g_h[gi] = s;
        __nv_bfloat16 hi = __float2bfloat16(s);
        g_h_hi[gi] = hi;
        g_h_lo[gi] = __float2bfloat16(s - __bfloat162float(hi));
    }
}

// ---------------------------------------------------------------------------
// K4: P12 = h @ [W1_top|W1_mid] (+bpe on P2 half); cb<2 also zero aggH half.
// ---------------------------------------------------------------------------
__global__ void __launch_bounds__(256, 2)
k_nodeprod(int N) {
    extern __shared__ unsigned char sm[];
    const uint32_t base = smem_to_u32(sm);
    const int tid = threadIdx.x, lane = tid & 31, wid = tid >> 5;
    const int cb = blockIdx.x & 3, rb = blockIdx.x >> 2;
    const int n0 = rb * 128;
    const int wm = wid >> 2, wn = wid & 3;

    if (cb < 2) {
        const float4 z = make_float4(0.f, 0.f, 0.f, 0.f);
#pragma unroll
        for (int i = 0; i < 16; i++) {
            int idx = tid + 256 * i;
            int row = idx >> 5, q = idx & 31;
            int n = n0 + row;
            if (n < N)
                *(float4*)(g_aggH + (size_t)n * 256 + cb * 128 + q * 4) = z;
        }
    }

    float acc[4][4][4];
#pragma unroll
    for (int i = 0; i < 4; i++)
#pragma unroll
        for (int j = 0; j < 4; j++)
#pragma unroll
            for (int k = 0; k < 4; k++) acc[i][j][k] = 0.f;

    for (int kc = 0; kc < 2; kc++) {
        {
            int row = tid & 127, which = tid >> 7;
            const __nv_bfloat16* src =
                (which ? g_w1p_lo : g_w1p_hi) +
                (size_t)(cb * 128 + row) * 128 + kc * 64;
            uint32_t dst = base + (which ? SL_BLO : SL_BHI) + row * 144;
#pragma unroll
            for (int j = 0; j < 8; j++) cp_async16(dst + j * 16, src + j * 8);
            CP_COMMIT();
        }
        {
            int row = tid & 127, which = tid >> 7;
            const __nv_bfloat16* src =
                (which ? g_h_lo : g_h_hi) + (size_t)(n0 + row) * 128 + kc * 64;
            unsigned char* dst = sm + (which ? SL_ALO : SL_AHI) + row * 144;
#pragma unroll
            for (int j = 0; j < 8; j++)
                *(uint4*)(dst + j * 16) = *(const uint4*)(src + j * 8);
        }
        CP_WAIT0();
        __syncthreads();
#pragma unroll
        for (int p = 0; p < 3; p++) {
            uint32_t aw = base + (p == 1 ? SL_ALO : SL_AHI) + (wm * 64 * 72) * 2;
            uint32_t bw = base + (p == 2 ? SL_BLO : SL_BHI) + (wn * 32) * 144;
            mma_chunk<72, 4>(acc, aw, bw, lane);
        }
        __syncthreads();
    }
#pragma unroll
    for (int mt = 0; mt < 4; mt++) {
        int r0 = wm * 64 + mt * 16 + (lane >> 2);
        int n1 = n0 + r0, n2 = n1 + 8;
#pragma unroll
        for (int nt = 0; nt < 4; nt++) {
            int colp = wn * 32 + nt * 8 + 2 * (lane & 3);
            int col = cb * 128 + colp;
            float2 badd = make_float2(0.f, 0.f);
            if (cb >= 2) badd = *(const float2*)(g_bpe + (cb - 2) * 128 + colp);
            if (n1 < N)
                *(float2*)(g_P + (size_t)n1 * 512 + col) =
                    make_float2(acc[mt][nt][0] + badd.x, acc[mt][nt][1] + badd.y);
            if (n2 < N)
                *(float2*)(g_P + (size_t)n2 * 512 + col) =
                    make_float2(acc[mt][nt][2] + badd.x, acc[mt][nt][3] + badd.y);
        }
    }
}

// ---------------------------------------------------------------------------
// K5: hidden = relu(P1[from]+P2[to]+ef@Wpe); aggH[to] += hidden (red.v4)
// ---------------------------------------------------------------------------
__global__ void __launch_bounds__(256)
k_hidden(const int* __restrict__ from_idx, const int* __restrict__ to_idx,
         const float* __restrict__ ef, int E) {
    __shared__ float ef_sm[64 * 16];
    __shared__ int from_sm[64], to_sm[64];
    const int tid = threadIdx.x;
    const int e0 = blockIdx.x * 64;
    const int cg = tid & 63, sub = tid >> 6;

    if (tid < 64) {
        int ed = e0 + tid;
        from_sm[tid] = (ed < E) ? from_idx[ed] : -1;
        to_sm[tid]   = (ed < E) ? to_idx[ed] : 0;
    }
#pragma unroll
    for (int i = 0; i < 4; i++) {
        int idx = tid + 256 * i;
        int ed = e0 + (idx >> 4);
        ef_sm[idx] = (ed < E) ? ef[(size_t)ed * 16 + (idx & 15)] : 0.f;
    }
    float4 w[16];
#pragma unroll
    for (int k = 0; k < 16; k++)
        w[k] = *(const float4*)(g_wpe + k * 256 + cg * 4);
    __syncthreads();

#pragma unroll 2
    for (int i = 0; i < 16; i++) {
        int le = i * 4 + sub;
        int f = from_sm[le];
        if (f < 0) continue;
        int t = to_sm[le];
        const float4 p1 = *(const float4*)(g_P + (size_t)f * 512 + cg * 4);
        const float4 p2 = *(const float4*)(g_P + (size_t)t * 512 + 256 + cg * 4);
        float s0 = p1.x + p2.x, s1 = p1.y + p2.y;
        float s2 = p1.z + p2.z, s3 = p1.w + p2.w;
        const float* er = ef_sm + le * 16;
#pragma unroll
        for (int k = 0; k < 16; k++) {
            float e = er[k];
            s0 = fmaf(e, w[k].x, s0);
            s1 = fmaf(e, w[k].y, s1);
            s2 = fmaf(e, w[k].z, s2);
            s3 = fmaf(e, w[k].w, s3);
        }
        s0 = fmaxf(s0, 0.f); s1 = fmaxf(s1, 0.f);
        s2 = fmaxf(s2, 0.f); s3 = fmaxf(s3, 0.f);
        red4(g_aggH + (size_t)t * 256 + cg * 4, s0, s1, s2, s3);
    }
}

// ---------------------------------------------------------------------------
// K6: node update.  last!=0: write to g_flat at REMAPPED slot
//     (pair*128 + q for query, pair*128 + 64 + c for corpus).
// ---------------------------------------------------------------------------
__global__ void __launch_bounds__(256, 2)
k_upd2(const float* __restrict__ bu, const int* __restrict__ pos, int last,
       int N) {
    extern __shared__ unsigned char sm[];
    const uint32_t base = smem_to_u32(sm);
    const int tid = threadIdx.x, lane = tid & 31, wid = tid >> 5;
    const int n0 = blockIdx.x * 128;
    const int wm = wid >> 2, wn = wid & 3;
    float acc[4][4][4];
#pragma unroll
    for (int i = 0; i < 4; i++)
#pragma unroll
        for (int j = 0; j < 4; j++)
#pragma unroll
            for (int k = 0; k < 4; k++) acc[i][j][k] = 0.f;

    for (int kc = 0; kc < 6; kc++) {
        {
            int row = tid & 127, which = tid >> 7;
            const __nv_bfloat16* src =
                (which ? g_wut2_lo : g_wut2_hi) + (size_t)row * 384 + kc * 64;
            uint32_t dst = base + (which ? SL_BLO : SL_BHI) + row * 144;
#pragma unroll
            for (int j = 0; j < 8; j++) cp_async16(dst + j * 16, src + j * 8);
            CP_COMMIT();
        }
#pragma unroll 2
        for (int i = 0; i < 8; i++) {
            int idx = tid + 256 * i;
            int row = idx >> 4, q = idx & 15;
            float4 v;
            if (kc < 2)
                v = *(const float4*)(g_h + (size_t)(n0 + row) * 128 +
                                     kc * 64 + q * 4);
            else
                v = *(const float4*)(g_aggH + (size_t)(n0 + row) * 256 +
                                     (kc - 2) * 64 + q * 4);
            __nv_bfloat16 h0 = __float2bfloat16(v.x), h1 = __float2bfloat16(v.y);
            __nv_bfloat16 h2 = __float2bfloat16(v.z), h3 = __float2bfloat16(v.w);
            uint2 hp, lp;
            hp.x = pkbf(v.x, v.y); hp.y = pkbf(v.z, v.w);
            lp.x = pkbf(v.x - __bfloat162float(h0), v.y - __bfloat162float(h1));
            lp.y = pkbf(v.z - __bfloat162float(h2), v.w - __bfloat162float(h3));
            int boff = (row * 72 + q * 4) * 2;
            *(uint2*)(sm + SL_AHI + boff) = hp;
            *(uint2*)(sm + SL_ALO + boff) = lp;
        }
        CP_WAIT0();
        __syncthreads();
#pragma unroll
        for (int p = 0; p < 3; p++) {
            uint32_t aw = base + (p == 1 ? SL_ALO : SL_AHI) + (wm * 64 * 72) * 2;
            uint32_t bw = base + (p == 2 ? SL_BLO : SL_BHI) + (wn * 32) * 144;
            mma_chunk<72, 4>(acc, aw, bw, lane);
        }
        __syncthreads();
    }
#pragma unroll
    for (int mt = 0; mt < 4; mt++) {
        int rr[2];
        rr[0] = wm * 64 + mt * 16 + (lane >> 2);
        rr[1] = rr[0] + 8;
#pragma unroll
        for (int nt = 0; nt < 4; nt++) {
            int col = wn * 32 + nt * 8 + 2 * (lane & 3);
            float2 bb = *(const float2*)(bu + col);
            float2 bc2 = *(const float2*)(g_bc + col);
#pragma unroll
            for (int h = 0; h < 2; h++) {
                int n = n0 + rr[h];
                if (n < N) {
                    float degf = (float)g_deg[n];
                    int pn = 0;
                    if (last) {
                        int slot = pos[n];
                        pn = (slot < 16384)
                                 ? ((slot >> 6) * 128 + (slot & 63))
                                 : (((slot - 16384) >> 6) * 128 + 64 + (slot & 63));
                    }
#pragma unroll
                    for (int z = 0; z < 2; z++) {
                        float v = g_h[(size_t)n * 128 + col + z] +
                                  acc[mt][nt][2 * h + z] + (z ? bb.y : bb.x) +
                                  degf * (z ? bc2.y : bc2.x);
                        if (last) {
                            g_flat[(size_t)pn * 128 + col + z] = v;
                        } else {
                            g_h[(size_t)n * 128 + col + z] = v;
                            __nv_bfloat16 hi = __float2bfloat16(v);
                            g_h_hi[(size_t)n * 128 + col + z] = hi;
                            g_h_lo[(size_t)n * 128 + col + z] =
                                __float2bfloat16(v - __bfloat162float(hi));
                        }
                    }
                }
            }
        }
    }
}

// ---------------------------------------------------------------------------
// K8: fused attention features + pair scoring.  Block b owns pair b
//     (g_flat rows b*128 .. b*128+127: 64 query then 64 corpus rows).
// ---------------------------------------------------------------------------
#define AP_HIDHI 0
#define AP_HIDLO 34816
#define AP_B2HI  73728
#define AP_B2LO  92160
#define AP_BUFA  0
#define AP_BUFB  33024
#define AP_L     66048
#define AP_PC    82688
#define AP_SMEM  110592
__global__ void __launch_bounds__(256, 2)
k_attpair(const float* __restrict__ ba1, const float* __restrict__ ba2,
          const int* __restrict__ qsz, const int* __restrict__ csz,
          float* __restrict__ out) {
    extern __shared__ unsigned char sm[];
    const uint32_t base = smem_to_u32(sm);
    const int tid = threadIdx.x, lane = tid & 31, wid = tid >> 5;
    const int b = blockIdx.x;
    const int r0 = b * 128;
    const int qs = qsz[b], cs = csz[b];
    const int wm = wid >> 2, wn = wid & 3;
    __shared__ float redq[8], redc[8];

    float acc[4][4][4];
#pragma unroll
    for (int i = 0; i < 4; i++)
#pragma unroll
        for (int j = 0; j < 4; j++)
#pragma unroll
            for (int k = 0; k < 4; k++) acc[i][j][k] = 0.f;

    // ---- stage 1: hidden = relu(x @ Wa1 + ba1) ----
    for (int kc = 0; kc < 2; kc++) {
        {
            int row = tid & 127, which = tid >> 7;
            const __nv_bfloat16* src =
                (which ? g_wa1t_lo : g_wa1t_hi) + (size_t)row * 128 + kc * 64;
            uint32_t dst = base + (which ? AP_B2LO : AP_B2HI) + row * 144;
#pragma unroll
            for (int j = 0; j < 8; j++) cp_async16(dst + j * 16, src + j * 8);
            CP_COMMIT();
        }
#pragma unroll 2
        for (int i = 0; i < 8; i++) {
            int idx = tid + 256 * i;
            int row = idx >> 4, q = idx & 15;
            float4 v = *(const float4*)(g_flat + (size_t)(r0 + row) * 128 +
                                        kc * 64 + q * 4);
            __nv_bfloat16 h0 = __float2bfloat16(v.x), h1 = __float2bfloat16(v.y);
            __nv_bfloat16 h2 = __float2bfloat16(v.z), h3 = __float2bfloat16(v.w);
            uint2 hp, lp;
            hp.x = pkbf(v.x, v.y); hp.y = pkbf(v.z, v.w);
            lp.x = pkbf(v.x - __bfloat162float(h0), v.y - __bfloat162float(h1));
            lp.y = pkbf(v.z - __bfloat162float(h2), v.w - __bfloat162float(h3));
            int boff = (row * 72 + q * 4) * 2;
            *(uint2*)(sm + SL_AHI + boff) = hp;
            *(uint2*)(sm + SL_ALO + boff) = lp;
        }
        CP_WAIT0();
        __syncthreads();
#pragma unroll
        for (int p = 0; p < 3; p++) {
            uint32_t aw = base + (p == 1 ? SL_ALO : SL_AHI) + (wm * 64 * 72) * 2;
            uint32_t bw = base + (p == 2 ? AP_B2LO : AP_B2HI) + (wn * 32) * 144;
            mma_chunk<72, 4>(acc, aw, bw, lane);
        }
        __syncthreads();
    }
    // relu+bias -> hidden hi/lo (aliases stage-1 A buffers; stride 136)
#pragma unroll
    for (int mt = 0; mt < 4; mt++) {
        int rr0 = wm * 64 + mt * 16 + (lane >> 2);
#pragma unroll
        for (int nt = 0; nt < 4; nt++) {
            int col = wn * 32 + nt * 8 + 2 * (lane & 3);
            float2 bb = *(const float2*)(ba1 + col);
#pragma unroll
            for (int h = 0; h < 2; h++) {
                int row = rr0 + h * 8;
                float v0 = fmaxf(acc[mt][nt][2 * h]     + bb.x, 0.f);
                float v1 = fmaxf(acc[mt][nt][2 * h + 1] + bb.y, 0.f);
                __nv_bfloat16 b0 = __float2bfloat16(v0), b1 = __float2bfloat16(v1);
                int boff = (row * 136 + col) * 2;
                *(uint32_t*)(sm + AP_HIDHI + boff) = pkbf(v0, v1);
                *(uint32_t*)(sm + AP_HIDLO + boff) =
                    pkbf(v0 - __bfloat162float(b0), v1 - __bfloat162float(b1));
            }
            acc[mt][nt][0] = acc[mt][nt][1] = acc[mt][nt][2] = acc[mt][nt][3] = 0.f;
        }
    }
    __syncthreads();
    // ---- stage 2: t = hidden @ Wa2 + ba2 ----
    for (int kc = 0; kc < 2; kc++) {
        {
            int row = tid & 127, which = tid >> 7;
            const __nv_bfloat16* src =
                (which ? g_wa2t_lo : g_wa2t_hi) + (size_t)row * 128 + kc * 64;
            uint32_t dst = base + (which ? AP_B2LO : AP_B2HI) + row * 144;
#pragma unroll
            for (int j = 0; j < 8; j++) cp_async16(dst + j * 16, src + j * 8);
            CP_COMMIT();
        }
        CP_WAIT0();
        __syncthreads();
#pragma unroll
        for (int p = 0; p < 3; p++) {
            uint32_t aw = base + (p == 1 ? AP_HIDLO : AP_HIDHI) +
                          (wm * 64 * 136 + kc * 64) * 2;
            uint32_t bw = base + (p == 2 ? AP_B2LO : AP_B2HI) + (wn * 32) * 144;
            mma_chunk<136, 4>(acc, aw, bw, lane);
        }
        __syncthreads();
    }
    // masked t -> smem bufA (query) / bufB (corpus); aliases hidden tiles
    float* bufA = (float*)(sm + AP_BUFA);
    float* bufB = (float*)(sm + AP_BUFB);
    float* L    = (float*)(sm + AP_L);
    float* pc   = (float*)(sm + AP_PC);
#pragma unroll
    for (int mt = 0; mt < 4; mt++) {
        int rr0 = wm * 64 + mt * 16 + (lane >> 2);
#pragma unroll
        for (int nt = 0; nt < 4; nt++) {
            int col = wn * 32 + nt * 8 + 2 * (lane & 3);
            float2 bb = *(const float2*)(ba2 + col);
#pragma unroll
            for (int h = 0; h < 2; h++) {
                int row = rr0 + h * 8;
                bool isq = row < 64;
                int q = isq ? row : row - 64;
                bool ok = q < (isq ? qs : cs);
                float v0 = ok ? acc[mt][nt][2 * h]     + bb.x : 0.f;
                float v1 = ok ? acc[mt][nt][2 * h + 1] + bb.y : 0.f;
                float* dst = isq ? bufA : bufB;
                dst[q * 129 + col]     = v0;
                dst[q * 129 + col + 1] = v1;
            }
        }
    }
    __syncthreads();

    // ---- logits: L[q][c] = 10 * dot(tq[q], tc[c]) with pair mask ----
    {
        int q = tid >> 2, cg = tid & 3;
        float la[16];
#pragma unroll
        for (int j = 0; j < 16; j++) la[j] = 0.f;
        for (int k = 0; k < 128; k++) {
            float a = bufA[q * 129 + k];
            const float* bp = bufB + (cg * 16) * 129 + k;
#pragma unroll
            for (int j = 0; j < 16; j++) la[j] += a * bp[j * 129];
        }
        bool qv = q < qs;
#pragma unroll
        for (int j = 0; j < 16; j++) {
            int c = cg * 16 + j;
            L[q * 65 + c] = (qv && c < cs) ? la[j] * 10.0f : -1e9f;
        }
    }
    __syncthreads();

    // reload raw node states into bufA/bufB
    for (int idx = tid; idx < 64 * 128; idx += 256) {
        int r = idx >> 7, k = idx & 127;
        bufA[r * 129 + k] = g_flat[(size_t)(r0 + r) * 128 + k];
        bufB[r * 129 + k] = g_flat[(size_t)(r0 + 64 + r) * 128 + k];
    }
    // col softmax (over query axis) into pc
    if (tid < 64) {
        int c = tid;
        float m = -1e30f;
        for (int q = 0; q < 64; q++) m = fmaxf(m, L[q * 65 + c]);
        float s = 0.f;
        for (int q = 0; q < 64; q++) {
            float ex = __expf(L[q * 65 + c] - m);
            s += ex;
            pc[q * 65 + c] = ex;
        }
        float inv = (c < cs) ? (1.0f / s) : 0.f;
        for (int q = 0; q < 64; q++) pc[q * 65 + c] *= inv;
    }
    __syncthreads();
    // row softmax (over corpus axis) in-place: L becomes pq
    if (tid < 64) {
        float m = -1e30f;
        for (int c = 0; c < 64; c++) m = fmaxf(m, L[tid * 65 + c]);
        float s = 0.f;
        for (int c = 0; c < 64; c++) {
            float ex = __expf(L[tid * 65 + c] - m);
            s += ex;
            L[tid * 65 + c] = ex;
        }
        float inv = (tid < qs) ? (1.0f / s) : 0.f;
        for (int c = 0; c < 64; c++) L[tid * 65 + c] *= inv;
    }
    __syncthreads();

    // ---- hinge alignment scores ----
    float lq = 0.f, lc = 0.f;
    {
        const int d = tid & 127, gg = tid >> 7;
        float av[32];
#pragma unroll
        for (int j = 0; j < 32; j++) av[j] = 0.f;
        for (int c = 0; c < 64; c++) {
            float bb = bufB[c * 129 + d];
            const float* pp = L + (gg * 32) * 65 + c;
#pragma unroll
            for (int j = 0; j < 32; j++) av[j] += pp[j * 65] * bb;
        }
#pragma unroll
        for (int j = 0; j < 32; j++) {
            int q = gg * 32 + j;
            lq += fmaxf(bufA[q * 129 + d] - av[j], 0.f);
        }
#pragma unroll
        for (int j = 0; j < 32; j++) av[j] = 0.f;
        for (int q = 0; q < 64; q++) {
            float aa = bufA[q * 129 + d];
            const float* pp = pc + q * 65 + gg * 32;
#pragma unroll
            for (int j = 0; j < 32; j++) av[j] += pp[j] * aa;
        }
#pragma unroll
        for (int j = 0; j < 32; j++) {
            int c = gg * 32 + j;
            lc += fmaxf(bufB[c * 129 + d] - av[j], 0.f);
        }
    }
    for (int o = 16; o; o >>= 1) {
        lq += __shfl_down_sync(0xffffffffu, lq, o);
        lc += __shfl_down_sync(0xffffffffu, lc, o);
    }
    if (lane == 0) { redq[wid] = lq; redc[wid] = lc; }
    __syncthreads();
    if (tid == 0) {
        float sq = 0.f, sc = 0.f;
        for (int i = 0; i < 8; i++) { sq += redq[i]; sc += redc[i]; }
        out[b] = fminf(-sq, -sc);
    }
}

// ---------------------------------------------------------------------------
extern "C" void kernel_launch(void* const* d_in, const int* in_sizes, int n_in,
                              void* d_out, int out_size) {
    const float* nf       = (const float*)d_in[0];
    const float* ef       = (const float*)d_in[1];
    const int*   from_idx = (const int*)d_in[2];
    const int*   to_idx   = (const int*)d_in[3];
    const int*   pos      = (const int*)d_in[4];
    const int*   qsz      = (const int*)d_in[5];
    const int*   csz      = (const int*)d_in[6];
    const float* W_node = (const float*)d_in[7];
    const float* b_node = (const float*)d_in[8];
    const float* W_edge = (const float*)d_in[9];
    const float* b_edge = (const float*)d_in[10];
    const float* W_msg1 = (const float*)d_in[11];
    const float* b_msg1 = (const float*)d_in[12];
    const float* W_msg2 = (const float*)d_in[13];
    const float* b_msg2 = (const float*)d_in[14];
    const float* W_upd  = (const float*)d_in[15];
    const float* b_upd  = (const float*)d_in[16];
    const float* Wa1    = (const float*)d_in[17];
    const float* ba1    = (const float*)d_in[18];
    const float* Wa2    = (const float*)d_in[19];
    const float* ba2    = (const float*)d_in[20];

    const int N = in_sizes[0] / 32;
    const int E = in_sizes[1] / 16;

    cudaFuncSetAttribute(k_nodeprod, cudaFuncAttributeMaxDynamicSharedMemorySize, SL_END);
    cudaFuncSetAttribute(k_upd2,     cudaFuncAttributeMaxDynamicSharedMemorySize, SL_END);
    cudaFuncSetAttribute(k_attpair,  cudaFuncAttributeMaxDynamicSharedMemorySize, AP_SMEM);

    void* degp = nullptr;
    cudaGetSymbolAddress(&degp, g_deg);

    const int egrid = (E + 63) / 64;
    const int ngrid = (N + 127) / 128;

    k_prep<<<384, 256>>>(W_msg1, Wa1, Wa2);
    k_wcpe<<<144, 256>>>(W_msg2, W_upd, W_edge, W_msg1);
    k_pack<<<194, 256>>>(W_upd, b_msg2, W_msg1, b_msg1, b_edge);
    cudaMemsetAsync(degp, 0, (size_t)N * sizeof(int));
    k_deg<<<(E + 255) / 256, 256>>>(to_idx, E);
    k_enc_node<<<(N + 15) / 16, 256>>>(nf, W_node, b_node, N);

    for (int s = 0; s < 3; s++) {
        k_nodeprod<<<ngrid * 4, 256, SL_END>>>(N);
        k_hidden<<<egrid, 256>>>(from_idx, to_idx, ef, E);
        k_upd2<<<ngrid, 256, SL_END>>>(b_upd, pos, s == 2 ? 1 : 0, N);
    }

    k_attpair<<<256, 256, AP_SMEM>>>(ba1, ba2, qsz, csz, (float*)d_out);
}